// round 11
// baseline (speedup 1.0000x reference)
#include <cuda_runtime.h>
#include <cuda_bf16.h>
#include <math.h>
#include <stdint.h>

// Problem constants
#define CC 512
#define TT 2048
#define BBATCH 2
#define HH 8
#define DD 64
#define LLAYERS 6
#define VV 32000
#define NROW (BBATCH*TT)   // 4096
#define NTILES_HEAD 250

// weight plane offsets (bf16 elems)
#define OFF_QKV  0
#define OFF_OUT  4718592
#define OFF_FF1  6291456
#define OFF_FF2  12582912
#define OFF_HEAD 18874368
#define WTOTAL   35258368

// ---------------- scratch (no allocations allowed) ----------------
__device__ float g_x  [NROW * CC];
__device__ float g_nll[NROW];
__device__ float g_pm [NROW * 256];
__device__ float g_ps [NROW * 256];
__device__ __nv_bfloat16 g_wh[WTOTAL];
__device__ __nv_bfloat16 g_wl[WTOTAL];
__device__ __nv_bfloat16 g_xnh[NROW * CC],     g_xnl[NROW * CC];
__device__ __nv_bfloat16 g_qkvh[NROW * 3 * CC], g_qkvl[NROW * 3 * CC];
__device__ __nv_bfloat16 g_atth[NROW * CC],    g_attl[NROW * CC];
__device__ __nv_bfloat16 g_ffh[NROW * 4 * CC],  g_ffl[NROW * 4 * CC];

// ================= helpers =================
__device__ __forceinline__ uint32_t smem_u32(const void* p) {
    uint32_t a;
    asm("{ .reg .u64 t; cvta.to.shared.u64 t, %1; cvt.u32.u64 %0, t; }"
        : "=r"(a) : "l"(p));
    return a;
}
__device__ __forceinline__ void ldsm_x4(uint32_t* r, uint32_t addr) {
    asm volatile("ldmatrix.sync.aligned.m8n8.x4.shared.b16 {%0,%1,%2,%3}, [%4];"
                 : "=r"(r[0]), "=r"(r[1]), "=r"(r[2]), "=r"(r[3]) : "r"(addr));
}
__device__ __forceinline__ void ldsm_x4_t(uint32_t* r, uint32_t addr) {
    asm volatile("ldmatrix.sync.aligned.m8n8.x4.trans.shared.b16 {%0,%1,%2,%3}, [%4];"
                 : "=r"(r[0]), "=r"(r[1]), "=r"(r[2]), "=r"(r[3]) : "r"(addr));
}
__device__ __forceinline__ void mma_bf16(float* c, const uint32_t* a, const uint32_t* b) {
    asm volatile("mma.sync.aligned.m16n8k16.row.col.f32.bf16.bf16.f32 "
                 "{%0,%1,%2,%3}, {%4,%5,%6,%7}, {%8,%9}, {%0,%1,%2,%3};"
                 : "+f"(c[0]), "+f"(c[1]), "+f"(c[2]), "+f"(c[3])
                 : "r"(a[0]), "r"(a[1]), "r"(a[2]), "r"(a[3]),
                   "r"(b[0]), "r"(b[1]));
}
__device__ __forceinline__ void split2(float a, float b, uint32_t& hi, uint32_t& lo) {
    __nv_bfloat16 ha = __float2bfloat16(a), hb = __float2bfloat16(b);
    __nv_bfloat16 la = __float2bfloat16(a - __bfloat162float(ha));
    __nv_bfloat16 lb = __float2bfloat16(b - __bfloat162float(hb));
    hi = (uint32_t)__bfloat16_as_ushort(ha) | ((uint32_t)__bfloat16_as_ushort(hb) << 16);
    lo = (uint32_t)__bfloat16_as_ushort(la) | ((uint32_t)__bfloat16_as_ushort(lb) << 16);
}
#define CP16(dst, src) \
    asm volatile("cp.async.cg.shared.global [%0], [%1], 16;" \
                 :: "r"(dst), "l"(src) : "memory")
#define CP_COMMIT() asm volatile("cp.async.commit_group;" ::: "memory")
#define CP_WAIT0()  asm volatile("cp.async.wait_group 0;" ::: "memory")

__device__ __forceinline__ float gelu_exact(float x) {
    return 0.5f * x * (1.0f + erff(x * 0.70710678118654752f));
}

// ---------------- weight split conversion ----------------
__global__ void cvtw_k(const float* __restrict__ s,
                       __nv_bfloat16* __restrict__ dh,
                       __nv_bfloat16* __restrict__ dl, int n4) {
    for (int i = blockIdx.x * blockDim.x + threadIdx.x; i < n4;
         i += gridDim.x * blockDim.x) {
        float4 v = ((const float4*)s)[i];
        uint32_t h0, l0, h1, l1;
        split2(v.x, v.y, h0, l0);
        split2(v.z, v.w, h1, l1);
        *(uint2*)(dh + (size_t)i * 4) = make_uint2(h0, h1);
        *(uint2*)(dl + (size_t)i * 4) = make_uint2(l0, l1);
    }
}

// ---------------- embedding ----------------
__global__ void embed_k(const int* __restrict__ idx,
                        const float* __restrict__ tok,
                        const float* __restrict__ pos,
                        float* __restrict__ x) {
    int row = blockIdx.x;
    int t   = row & (TT - 1);
    int tokid = idx[row];
    const float4* te = (const float4*)(tok + (size_t)tokid * CC);
    const float4* pe = (const float4*)(pos + (size_t)t * CC);
    float4* xr = (float4*)(x + (size_t)row * CC);
    for (int i = threadIdx.x; i < CC / 4; i += blockDim.x) {
        float4 a = te[i], b = pe[i];
        a.x += b.x; a.y += b.y; a.z += b.z; a.w += b.w;
        xr[i] = a;
    }
}

// ---------------- layernorm -> bf16 hi/lo planes ----------------
__global__ __launch_bounds__(128) void ln_bf(const float* __restrict__ x,
                                             const float* __restrict__ w,
                                             const float* __restrict__ b,
                                             __nv_bfloat16* __restrict__ yh,
                                             __nv_bfloat16* __restrict__ yl) {
    int row = blockIdx.x;
    int tid = threadIdx.x;
    const float4* xr = (const float4*)(x + (size_t)row * CC);
    float4 v = xr[tid];
    float s = v.x + v.y + v.z + v.w;
    float q = v.x * v.x + v.y * v.y + v.z * v.z + v.w * v.w;
    #pragma unroll
    for (int o = 16; o > 0; o >>= 1) {
        s += __shfl_xor_sync(0xffffffffu, s, o);
        q += __shfl_xor_sync(0xffffffffu, q, o);
    }
    __shared__ float ss[4], qq[4];
    int wid = tid >> 5;
    if ((tid & 31) == 0) { ss[wid] = s; qq[wid] = q; }
    __syncthreads();
    s = ss[0] + ss[1] + ss[2] + ss[3];
    q = qq[0] + qq[1] + qq[2] + qq[3];
    float mu   = s * (1.0f / CC);
    float var  = q * (1.0f / CC) - mu * mu;
    float rstd = rsqrtf(var + 1e-5f);
    float4 wv = ((const float4*)w)[tid];
    float4 bv = ((const float4*)b)[tid];
    float o0 = (v.x - mu) * rstd * wv.x + bv.x;
    float o1 = (v.y - mu) * rstd * wv.y + bv.y;
    float o2 = (v.z - mu) * rstd * wv.z + bv.z;
    float o3 = (v.w - mu) * rstd * wv.w + bv.w;
    uint32_t h0, l0, h1, l1;
    split2(o0, o1, h0, l0);
    split2(o2, o3, h1, l1);
    *(uint2*)(yh + (size_t)row * CC + tid * 4) = make_uint2(h0, h1);
    *(uint2*)(yl + (size_t)row * CC + tid * 4) = make_uint2(l0, l1);
}

#define MODE_NONE 0
#define MODE_GELU 1
#define MODE_RES  2
#define MODE_BF   3
#define MODE_HEAD 4

// ================= gemm_bf: 128x128 CTA, 8 warps, warp tile 64x32 ===
#define BM 128
#define BN 128
#define BK 32
#define PLANE_B 10240
#define STAGE_B (4 * PLANE_B)
#define GEMM_SMEM (2 * STAGE_B)   // 81920

__global__ __launch_bounds__(256, 2) void gemm_bf(
    const __nv_bfloat16* __restrict__ Ah, const __nv_bfloat16* __restrict__ Al,
    const __nv_bfloat16* __restrict__ Bh, const __nv_bfloat16* __restrict__ Bl,
    const float* __restrict__ bias, const float* __restrict__ res,
    float* __restrict__ Cf,
    __nv_bfloat16* __restrict__ Ch, __nv_bfloat16* __restrict__ Cl,
    int N, int K, int mode) {
    extern __shared__ __align__(16) char smem[];
    uint32_t sb = smem_u32(smem);

    int tid  = threadIdx.x;
    int lane = tid & 31;
    int wid  = tid >> 5;
    int wm   = wid & 1;
    int wn   = wid >> 1;
    int bm   = blockIdx.x * BM;
    int bn   = blockIdx.y * BN;

    int r = tid >> 1;
    int cb = (tid & 1) * 2;
    const __nv_bfloat16* Agp = Ah + (size_t)(bm + r) * K + cb * 8;
    const __nv_bfloat16* Alp = Al + (size_t)(bm + r) * K + cb * 8;
    const __nv_bfloat16* Bgp = Bh + (size_t)(bn + r) * K + cb * 8;
    const __nv_bfloat16* Blp = Bl + (size_t)(bn + r) * K + cb * 8;
    uint32_t sdst = (uint32_t)(r * 80 + cb * 16);

    float acc[4][4][4];
    #pragma unroll
    for (int i = 0; i < 4; i++)
        #pragma unroll
        for (int j = 0; j < 4; j++)
            #pragma unroll
            for (int k = 0; k < 4; k++) acc[i][j][k] = 0.0f;

    int nk = K / BK;

    {
        uint32_t st = sb + sdst;
        CP16(st + 0 * PLANE_B,      Agp);     CP16(st + 0 * PLANE_B + 16, Agp + 8);
        CP16(st + 1 * PLANE_B,      Alp);     CP16(st + 1 * PLANE_B + 16, Alp + 8);
        CP16(st + 2 * PLANE_B,      Bgp);     CP16(st + 2 * PLANE_B + 16, Bgp + 8);
        CP16(st + 3 * PLANE_B,      Blp);     CP16(st + 3 * PLANE_B + 16, Blp + 8);
        CP_COMMIT();
    }

    for (int t = 0; t < nk; t++) {
        CP_WAIT0();
        __syncthreads();
        if (t + 1 < nk) {
            uint32_t st = sb + ((t + 1) & 1) * STAGE_B + sdst;
            const __nv_bfloat16* a0 = Agp + (t + 1) * BK;
            const __nv_bfloat16* a1 = Alp + (t + 1) * BK;
            const __nv_bfloat16* b0 = Bgp + (t + 1) * BK;
            const __nv_bfloat16* b1 = Blp + (t + 1) * BK;
            CP16(st + 0 * PLANE_B,      a0);  CP16(st + 0 * PLANE_B + 16, a0 + 8);
            CP16(st + 1 * PLANE_B,      a1);  CP16(st + 1 * PLANE_B + 16, a1 + 8);
            CP16(st + 2 * PLANE_B,      b0);  CP16(st + 2 * PLANE_B + 16, b0 + 8);
            CP16(st + 3 * PLANE_B,      b1);  CP16(st + 3 * PLANE_B + 16, b1 + 8);
        }
        CP_COMMIT();

        uint32_t cAh = sb + (t & 1) * STAGE_B;
        uint32_t cAl = cAh + PLANE_B;
        uint32_t cBh = cAh + 2 * PLANE_B;
        uint32_t cBl = cAh + 3 * PLANE_B;

        #pragma unroll
        for (int kf = 0; kf < 2; kf++) {
            uint32_t kb = kf * 32;
            uint32_t aoff = (uint32_t)((wm * 64 + (lane & 15)) * 80 + kb + ((lane >> 4) * 16));
            uint32_t bo4 = (uint32_t)((wn * 32 + ((lane >> 4) * 8) + (lane & 7)) * 80
                                      + kb + (((lane >> 3) & 1) * 16));

            uint32_t ah4[4][4], al4[4][4], bp4[2][4];
            #pragma unroll
            for (int mf = 0; mf < 4; mf++) ldsm_x4(ah4[mf], cAh + aoff + mf * 16 * 80);
            #pragma unroll
            for (int p = 0; p < 2; p++)   ldsm_x4(bp4[p],  cBh + bo4 + p * 16 * 80);
            #pragma unroll
            for (int p = 0; p < 2; p++) {
                #pragma unroll
                for (int mf = 0; mf < 4; mf++) {
                    mma_bf16(acc[mf][2 * p],     ah4[mf], &bp4[p][0]);
                    mma_bf16(acc[mf][2 * p + 1], ah4[mf], &bp4[p][2]);
                }
            }
            #pragma unroll
            for (int mf = 0; mf < 4; mf++) ldsm_x4(al4[mf], cAl + aoff + mf * 16 * 80);
            #pragma unroll
            for (int p = 0; p < 2; p++) {
                #pragma unroll
                for (int mf = 0; mf < 4; mf++) {
                    mma_bf16(acc[mf][2 * p],     al4[mf], &bp4[p][0]);
                    mma_bf16(acc[mf][2 * p + 1], al4[mf], &bp4[p][2]);
                }
            }
            #pragma unroll
            for (int p = 0; p < 2; p++)   ldsm_x4(bp4[p], cBl + bo4 + p * 16 * 80);
            #pragma unroll
            for (int p = 0; p < 2; p++) {
                #pragma unroll
                for (int mf = 0; mf < 4; mf++) {
                    mma_bf16(acc[mf][2 * p],     ah4[mf], &bp4[p][0]);
                    mma_bf16(acc[mf][2 * p + 1], ah4[mf], &bp4[p][2]);
                }
            }
        }
    }

    if (mode == MODE_HEAD) {
        __syncthreads();
        float* pm_s = (float*)smem;
        float* ps_s = (float*)(smem + 2048);
        #pragma unroll
        for (int mf = 0; mf < 4; mf++) {
            int rl0 = wm * 64 + mf * 16 + (lane >> 2);
            float rv0[8], rv1[8];
            #pragma unroll
            for (int nf = 0; nf < 4; nf++) {
                int col = bn + wn * 32 + nf * 8 + (lane & 3) * 2;
                float b0 = bias[col], b1 = bias[col + 1];
                float v0 = acc[mf][nf][0] + b0;
                float v1 = acc[mf][nf][1] + b1;
                float v2 = acc[mf][nf][2] + b0;
                float v3 = acc[mf][nf][3] + b1;
                int r0g = bm + rl0;
                *(float2*)(Cf + (size_t)r0g * N + col)       = make_float2(v0, v1);
                *(float2*)(Cf + (size_t)(r0g + 8) * N + col) = make_float2(v2, v3);
                rv0[nf * 2] = v0; rv0[nf * 2 + 1] = v1;
                rv1[nf * 2] = v2; rv1[nf * 2 + 1] = v3;
            }
            float m0 = rv0[0], m1 = rv1[0];
            #pragma unroll
            for (int i = 1; i < 8; i++) { m0 = fmaxf(m0, rv0[i]); m1 = fmaxf(m1, rv1[i]); }
            m0 = fmaxf(m0, __shfl_xor_sync(0xffffffffu, m0, 1));
            m0 = fmaxf(m0, __shfl_xor_sync(0xffffffffu, m0, 2));
            m1 = fmaxf(m1, __shfl_xor_sync(0xffffffffu, m1, 1));
            m1 = fmaxf(m1, __shfl_xor_sync(0xffffffffu, m1, 2));
            float s0 = 0.0f, s1 = 0.0f;
            #pragma unroll
            for (int i = 0; i < 8; i++) {
                s0 += __expf(rv0[i] - m0);
                s1 += __expf(rv1[i] - m1);
            }
            s0 += __shfl_xor_sync(0xffffffffu, s0, 1);
            s0 += __shfl_xor_sync(0xffffffffu, s0, 2);
            s1 += __shfl_xor_sync(0xffffffffu, s1, 1);
            s1 += __shfl_xor_sync(0xffffffffu, s1, 2);
            if ((lane & 3) == 0) {
                pm_s[rl0 * 4 + wn] = m0;       ps_s[rl0 * 4 + wn] = s0;
                pm_s[(rl0 + 8) * 4 + wn] = m1; ps_s[(rl0 + 8) * 4 + wn] = s1;
            }
        }
        __syncthreads();
        if (tid < 128) {
            float m = -1e30f, s = 0.0f;
            #pragma unroll
            for (int w = 0; w < 4; w++) {
                float mi = pm_s[tid * 4 + w], si = ps_s[tid * 4 + w];
                float mn = fmaxf(m, mi);
                s = s * __expf(m - mn) + si * __expf(mi - mn);
                m = mn;
            }
            g_pm[(size_t)(bm + tid) * 256 + blockIdx.y] = m;
            g_ps[(size_t)(bm + tid) * 256 + blockIdx.y] = s;
        }
        return;
    }

    #pragma unroll
    for (int mf = 0; mf < 4; mf++) {
        int r0 = bm + wm * 64 + mf * 16 + (lane >> 2);
        #pragma unroll
        for (int nf = 0; nf < 4; nf++) {
            int col = bn + wn * 32 + nf * 8 + (lane & 3) * 2;
            float b0 = bias[col], b1 = bias[col + 1];
            float v0 = acc[mf][nf][0] + b0;
            float v1 = acc[mf][nf][1] + b1;
            float v2 = acc[mf][nf][2] + b0;
            float v3 = acc[mf][nf][3] + b1;
            if (mode == MODE_GELU) {
                v0 = gelu_exact(v0); v1 = gelu_exact(v1);
                v2 = gelu_exact(v2); v3 = gelu_exact(v3);
            } else if (mode == MODE_RES) {
                float2 r0v = *(const float2*)(res + (size_t)r0 * N + col);
                float2 r1v = *(const float2*)(res + (size_t)(r0 + 8) * N + col);
                v0 += r0v.x; v1 += r0v.y; v2 += r1v.x; v3 += r1v.y;
            }
            if (mode == MODE_RES || mode == MODE_NONE) {
                *(float2*)(Cf + (size_t)r0 * N + col)       = make_float2(v0, v1);
                *(float2*)(Cf + (size_t)(r0 + 8) * N + col) = make_float2(v2, v3);
            } else {
                uint32_t hp, lp;
                split2(v0, v1, hp, lp);
                *(uint32_t*)(Ch + (size_t)r0 * N + col) = hp;
                *(uint32_t*)(Cl + (size_t)r0 * N + col) = lp;
                split2(v2, v3, hp, lp);
                *(uint32_t*)(Ch + (size_t)(r0 + 8) * N + col) = hp;
                *(uint32_t*)(Cl + (size_t)(r0 + 8) * N + col) = lp;
            }
        }
    }
}

// ======== tensor-core flash attention: 64-row Q tiles, 128 threads, 2 CTAs/SM ========
#define SQH 0
#define SQL 9216
#define SKV 18432
#define KVB 36864
#define ATT_SMEM (SKV + 2 * KVB)   // 92160

__global__ __launch_bounds__(128) void attn_mma(
    const __nv_bfloat16* __restrict__ qkvh,
    const __nv_bfloat16* __restrict__ qkvl,
    __nv_bfloat16* __restrict__ outh,
    __nv_bfloat16* __restrict__ outl) {
    extern __shared__ __align__(16) char sm[];
    uint32_t sb = smem_u32(sm);
    int tid = threadIdx.x, lane = tid & 31, w = tid >> 5;   // 4 warps
    int bh = blockIdx.y, b = bh >> 3, h = bh & 7;
    int qb = (int)gridDim.x - 1 - (int)blockIdx.x;           // heavy blocks first
    size_t bbase = (size_t)b * TT * (3 * CC);

    int ntiles = qb + 1;
    int sr2 = tid >> 1, qd = tid & 1;                        // 64 rows x 2 halves

    // prologue: KV tile 0 -> buf 0 (each thread: 64B per plane = 4 x CP16)
    {
        size_t ro = bbase + (size_t)sr2 * (3 * CC);
        const __nv_bfloat16* kh = qkvh + ro + CC + h * DD + qd * 32;
        const __nv_bfloat16* kl = qkvl + ro + CC + h * DD + qd * 32;
        const __nv_bfloat16* vh = qkvh + ro + 2 * CC + h * DD + qd * 32;
        const __nv_bfloat16* vl = qkvl + ro + 2 * CC + h * DD + qd * 32;
        uint32_t sd = sb + SKV + (uint32_t)(sr2 * 144 + qd * 64);
        #pragma unroll
        for (int j = 0; j < 4; j++) {
            CP16(sd + j * 16,         kh + j * 8);
            CP16(sd + 9216 + j * 16,  kl + j * 8);
            CP16(sd + 18432 + j * 16, vh + j * 8);
            CP16(sd + 27648 + j * 16, vl + j * 8);
        }
        CP_COMMIT();
    }

    // stage Q (64 rows; thread -> row tid>>1, half tid&1)
    {
        int r = tid >> 1, hf = tid & 1;
        const __nv_bfloat16* qgh = qkvh + bbase + (size_t)(qb * 64 + r) * (3 * CC) + h * DD + hf * 32;
        const __nv_bfloat16* qgl = qkvl + bbase + (size_t)(qb * 64 + r) * (3 * CC) + h * DD + hf * 32;
        uint32_t qoff = (uint32_t)(r * 144 + hf * 64);
        #pragma unroll
        for (int j = 0; j < 4; j++) {
            *(uint4*)(sm + SQH + qoff + j * 16) = *(const uint4*)(qgh + j * 8);
            *(uint4*)(sm + SQL + qoff + j * 16) = *(const uint4*)(qgl + j * 8);
        }
    }
    __syncthreads();

    uint32_t qh[4][4], qlo[4][4];
    {
        uint32_t ro = (uint32_t)((w * 16 + (lane & 15)) * 144 + ((lane >> 4) * 16));
        #pragma unroll
        for (int kf = 0; kf < 4; kf++) {
            ldsm_x4(qh[kf],  sb + SQH + ro + kf * 32);
            ldsm_x4(qlo[kf], sb + SQL + ro + kf * 32);
        }
    }

    float o[8][4];
    #pragma unroll
    for (int i = 0; i < 8; i++)
        #pragma unroll
        for (int j = 0; j < 4; j++) o[i][j] = 0.0f;
    float m0 = -1e30f, m1 = -1e30f, l0 = 0.0f, l1 = 0.0f;

    for (int t = 0; t < ntiles; t++) {
        CP_WAIT0();
        __syncthreads();
        if (t + 1 < ntiles) {
            size_t ro = bbase + (size_t)((t + 1) * 64 + sr2) * (3 * CC);
            const __nv_bfloat16* kh = qkvh + ro + CC + h * DD + qd * 32;
            const __nv_bfloat16* kl = qkvl + ro + CC + h * DD + qd * 32;
            const __nv_bfloat16* vh = qkvh + ro + 2 * CC + h * DD + qd * 32;
            const __nv_bfloat16* vl = qkvl + ro + 2 * CC + h * DD + qd * 32;
            uint32_t sd = sb + SKV + ((t + 1) & 1) * KVB + (uint32_t)(sr2 * 144 + qd * 64);
            #pragma unroll
            for (int j = 0; j < 4; j++) {
                CP16(sd + j * 16,         kh + j * 8);
                CP16(sd + 9216 + j * 16,  kl + j * 8);
                CP16(sd + 18432 + j * 16, vh + j * 8);
                CP16(sd + 27648 + j * 16, vl + j * 8);
            }
        }
        CP_COMMIT();

        uint32_t KH = sb + SKV + (t & 1) * KVB;
        uint32_t KL = KH + 9216;
        uint32_t VH = KH + 18432;
        uint32_t VL = KH + 27648;

        float sacc[8][4];
        #pragma unroll
        for (int i = 0; i < 8; i++)
            #pragma unroll
            for (int j = 0; j < 4; j++) sacc[i][j] = 0.0f;

        #pragma unroll
        for (int kf = 0; kf < 4; kf++) {
            uint32_t bo = (uint32_t)((lane & 15) * 144 + kf * 32 + (lane >> 4) * 16);
            uint32_t kk[4][4];
            #pragma unroll
            for (int p = 0; p < 4; p++) ldsm_x4(kk[p], KH + bo + p * 16 * 144);
            #pragma unroll
            for (int p = 0; p < 4; p++) {
                uint32_t b0[2] = {kk[p][0], kk[p][2]};
                uint32_t b1[2] = {kk[p][1], kk[p][3]};
                mma_bf16(sacc[2 * p],     qh[kf],  b0);
                mma_bf16(sacc[2 * p + 1], qh[kf],  b1);
                mma_bf16(sacc[2 * p],     qlo[kf], b0);
                mma_bf16(sacc[2 * p + 1], qlo[kf], b1);
            }
            #pragma unroll
            for (int p = 0; p < 4; p++) ldsm_x4(kk[p], KL + bo + p * 16 * 144);
            #pragma unroll
            for (int p = 0; p < 4; p++) {
                uint32_t b0[2] = {kk[p][0], kk[p][2]};
                uint32_t b1[2] = {kk[p][1], kk[p][3]};
                mma_bf16(sacc[2 * p],     qh[kf], b0);
                mma_bf16(sacc[2 * p + 1], qh[kf], b1);
            }
        }
        #pragma unroll
        for (int nf = 0; nf < 8; nf++) {
            sacc[nf][0] *= 0.125f; sacc[nf][1] *= 0.125f;
            sacc[nf][2] *= 0.125f; sacc[nf][3] *= 0.125f;
        }

        if (t == qb) {   // diagonal tile: causal mask
            int row0 = qb * 64 + w * 16 + (lane >> 2);
            int kc0  = t * 64 + (lane & 3) * 2;
            #pragma unroll
            for (int nf = 0; nf < 8; nf++) {
                int kc = kc0 + nf * 8;
                if (kc     > row0)     sacc[nf][0] = -1e30f;
                if (kc + 1 > row0)     sacc[nf][1] = -1e30f;
                if (kc     > row0 + 8) sacc[nf][2] = -1e30f;
                if (kc + 1 > row0 + 8) sacc[nf][3] = -1e30f;
            }
        }

        float mx0 = -1e30f, mx1 = -1e30f;
        #pragma unroll
        for (int nf = 0; nf < 8; nf++) {
            mx0 = fmaxf(mx0, fmaxf(sacc[nf][0], sacc[nf][1]));
            mx1 = fmaxf(mx1, fmaxf(sacc[nf][2], sacc[nf][3]));
        }
        mx0 = fmaxf(mx0, __shfl_xor_sync(0xffffffffu, mx0, 1));
        mx0 = fmaxf(mx0, __shfl_xor_sync(0xffffffffu, mx0, 2));
        mx1 = fmaxf(mx1, __shfl_xor_sync(0xffffffffu, mx1, 1));
        mx1 = fmaxf(mx1, __shfl_xor_sync(0xffffffffu, mx1, 2));
        float mn0 = fmaxf(m0, mx0), mn1 = fmaxf(m1, mx1);
        float cs0 = __expf(m0 - mn0), cs1 = __expf(m1 - mn1);
        m0 = mn0; m1 = mn1;
        float ps0 = 0.0f, ps1 = 0.0f;
        #pragma unroll
        for (int nf = 0; nf < 8; nf++) {
            sacc[nf][0] = __expf(sacc[nf][0] - m0); ps0 += sacc[nf][0];
            sacc[nf][1] = __expf(sacc[nf][1] - m0); ps0 += sacc[nf][1];
            sacc[nf][2] = __expf(sacc[nf][2] - m1); ps1 += sacc[nf][2];
            sacc[nf][3] = __expf(sacc[nf][3] - m1); ps1 += sacc[nf][3];
        }
        l0 = l0 * cs0 + ps0;
        l1 = l1 * cs1 + ps1;
        #pragma unroll
        for (int nd = 0; nd < 8; nd++) {
            o[nd][0] *= cs0; o[nd][1] *= cs0;
            o[nd][2] *= cs1; o[nd][3] *= cs1;
        }

        uint32_t ph[4][4], plo[4][4];
        #pragma unroll
        for (int j = 0; j < 4; j++) {
            split2(sacc[2 * j][0],     sacc[2 * j][1],     ph[j][0], plo[j][0]);
            split2(sacc[2 * j][2],     sacc[2 * j][3],     ph[j][1], plo[j][1]);
            split2(sacc[2 * j + 1][0], sacc[2 * j + 1][1], ph[j][2], plo[j][2]);
            split2(sacc[2 * j + 1][2], sacc[2 * j + 1][3], ph[j][3], plo[j][3]);
        }

        #pragma unroll
        for (int nd = 0; nd < 8; nd++) {
            #pragma unroll
            for (int jp = 0; jp < 2; jp++) {
                uint32_t vv[4];
                uint32_t vo = (uint32_t)((jp * 32 + lane) * 144 + nd * 16);
                ldsm_x4_t(vv, VH + vo);
                {
                    uint32_t b0[2] = {vv[0], vv[1]};
                    uint32_t b1[2] = {vv[2], vv[3]};
                    mma_bf16(o[nd], ph[2 * jp],      b0);
                    mma_bf16(o[nd], ph[2 * jp + 1],  b1);
                    mma_bf16(o[nd], plo[2 * jp],     b0);
                    mma_bf16(o[nd], plo[2 * jp + 1], b1);
                }
                ldsm_x4_t(vv, VL + vo);
                {
                    uint32_t b0[2] = {vv[0], vv[1]};
                    uint32_t b1[2] = {vv[2], vv[3]};
                    mma_bf16(o[nd], ph[2 * jp],     b0);
                    mma_bf16(o[nd], ph[2 * jp + 1], b1);
                }
            }
        }
    }

    l0 += __shfl_xor_sync(0xffffffffu, l0, 1);
    l0 += __shfl_xor_sync(0xffffffffu, l0, 2);
    l1 += __shfl_xor_sync(0xffffffffu, l1, 1);
    l1 += __shfl_xor_sync(0xffffffffu, l1, 2);
    float inv0 = 1.0f / l0, inv1 = 1.0f / l1;
    int rowg = b * TT + qb * 64 + w * 16 + (lane >> 2);
    __nv_bfloat16* oph = outh + (size_t)rowg * CC + h * DD;
    __nv_bfloat16* opl = outl + (size_t)rowg * CC + h * DD;
    #pragma unroll
    for (int nd = 0; nd < 8; nd++) {
        int col = nd * 8 + (lane & 3) * 2;
        uint32_t hp, lp;
        split2(o[nd][0] * inv0, o[nd][1] * inv0, hp, lp);
        *(uint32_t*)(oph + col) = hp;
        *(uint32_t*)(opl + col) = lp;
        split2(o[nd][2] * inv1, o[nd][3] * inv1, hp, lp);
        *(uint32_t*)(oph + 8 * CC + col) = hp;
        *(uint32_t*)(opl + 8 * CC + col) = lp;
    }
}

// ---------------- NLL from logsumexp partials ----------------
__global__ __launch_bounds__(256) void nll2_k(const float* __restrict__ logits,
                                              const int* __restrict__ tgt,
                                              float* __restrict__ nll) {
    int row = blockIdx.x;
    const float* pm = g_pm + (size_t)row * 256;
    const float* ps = g_ps + (size_t)row * 256;
    float m = -1e30f, s = 0.0f;
    for (int j = threadIdx.x; j < NTILES_HEAD; j += 256) {
        float mi = pm[j], si = ps[j];
        float mn = fmaxf(m, mi);
        s = s * __expf(m - mn) + si * __expf(mi - mn);
        m = mn;
    }
    #pragma unroll
    for (int o = 16; o > 0; o >>= 1) {
        float m2 = __shfl_xor_sync(0xffffffffu, m, o);
        float s2 = __shfl_xor_sync(0xffffffffu, s, o);
        float mn = fmaxf(m, m2);
        s = s * __expf(m - mn) + s2 * __expf(m2 - mn);
        m = mn;
    }
    __shared__ float ms[8], ls[8];
    int wid = threadIdx.x >> 5;
    if ((threadIdx.x & 31) == 0) { ms[wid] = m; ls[wid] = s; }
    __syncthreads();
    if (threadIdx.x == 0) {
        float M = ms[0], S = ls[0];
        #pragma unroll
        for (int w = 1; w < 8; w++) {
            float mn = fmaxf(M, ms[w]);
            S = S * __expf(M - mn) + ls[w] * __expf(ms[w] - mn);
            M = mn;
        }
        float lse = M + logf(S);
        nll[row] = lse - logits[(size_t)row * VV + tgt[row]];
    }
}

__global__ __launch_bounds__(256) void loss_k(const float* __restrict__ nll,
                                              float* __restrict__ out_loss) {
    float s = 0.0f;
    for (int i = threadIdx.x; i < NROW; i += 256) s += nll[i];
    #pragma unroll
    for (int o = 16; o > 0; o >>= 1) s += __shfl_xor_sync(0xffffffffu, s, o);
    __shared__ float ws[8];
    int wid = threadIdx.x >> 5;
    if ((threadIdx.x & 31) == 0) ws[wid] = s;
    __syncthreads();
    if (threadIdx.x == 0) {
        float t = 0.0f;
        #pragma unroll
        for (int w = 0; w < 8; w++) t += ws[w];
        out_loss[0] = t / (float)NROW;
    }
}

// ---------------- orchestration ----------------
extern "C" void kernel_launch(void* const* d_in, const int* in_sizes, int n_in,
                              void* d_out, int out_size) {
    const int*   idx       = (const int*)  d_in[0];
    const int*   targets   = (const int*)  d_in[1];
    const float* tok_embed = (const float*)d_in[2];
    const float* pos_embed = (const float*)d_in[3];
    const float* qkv_w     = (const float*)d_in[4];
    const float* qkv_b     = (const float*)d_in[5];
    const float* out_w     = (const float*)d_in[6];
    const float* out_b     = (const float*)d_in[7];
    const float* ln1_w     = (const float*)d_in[8];
    const float* ln1_b     = (const float*)d_in[9];
    const float* ff1_w     = (const float*)d_in[10];
    const float* ff1_b     = (const float*)d_in[11];
    const float* ff2_w     = (const float*)d_in[12];
    const float* ff2_b     = (const float*)d_in[13];
    const float* ln2_w     = (const float*)d_in[14];
    const float* ln2_b     = (const float*)d_in[15];
    const float* lnf_w     = (const float*)d_in[16];
    const float* lnf_b     = (const float*)d_in[17];
    const float* head_w    = (const float*)d_in[18];
    const float* head_b    = (const float*)d_in[19];
    float* logits = (float*)d_out;

    static float *px = nullptr, *pnll = nullptr;
    static __nv_bfloat16 *wh, *wl, *xnh, *xnl, *qkvh, *qkvl, *atth, *attl, *ffh, *ffl;
    if (!px) {
        cudaGetSymbolAddress((void**)&px,   g_x);
        cudaGetSymbolAddress((void**)&pnll, g_nll);
        cudaGetSymbolAddress((void**)&wh,   g_wh);
        cudaGetSymbolAddress((void**)&wl,   g_wl);
        cudaGetSymbolAddress((void**)&xnh,  g_xnh);
        cudaGetSymbolAddress((void**)&xnl,  g_xnl);
        cudaGetSymbolAddress((void**)&qkvh, g_qkvh);
        cudaGetSymbolAddress((void**)&qkvl, g_qkvl);
        cudaGetSymbolAddress((void**)&atth, g_atth);
        cudaGetSymbolAddress((void**)&attl, g_attl);
        cudaGetSymbolAddress((void**)&ffh,  g_ffh);
        cudaGetSymbolAddress((void**)&ffl,  g_ffl);
        cudaFuncSetAttribute(gemm_bf,  cudaFuncAttributeMaxDynamicSharedMemorySize, GEMM_SMEM);
        cudaFuncSetAttribute(attn_mma, cudaFuncAttributeMaxDynamicSharedMemorySize, ATT_SMEM);
    }

    cvtw_k<<<2048, 256>>>(qkv_w,  wh + OFF_QKV,  wl + OFF_QKV,  6 * 3 * CC * CC / 4);
    cvtw_k<<<2048, 256>>>(out_w,  wh + OFF_OUT,  wl + OFF_OUT,  6 * CC * CC / 4);
    cvtw_k<<<2048, 256>>>(ff1_w,  wh + OFF_FF1,  wl + OFF_FF1,  6 * 4 * CC * CC / 4);
    cvtw_k<<<2048, 256>>>(ff2_w,  wh + OFF_FF2,  wl + OFF_FF2,  6 * 4 * CC * CC / 4);
    cvtw_k<<<2048, 256>>>(head_w, wh + OFF_HEAD, wl + OFF_HEAD, VV * CC / 4);

    embed_k<<<NROW, 128>>>(idx, tok_embed, pos_embed, px);

    dim3 gQKV(NROW / 128, 3 * CC / 128);   // (32, 12)
    dim3 gPROJ(NROW / 128, CC / 128);      // (32, 4)
    dim3 gFF1(NROW / 128, 4 * CC / 128);   // (32, 16)
    dim3 gHEAD(NROW / 128, VV / 128);      // (32, 250)
    dim3 gATT(TT / 64, BBATCH * HH);       // (32, 16) = 512 blocks

    for (int l = 0; l < LLAYERS; l++) {
        ln_bf<<<NROW, 128>>>(px, ln1_w + l * CC, ln1_b + l * CC, xnh, xnl);
        gemm_bf<<<gQKV, 256, GEMM_SMEM>>>(xnh, xnl,
            wh + OFF_QKV + (size_t)l * 3 * CC * CC, wl + OFF_QKV + (size_t)l * 3 * CC * CC,
            qkv_b + l * 3 * CC, nullptr, nullptr, qkvh, qkvl, 3 * CC, CC, MODE_BF);
        attn_mma<<<gATT, 128, ATT_SMEM>>>(qkvh, qkvl, atth, attl);
        gemm_bf<<<gPROJ, 256, GEMM_SMEM>>>(atth, attl,
            wh + OFF_OUT + (size_t)l * CC * CC, wl + OFF_OUT + (size_t)l * CC * CC,
            out_b + l * CC, px, px, nullptr, nullptr, CC, CC, MODE_RES);
        ln_bf<<<NROW, 128>>>(px, ln2_w + l * CC, ln2_b + l * CC, xnh, xnl);
        gemm_bf<<<gFF1, 256, GEMM_SMEM>>>(xnh, xnl,
            wh + OFF_FF1 + (size_t)l * 4 * CC * CC, wl + OFF_FF1 + (size_t)l * 4 * CC * CC,
            ff1_b + l * 4 * CC, nullptr, nullptr, ffh, ffl, 4 * CC, CC, MODE_GELU);
        gemm_bf<<<gPROJ, 256, GEMM_SMEM>>>(ffh, ffl,
            wh + OFF_FF2 + (size_t)l * CC * 4 * CC, wl + OFF_FF2 + (size_t)l * CC * 4 * CC,
            ff2_b + l * CC, px, px, nullptr, nullptr, CC, 4 * CC, MODE_RES);
    }

    ln_bf<<<NROW, 128>>>(px, lnf_w, lnf_b, xnh, xnl);
    gemm_bf<<<gHEAD, 256, GEMM_SMEM>>>(xnh, xnl,
        wh + OFF_HEAD, wl + OFF_HEAD,
        head_b, nullptr, logits, nullptr, nullptr, VV, CC, MODE_HEAD);

    nll2_k<<<NROW, 256>>>(logits, targets, pnll);
    if (out_size > NROW * VV) {
        loss_k<<<1, 256>>>(pnll, logits + (size_t)NROW * VV);
    }
}

// round 12
// speedup vs baseline: 1.0105x; 1.0105x over previous
#include <cuda_runtime.h>
#include <cuda_bf16.h>
#include <math.h>
#include <stdint.h>

// Problem constants
#define CC 512
#define TT 2048
#define BBATCH 2
#define HH 8
#define DD 64
#define LLAYERS 6
#define VV 32000
#define NROW (BBATCH*TT)   // 4096
#define NTILES_HEAD 250

// weight plane offsets (bf16 elems)
#define OFF_QKV  0
#define OFF_OUT  4718592
#define OFF_FF1  6291456
#define OFF_FF2  12582912
#define OFF_HEAD 18874368
#define WTOTAL   35258368

// ---------------- scratch (no allocations allowed) ----------------
__device__ float g_x  [NROW * CC];
__device__ float g_nll[NROW];
__device__ float g_pm [NROW * 256];
__device__ float g_ps [NROW * 256];
__device__ __nv_bfloat16 g_wh[WTOTAL];
__device__ __nv_bfloat16 g_wl[WTOTAL];
__device__ __nv_bfloat16 g_xnh[NROW * CC],     g_xnl[NROW * CC];
__device__ __nv_bfloat16 g_qkvh[NROW * 3 * CC], g_qkvl[NROW * 3 * CC];
__device__ __nv_bfloat16 g_atth[NROW * CC],    g_attl[NROW * CC];
__device__ __nv_bfloat16 g_ffh[NROW * 4 * CC],  g_ffl[NROW * 4 * CC];

// ================= helpers =================
__device__ __forceinline__ uint32_t smem_u32(const void* p) {
    uint32_t a;
    asm("{ .reg .u64 t; cvta.to.shared.u64 t, %1; cvt.u32.u64 %0, t; }"
        : "=r"(a) : "l"(p));
    return a;
}
__device__ __forceinline__ void ldsm_x4(uint32_t* r, uint32_t addr) {
    asm volatile("ldmatrix.sync.aligned.m8n8.x4.shared.b16 {%0,%1,%2,%3}, [%4];"
                 : "=r"(r[0]), "=r"(r[1]), "=r"(r[2]), "=r"(r[3]) : "r"(addr));
}
__device__ __forceinline__ void ldsm_x4_t(uint32_t* r, uint32_t addr) {
    asm volatile("ldmatrix.sync.aligned.m8n8.x4.trans.shared.b16 {%0,%1,%2,%3}, [%4];"
                 : "=r"(r[0]), "=r"(r[1]), "=r"(r[2]), "=r"(r[3]) : "r"(addr));
}
__device__ __forceinline__ void mma_bf16(float* c, const uint32_t* a, const uint32_t* b) {
    asm volatile("mma.sync.aligned.m16n8k16.row.col.f32.bf16.bf16.f32 "
                 "{%0,%1,%2,%3}, {%4,%5,%6,%7}, {%8,%9}, {%0,%1,%2,%3};"
                 : "+f"(c[0]), "+f"(c[1]), "+f"(c[2]), "+f"(c[3])
                 : "r"(a[0]), "r"(a[1]), "r"(a[2]), "r"(a[3]),
                   "r"(b[0]), "r"(b[1]));
}
__device__ __forceinline__ void split2(float a, float b, uint32_t& hi, uint32_t& lo) {
    __nv_bfloat16 ha = __float2bfloat16(a), hb = __float2bfloat16(b);
    __nv_bfloat16 la = __float2bfloat16(a - __bfloat162float(ha));
    __nv_bfloat16 lb = __float2bfloat16(b - __bfloat162float(hb));
    hi = (uint32_t)__bfloat16_as_ushort(ha) | ((uint32_t)__bfloat16_as_ushort(hb) << 16);
    lo = (uint32_t)__bfloat16_as_ushort(la) | ((uint32_t)__bfloat16_as_ushort(lb) << 16);
}
#define CP16(dst, src) \
    asm volatile("cp.async.cg.shared.global [%0], [%1], 16;" \
                 :: "r"(dst), "l"(src) : "memory")
#define CP_COMMIT() asm volatile("cp.async.commit_group;" ::: "memory")
#define CP_WAIT0()  asm volatile("cp.async.wait_group 0;" ::: "memory")

__device__ __forceinline__ float gelu_exact(float x) {
    return 0.5f * x * (1.0f + erff(x * 0.70710678118654752f));
}

// ---------------- weight split conversion (4-way MLP grid-stride) ----------------
__global__ void cvtw_k(const float* __restrict__ s,
                       __nv_bfloat16* __restrict__ dh,
                       __nv_bfloat16* __restrict__ dl, int n4) {
    int stride = gridDim.x * blockDim.x;
    int base = blockIdx.x * blockDim.x + threadIdx.x;
    for (int i = base; i < n4; i += 4 * stride) {
        float4 v[4];
        int idx[4];
        #pragma unroll
        for (int j = 0; j < 4; j++) {
            idx[j] = i + j * stride;
            if (idx[j] < n4) v[j] = ((const float4*)s)[idx[j]];
        }
        #pragma unroll
        for (int j = 0; j < 4; j++) {
            if (idx[j] < n4) {
                uint32_t h0, l0, h1, l1;
                split2(v[j].x, v[j].y, h0, l0);
                split2(v[j].z, v[j].w, h1, l1);
                *(uint2*)(dh + (size_t)idx[j] * 4) = make_uint2(h0, h1);
                *(uint2*)(dl + (size_t)idx[j] * 4) = make_uint2(l0, l1);
            }
        }
    }
}

// ---------------- embedding ----------------
__global__ void embed_k(const int* __restrict__ idx,
                        const float* __restrict__ tok,
                        const float* __restrict__ pos,
                        float* __restrict__ x) {
    int row = blockIdx.x;
    int t   = row & (TT - 1);
    int tokid = idx[row];
    const float4* te = (const float4*)(tok + (size_t)tokid * CC);
    const float4* pe = (const float4*)(pos + (size_t)t * CC);
    float4* xr = (float4*)(x + (size_t)row * CC);
    for (int i = threadIdx.x; i < CC / 4; i += blockDim.x) {
        float4 a = te[i], b = pe[i];
        a.x += b.x; a.y += b.y; a.z += b.z; a.w += b.w;
        xr[i] = a;
    }
}

// ---------------- layernorm -> bf16 hi/lo planes ----------------
__global__ __launch_bounds__(128) void ln_bf(const float* __restrict__ x,
                                             const float* __restrict__ w,
                                             const float* __restrict__ b,
                                             __nv_bfloat16* __restrict__ yh,
                                             __nv_bfloat16* __restrict__ yl) {
    int row = blockIdx.x;
    int tid = threadIdx.x;
    const float4* xr = (const float4*)(x + (size_t)row * CC);
    float4 v = xr[tid];
    float s = v.x + v.y + v.z + v.w;
    float q = v.x * v.x + v.y * v.y + v.z * v.z + v.w * v.w;
    #pragma unroll
    for (int o = 16; o > 0; o >>= 1) {
        s += __shfl_xor_sync(0xffffffffu, s, o);
        q += __shfl_xor_sync(0xffffffffu, q, o);
    }
    __shared__ float ss[4], qq[4];
    int wid = tid >> 5;
    if ((tid & 31) == 0) { ss[wid] = s; qq[wid] = q; }
    __syncthreads();
    s = ss[0] + ss[1] + ss[2] + ss[3];
    q = qq[0] + qq[1] + qq[2] + qq[3];
    float mu   = s * (1.0f / CC);
    float var  = q * (1.0f / CC) - mu * mu;
    float rstd = rsqrtf(var + 1e-5f);
    float4 wv = ((const float4*)w)[tid];
    float4 bv = ((const float4*)b)[tid];
    float o0 = (v.x - mu) * rstd * wv.x + bv.x;
    float o1 = (v.y - mu) * rstd * wv.y + bv.y;
    float o2 = (v.z - mu) * rstd * wv.z + bv.z;
    float o3 = (v.w - mu) * rstd * wv.w + bv.w;
    uint32_t h0, l0, h1, l1;
    split2(o0, o1, h0, l0);
    split2(o2, o3, h1, l1);
    *(uint2*)(yh + (size_t)row * CC + tid * 4) = make_uint2(h0, h1);
    *(uint2*)(yl + (size_t)row * CC + tid * 4) = make_uint2(l0, l1);
}

#define MODE_NONE 0
#define MODE_GELU 1
#define MODE_RES  2
#define MODE_BF   3
#define MODE_HEAD 4

// ================= gemm_bf: 128x128 CTA, 8 warps, warp tile 64x32 ===
#define BM 128
#define BN 128
#define BK 32
#define PLANE_B 10240
#define STAGE_B (4 * PLANE_B)
#define GEMM_SMEM (2 * STAGE_B)   // 81920

__global__ __launch_bounds__(256, 2) void gemm_bf(
    const __nv_bfloat16* __restrict__ Ah, const __nv_bfloat16* __restrict__ Al,
    const __nv_bfloat16* __restrict__ Bh, const __nv_bfloat16* __restrict__ Bl,
    const float* __restrict__ bias, const float* __restrict__ res,
    float* __restrict__ Cf,
    __nv_bfloat16* __restrict__ Ch, __nv_bfloat16* __restrict__ Cl,
    int N, int K, int mode) {
    extern __shared__ __align__(16) char smem[];
    uint32_t sb = smem_u32(smem);

    int tid  = threadIdx.x;
    int lane = tid & 31;
    int wid  = tid >> 5;
    int wm   = wid & 1;
    int wn   = wid >> 1;
    int bm   = blockIdx.x * BM;
    int bn   = blockIdx.y * BN;

    int r = tid >> 1;
    int cb = (tid & 1) * 2;
    const __nv_bfloat16* Agp = Ah + (size_t)(bm + r) * K + cb * 8;
    const __nv_bfloat16* Alp = Al + (size_t)(bm + r) * K + cb * 8;
    const __nv_bfloat16* Bgp = Bh + (size_t)(bn + r) * K + cb * 8;
    const __nv_bfloat16* Blp = Bl + (size_t)(bn + r) * K + cb * 8;
    uint32_t sdst = (uint32_t)(r * 80 + cb * 16);

    float acc[4][4][4];
    #pragma unroll
    for (int i = 0; i < 4; i++)
        #pragma unroll
        for (int j = 0; j < 4; j++)
            #pragma unroll
            for (int k = 0; k < 4; k++) acc[i][j][k] = 0.0f;

    int nk = K / BK;

    {
        uint32_t st = sb + sdst;
        CP16(st + 0 * PLANE_B,      Agp);     CP16(st + 0 * PLANE_B + 16, Agp + 8);
        CP16(st + 1 * PLANE_B,      Alp);     CP16(st + 1 * PLANE_B + 16, Alp + 8);
        CP16(st + 2 * PLANE_B,      Bgp);     CP16(st + 2 * PLANE_B + 16, Bgp + 8);
        CP16(st + 3 * PLANE_B,      Blp);     CP16(st + 3 * PLANE_B + 16, Blp + 8);
        CP_COMMIT();
    }

    for (int t = 0; t < nk; t++) {
        CP_WAIT0();
        __syncthreads();
        if (t + 1 < nk) {
            uint32_t st = sb + ((t + 1) & 1) * STAGE_B + sdst;
            const __nv_bfloat16* a0 = Agp + (t + 1) * BK;
            const __nv_bfloat16* a1 = Alp + (t + 1) * BK;
            const __nv_bfloat16* b0 = Bgp + (t + 1) * BK;
            const __nv_bfloat16* b1 = Blp + (t + 1) * BK;
            CP16(st + 0 * PLANE_B,      a0);  CP16(st + 0 * PLANE_B + 16, a0 + 8);
            CP16(st + 1 * PLANE_B,      a1);  CP16(st + 1 * PLANE_B + 16, a1 + 8);
            CP16(st + 2 * PLANE_B,      b0);  CP16(st + 2 * PLANE_B + 16, b0 + 8);
            CP16(st + 3 * PLANE_B,      b1);  CP16(st + 3 * PLANE_B + 16, b1 + 8);
        }
        CP_COMMIT();

        uint32_t cAh = sb + (t & 1) * STAGE_B;
        uint32_t cAl = cAh + PLANE_B;
        uint32_t cBh = cAh + 2 * PLANE_B;
        uint32_t cBl = cAh + 3 * PLANE_B;

        #pragma unroll
        for (int kf = 0; kf < 2; kf++) {
            uint32_t kb = kf * 32;
            uint32_t aoff = (uint32_t)((wm * 64 + (lane & 15)) * 80 + kb + ((lane >> 4) * 16));
            uint32_t bo4 = (uint32_t)((wn * 32 + ((lane >> 4) * 8) + (lane & 7)) * 80
                                      + kb + (((lane >> 3) & 1) * 16));

            uint32_t ah4[4][4], al4[4][4], bp4[2][4];
            #pragma unroll
            for (int mf = 0; mf < 4; mf++) ldsm_x4(ah4[mf], cAh + aoff + mf * 16 * 80);
            #pragma unroll
            for (int p = 0; p < 2; p++)   ldsm_x4(bp4[p],  cBh + bo4 + p * 16 * 80);
            #pragma unroll
            for (int p = 0; p < 2; p++) {
                #pragma unroll
                for (int mf = 0; mf < 4; mf++) {
                    mma_bf16(acc[mf][2 * p],     ah4[mf], &bp4[p][0]);
                    mma_bf16(acc[mf][2 * p + 1], ah4[mf], &bp4[p][2]);
                }
            }
            #pragma unroll
            for (int mf = 0; mf < 4; mf++) ldsm_x4(al4[mf], cAl + aoff + mf * 16 * 80);
            #pragma unroll
            for (int p = 0; p < 2; p++) {
                #pragma unroll
                for (int mf = 0; mf < 4; mf++) {
                    mma_bf16(acc[mf][2 * p],     al4[mf], &bp4[p][0]);
                    mma_bf16(acc[mf][2 * p + 1], al4[mf], &bp4[p][2]);
                }
            }
            #pragma unroll
            for (int p = 0; p < 2; p++)   ldsm_x4(bp4[p], cBl + bo4 + p * 16 * 80);
            #pragma unroll
            for (int p = 0; p < 2; p++) {
                #pragma unroll
                for (int mf = 0; mf < 4; mf++) {
                    mma_bf16(acc[mf][2 * p],     ah4[mf], &bp4[p][0]);
                    mma_bf16(acc[mf][2 * p + 1], ah4[mf], &bp4[p][2]);
                }
            }
        }
    }

    if (mode == MODE_HEAD) {
        __syncthreads();
        float* pm_s = (float*)smem;
        float* ps_s = (float*)(smem + 2048);
        #pragma unroll
        for (int mf = 0; mf < 4; mf++) {
            int rl0 = wm * 64 + mf * 16 + (lane >> 2);
            float rv0[8], rv1[8];
            #pragma unroll
            for (int nf = 0; nf < 4; nf++) {
                int col = bn + wn * 32 + nf * 8 + (lane & 3) * 2;
                float b0 = bias[col], b1 = bias[col + 1];
                float v0 = acc[mf][nf][0] + b0;
                float v1 = acc[mf][nf][1] + b1;
                float v2 = acc[mf][nf][2] + b0;
                float v3 = acc[mf][nf][3] + b1;
                int r0g = bm + rl0;
                *(float2*)(Cf + (size_t)r0g * N + col)       = make_float2(v0, v1);
                *(float2*)(Cf + (size_t)(r0g + 8) * N + col) = make_float2(v2, v3);
                rv0[nf * 2] = v0; rv0[nf * 2 + 1] = v1;
                rv1[nf * 2] = v2; rv1[nf * 2 + 1] = v3;
            }
            float m0 = rv0[0], m1 = rv1[0];
            #pragma unroll
            for (int i = 1; i < 8; i++) { m0 = fmaxf(m0, rv0[i]); m1 = fmaxf(m1, rv1[i]); }
            m0 = fmaxf(m0, __shfl_xor_sync(0xffffffffu, m0, 1));
            m0 = fmaxf(m0, __shfl_xor_sync(0xffffffffu, m0, 2));
            m1 = fmaxf(m1, __shfl_xor_sync(0xffffffffu, m1, 1));
            m1 = fmaxf(m1, __shfl_xor_sync(0xffffffffu, m1, 2));
            float s0 = 0.0f, s1 = 0.0f;
            #pragma unroll
            for (int i = 0; i < 8; i++) {
                s0 += __expf(rv0[i] - m0);
                s1 += __expf(rv1[i] - m1);
            }
            s0 += __shfl_xor_sync(0xffffffffu, s0, 1);
            s0 += __shfl_xor_sync(0xffffffffu, s0, 2);
            s1 += __shfl_xor_sync(0xffffffffu, s1, 1);
            s1 += __shfl_xor_sync(0xffffffffu, s1, 2);
            if ((lane & 3) == 0) {
                pm_s[rl0 * 4 + wn] = m0;       ps_s[rl0 * 4 + wn] = s0;
                pm_s[(rl0 + 8) * 4 + wn] = m1; ps_s[(rl0 + 8) * 4 + wn] = s1;
            }
        }
        __syncthreads();
        if (tid < 128) {
            float m = -1e30f, s = 0.0f;
            #pragma unroll
            for (int w = 0; w < 4; w++) {
                float mi = pm_s[tid * 4 + w], si = ps_s[tid * 4 + w];
                float mn = fmaxf(m, mi);
                s = s * __expf(m - mn) + si * __expf(mi - mn);
                m = mn;
            }
            g_pm[(size_t)(bm + tid) * 256 + blockIdx.y] = m;
            g_ps[(size_t)(bm + tid) * 256 + blockIdx.y] = s;
        }
        return;
    }

    #pragma unroll
    for (int mf = 0; mf < 4; mf++) {
        int r0 = bm + wm * 64 + mf * 16 + (lane >> 2);
        #pragma unroll
        for (int nf = 0; nf < 4; nf++) {
            int col = bn + wn * 32 + nf * 8 + (lane & 3) * 2;
            float b0 = bias[col], b1 = bias[col + 1];
            float v0 = acc[mf][nf][0] + b0;
            float v1 = acc[mf][nf][1] + b1;
            float v2 = acc[mf][nf][2] + b0;
            float v3 = acc[mf][nf][3] + b1;
            if (mode == MODE_GELU) {
                v0 = gelu_exact(v0); v1 = gelu_exact(v1);
                v2 = gelu_exact(v2); v3 = gelu_exact(v3);
            } else if (mode == MODE_RES) {
                float2 r0v = *(const float2*)(res + (size_t)r0 * N + col);
                float2 r1v = *(const float2*)(res + (size_t)(r0 + 8) * N + col);
                v0 += r0v.x; v1 += r0v.y; v2 += r1v.x; v3 += r1v.y;
            }
            if (mode == MODE_RES || mode == MODE_NONE) {
                *(float2*)(Cf + (size_t)r0 * N + col)       = make_float2(v0, v1);
                *(float2*)(Cf + (size_t)(r0 + 8) * N + col) = make_float2(v2, v3);
            } else {
                uint32_t hp, lp;
                split2(v0, v1, hp, lp);
                *(uint32_t*)(Ch + (size_t)r0 * N + col) = hp;
                *(uint32_t*)(Cl + (size_t)r0 * N + col) = lp;
                split2(v2, v3, hp, lp);
                *(uint32_t*)(Ch + (size_t)(r0 + 8) * N + col) = hp;
                *(uint32_t*)(Cl + (size_t)(r0 + 8) * N + col) = lp;
            }
        }
    }
}

// ================= tensor-core flash attention (R10 proven config) ========
#define SQH 0
#define SQL 18432
#define SKV 36864
#define KVB 36864
#define ATT_SMEM (SKV + 2 * KVB)   // 110592

__global__ __launch_bounds__(256) void attn_mma(
    const __nv_bfloat16* __restrict__ qkvh,
    const __nv_bfloat16* __restrict__ qkvl,
    __nv_bfloat16* __restrict__ outh,
    __nv_bfloat16* __restrict__ outl) {
    extern __shared__ __align__(16) char sm[];
    uint32_t sb = smem_u32(sm);
    int tid = threadIdx.x, lane = tid & 31, w = tid >> 5;
    int bh = blockIdx.y, b = bh >> 3, h = bh & 7;
    int qb = (int)gridDim.x - 1 - (int)blockIdx.x;
    size_t bbase = (size_t)b * TT * (3 * CC);

    int ntiles = qb * 2 + 2;
    int sr2 = tid >> 2, qd = tid & 3;

    {
        size_t ro = bbase + (size_t)sr2 * (3 * CC);
        const __nv_bfloat16* kh = qkvh + ro + CC + h * DD + qd * 16;
        const __nv_bfloat16* kl = qkvl + ro + CC + h * DD + qd * 16;
        const __nv_bfloat16* vh = qkvh + ro + 2 * CC + h * DD + qd * 16;
        const __nv_bfloat16* vl = qkvl + ro + 2 * CC + h * DD + qd * 16;
        uint32_t sd = sb + SKV + (uint32_t)(sr2 * 144 + qd * 32);
        CP16(sd + 0,         kh);  CP16(sd + 16,         kh + 8);
        CP16(sd + 9216,      kl);  CP16(sd + 9216 + 16,  kl + 8);
        CP16(sd + 18432,     vh);  CP16(sd + 18432 + 16, vh + 8);
        CP16(sd + 27648,     vl);  CP16(sd + 27648 + 16, vl + 8);
        CP_COMMIT();
    }

    {
        int r = tid >> 1, hf = tid & 1;
        const __nv_bfloat16* qgh = qkvh + bbase + (size_t)(qb * 128 + r) * (3 * CC) + h * DD + hf * 32;
        const __nv_bfloat16* qgl = qkvl + bbase + (size_t)(qb * 128 + r) * (3 * CC) + h * DD + hf * 32;
        uint32_t qoff = (uint32_t)(r * 144 + hf * 64);
        #pragma unroll
        for (int j = 0; j < 4; j++) {
            *(uint4*)(sm + SQH + qoff + j * 16) = *(const uint4*)(qgh + j * 8);
            *(uint4*)(sm + SQL + qoff + j * 16) = *(const uint4*)(qgl + j * 8);
        }
    }
    __syncthreads();

    uint32_t qh[4][4], qlo[4][4];
    {
        uint32_t ro = (uint32_t)((w * 16 + (lane & 15)) * 144 + ((lane >> 4) * 16));
        #pragma unroll
        for (int kf = 0; kf < 4; kf++) {
            ldsm_x4(qh[kf],  sb + SQH + ro + kf * 32);
            ldsm_x4(qlo[kf], sb + SQL + ro + kf * 32);
        }
    }

    float o[8][4];
    #pragma unroll
    for (int i = 0; i < 8; i++)
        #pragma unroll
        for (int j = 0; j < 4; j++) o[i][j] = 0.0f;
    float m0 = -1e30f, m1 = -1e30f, l0 = 0.0f, l1 = 0.0f;

    for (int t = 0; t < ntiles; t++) {
        CP_WAIT0();
        __syncthreads();
        if (t + 1 < ntiles) {
            size_t ro = bbase + (size_t)((t + 1) * 64 + sr2) * (3 * CC);
            const __nv_bfloat16* kh = qkvh + ro + CC + h * DD + qd * 16;
            const __nv_bfloat16* kl = qkvl + ro + CC + h * DD + qd * 16;
            const __nv_bfloat16* vh = qkvh + ro + 2 * CC + h * DD + qd * 16;
            const __nv_bfloat16* vl = qkvl + ro + 2 * CC + h * DD + qd * 16;
            uint32_t sd = sb + SKV + ((t + 1) & 1) * KVB + (uint32_t)(sr2 * 144 + qd * 32);
            CP16(sd + 0,         kh);  CP16(sd + 16,         kh + 8);
            CP16(sd + 9216,      kl);  CP16(sd + 9216 + 16,  kl + 8);
            CP16(sd + 18432,     vh);  CP16(sd + 18432 + 16, vh + 8);
            CP16(sd + 27648,     vl);  CP16(sd + 27648 + 16, vl + 8);
        }
        CP_COMMIT();

        uint32_t KH = sb + SKV + (t & 1) * KVB;
        uint32_t KL = KH + 9216;
        uint32_t VH = KH + 18432;
        uint32_t VL = KH + 27648;

        float sacc[8][4];
        #pragma unroll
        for (int i = 0; i < 8; i++)
            #pragma unroll
            for (int j = 0; j < 4; j++) sacc[i][j] = 0.0f;

        #pragma unroll
        for (int kf = 0; kf < 4; kf++) {
            uint32_t bo = (uint32_t)((lane & 15) * 144 + kf * 32 + (lane >> 4) * 16);
            uint32_t kk[4][4];
            #pragma unroll
            for (int p = 0; p < 4; p++) ldsm_x4(kk[p], KH + bo + p * 16 * 144);
            #pragma unroll
            for (int p = 0; p < 4; p++) {
                uint32_t b0[2] = {kk[p][0], kk[p][2]};
                uint32_t b1[2] = {kk[p][1], kk[p][3]};
                mma_bf16(sacc[2 * p],     qh[kf],  b0);
                mma_bf16(sacc[2 * p + 1], qh[kf],  b1);
                mma_bf16(sacc[2 * p],     qlo[kf], b0);
                mma_bf16(sacc[2 * p + 1], qlo[kf], b1);
            }
            #pragma unroll
            for (int p = 0; p < 4; p++) ldsm_x4(kk[p], KL + bo + p * 16 * 144);
            #pragma unroll
            for (int p = 0; p < 4; p++) {
                uint32_t b0[2] = {kk[p][0], kk[p][2]};
                uint32_t b1[2] = {kk[p][1], kk[p][3]};
                mma_bf16(sacc[2 * p],     qh[kf], b0);
                mma_bf16(sacc[2 * p + 1], qh[kf], b1);
            }
        }
        #pragma unroll
        for (int nf = 0; nf < 8; nf++) {
            sacc[nf][0] *= 0.125f; sacc[nf][1] *= 0.125f;
            sacc[nf][2] *= 0.125f; sacc[nf][3] *= 0.125f;
        }

        if (t >= 2 * qb) {
            int row0 = qb * 128 + w * 16 + (lane >> 2);
            int kc0  = t * 64 + (lane & 3) * 2;
            #pragma unroll
            for (int nf = 0; nf < 8; nf++) {
                int kc = kc0 + nf * 8;
                if (kc     > row0)     sacc[nf][0] = -1e30f;
                if (kc + 1 > row0)     sacc[nf][1] = -1e30f;
                if (kc     > row0 + 8) sacc[nf][2] = -1e30f;
                if (kc + 1 > row0 + 8) sacc[nf][3] = -1e30f;
            }
        }

        float mx0 = -1e30f, mx1 = -1e30f;
        #pragma unroll
        for (int nf = 0; nf < 8; nf++) {
            mx0 = fmaxf(mx0, fmaxf(sacc[nf][0], sacc[nf][1]));
            mx1 = fmaxf(mx1, fmaxf(sacc[nf][2], sacc[nf][3]));
        }
        mx0 = fmaxf(mx0, __shfl_xor_sync(0xffffffffu, mx0, 1));
        mx0 = fmaxf(mx0, __shfl_xor_sync(0xffffffffu, mx0, 2));
        mx1 = fmaxf(mx1, __shfl_xor_sync(0xffffffffu, mx1, 1));
        mx1 = fmaxf(mx1, __shfl_xor_sync(0xffffffffu, mx1, 2));
        float mn0 = fmaxf(m0, mx0), mn1 = fmaxf(m1, mx1);
        float cs0 = __expf(m0 - mn0), cs1 = __expf(m1 - mn1);
        m0 = mn0; m1 = mn1;
        float ps0 = 0.0f, ps1 = 0.0f;
        #pragma unroll
        for (int nf = 0; nf < 8; nf++) {
            sacc[nf][0] = __expf(sacc[nf][0] - m0); ps0 += sacc[nf][0];
            sacc[nf][1] = __expf(sacc[nf][1] - m0); ps0 += sacc[nf][1];
            sacc[nf][2] = __expf(sacc[nf][2] - m1); ps1 += sacc[nf][2];
            sacc[nf][3] = __expf(sacc[nf][3] - m1); ps1 += sacc[nf][3];
        }
        l0 = l0 * cs0 + ps0;
        l1 = l1 * cs1 + ps1;
        #pragma unroll
        for (int nd = 0; nd < 8; nd++) {
            o[nd][0] *= cs0; o[nd][1] *= cs0;
            o[nd][2] *= cs1; o[nd][3] *= cs1;
        }

        uint32_t ph[4][4], plo[4][4];
        #pragma unroll
        for (int j = 0; j < 4; j++) {
            split2(sacc[2 * j][0],     sacc[2 * j][1],     ph[j][0], plo[j][0]);
            split2(sacc[2 * j][2],     sacc[2 * j][3],     ph[j][1], plo[j][1]);
            split2(sacc[2 * j + 1][0], sacc[2 * j + 1][1], ph[j][2], plo[j][2]);
            split2(sacc[2 * j + 1][2], sacc[2 * j + 1][3], ph[j][3], plo[j][3]);
        }

        #pragma unroll
        for (int nd = 0; nd < 8; nd++) {
            #pragma unroll
            for (int jp = 0; jp < 2; jp++) {
                uint32_t vv[4];
                uint32_t vo = (uint32_t)((jp * 32 + lane) * 144 + nd * 16);
                ldsm_x4_t(vv, VH + vo);
                {
                    uint32_t b0[2] = {vv[0], vv[1]};
                    uint32_t b1[2] = {vv[2], vv[3]};
                    mma_bf16(o[nd], ph[2 * jp],      b0);
                    mma_bf16(o[nd], ph[2 * jp + 1],  b1);
                    mma_bf16(o[nd], plo[2 * jp],     b0);
                    mma_bf16(o[nd], plo[2 * jp + 1], b1);
                }
                ldsm_x4_t(vv, VL + vo);
                {
                    uint32_t b0[2] = {vv[0], vv[1]};
                    uint32_t b1[2] = {vv[2], vv[3]};
                    mma_bf16(o[nd], ph[2 * jp],     b0);
                    mma_bf16(o[nd], ph[2 * jp + 1], b1);
                }
            }
        }
    }

    l0 += __shfl_xor_sync(0xffffffffu, l0, 1);
    l0 += __shfl_xor_sync(0xffffffffu, l0, 2);
    l1 += __shfl_xor_sync(0xffffffffu, l1, 1);
    l1 += __shfl_xor_sync(0xffffffffu, l1, 2);
    float inv0 = 1.0f / l0, inv1 = 1.0f / l1;
    int rowg = b * TT + qb * 128 + w * 16 + (lane >> 2);
    __nv_bfloat16* oph = outh + (size_t)rowg * CC + h * DD;
    __nv_bfloat16* opl = outl + (size_t)rowg * CC + h * DD;
    #pragma unroll
    for (int nd = 0; nd < 8; nd++) {
        int col = nd * 8 + (lane & 3) * 2;
        uint32_t hp, lp;
        split2(o[nd][0] * inv0, o[nd][1] * inv0, hp, lp);
        *(uint32_t*)(oph + col) = hp;
        *(uint32_t*)(opl + col) = lp;
        split2(o[nd][2] * inv1, o[nd][3] * inv1, hp, lp);
        *(uint32_t*)(oph + 8 * CC + col) = hp;
        *(uint32_t*)(opl + 8 * CC + col) = lp;
    }
}

// ---------------- NLL from logsumexp partials ----------------
__global__ __launch_bounds__(256) void nll2_k(const float* __restrict__ logits,
                                              const int* __restrict__ tgt,
                                              float* __restrict__ nll) {
    int row = blockIdx.x;
    const float* pm = g_pm + (size_t)row * 256;
    const float* ps = g_ps + (size_t)row * 256;
    float m = -1e30f, s = 0.0f;
    for (int j = threadIdx.x; j < NTILES_HEAD; j += 256) {
        float mi = pm[j], si = ps[j];
        float mn = fmaxf(m, mi);
        s = s * __expf(m - mn) + si * __expf(mi - mn);
        m = mn;
    }
    #pragma unroll
    for (int o = 16; o > 0; o >>= 1) {
        float m2 = __shfl_xor_sync(0xffffffffu, m, o);
        float s2 = __shfl_xor_sync(0xffffffffu, s, o);
        float mn = fmaxf(m, m2);
        s = s * __expf(m - mn) + s2 * __expf(m2 - mn);
        m = mn;
    }
    __shared__ float ms[8], ls[8];
    int wid = threadIdx.x >> 5;
    if ((threadIdx.x & 31) == 0) { ms[wid] = m; ls[wid] = s; }
    __syncthreads();
    if (threadIdx.x == 0) {
        float M = ms[0], S = ls[0];
        #pragma unroll
        for (int w = 1; w < 8; w++) {
            float mn = fmaxf(M, ms[w]);
            S = S * __expf(M - mn) + ls[w] * __expf(ms[w] - mn);
            M = mn;
        }
        float lse = M + logf(S);
        nll[row] = lse - logits[(size_t)row * VV + tgt[row]];
    }
}

__global__ __launch_bounds__(256) void loss_k(const float* __restrict__ nll,
                                              float* __restrict__ out_loss) {
    float s = 0.0f;
    for (int i = threadIdx.x; i < NROW; i += 256) s += nll[i];
    #pragma unroll
    for (int o = 16; o > 0; o >>= 1) s += __shfl_xor_sync(0xffffffffu, s, o);
    __shared__ float ws[8];
    int wid = threadIdx.x >> 5;
    if ((threadIdx.x & 31) == 0) ws[wid] = s;
    __syncthreads();
    if (threadIdx.x == 0) {
        float t = 0.0f;
        #pragma unroll
        for (int w = 0; w < 8; w++) t += ws[w];
        out_loss[0] = t / (float)NROW;
    }
}

// ---------------- orchestration ----------------
extern "C" void kernel_launch(void* const* d_in, const int* in_sizes, int n_in,
                              void* d_out, int out_size) {
    const int*   idx       = (const int*)  d_in[0];
    const int*   targets   = (const int*)  d_in[1];
    const float* tok_embed = (const float*)d_in[2];
    const float* pos_embed = (const float*)d_in[3];
    const float* qkv_w     = (const float*)d_in[4];
    const float* qkv_b     = (const float*)d_in[5];
    const float* out_w     = (const float*)d_in[6];
    const float* out_b     = (const float*)d_in[7];
    const float* ln1_w     = (const float*)d_in[8];
    const float* ln1_b     = (const float*)d_in[9];
    const float* ff1_w     = (const float*)d_in[10];
    const float* ff1_b     = (const float*)d_in[11];
    const float* ff2_w     = (const float*)d_in[12];
    const float* ff2_b     = (const float*)d_in[13];
    const float* ln2_w     = (const float*)d_in[14];
    const float* ln2_b     = (const float*)d_in[15];
    const float* lnf_w     = (const float*)d_in[16];
    const float* lnf_b     = (const float*)d_in[17];
    const float* head_w    = (const float*)d_in[18];
    const float* head_b    = (const float*)d_in[19];
    float* logits = (float*)d_out;

    static float *px = nullptr, *pnll = nullptr;
    static __nv_bfloat16 *wh, *wl, *xnh, *xnl, *qkvh, *qkvl, *atth, *attl, *ffh, *ffl;
    if (!px) {
        cudaGetSymbolAddress((void**)&px,   g_x);
        cudaGetSymbolAddress((void**)&pnll, g_nll);
        cudaGetSymbolAddress((void**)&wh,   g_wh);
        cudaGetSymbolAddress((void**)&wl,   g_wl);
        cudaGetSymbolAddress((void**)&xnh,  g_xnh);
        cudaGetSymbolAddress((void**)&xnl,  g_xnl);
        cudaGetSymbolAddress((void**)&qkvh, g_qkvh);
        cudaGetSymbolAddress((void**)&qkvl, g_qkvl);
        cudaGetSymbolAddress((void**)&atth, g_atth);
        cudaGetSymbolAddress((void**)&attl, g_attl);
        cudaGetSymbolAddress((void**)&ffh,  g_ffh);
        cudaGetSymbolAddress((void**)&ffl,  g_ffl);
        cudaFuncSetAttribute(gemm_bf,  cudaFuncAttributeMaxDynamicSharedMemorySize, GEMM_SMEM);
        cudaFuncSetAttribute(attn_mma, cudaFuncAttributeMaxDynamicSharedMemorySize, ATT_SMEM);
    }

    cvtw_k<<<2048, 256>>>(qkv_w,  wh + OFF_QKV,  wl + OFF_QKV,  6 * 3 * CC * CC / 4);
    cvtw_k<<<2048, 256>>>(out_w,  wh + OFF_OUT,  wl + OFF_OUT,  6 * CC * CC / 4);
    cvtw_k<<<2048, 256>>>(ff1_w,  wh + OFF_FF1,  wl + OFF_FF1,  6 * 4 * CC * CC / 4);
    cvtw_k<<<2048, 256>>>(ff2_w,  wh + OFF_FF2,  wl + OFF_FF2,  6 * 4 * CC * CC / 4);
    cvtw_k<<<2048, 256>>>(head_w, wh + OFF_HEAD, wl + OFF_HEAD, VV * CC / 4);

    embed_k<<<NROW, 128>>>(idx, tok_embed, pos_embed, px);

    dim3 gQKV(NROW / 128, 3 * CC / 128);   // (32, 12)
    dim3 gPROJ(NROW / 128, CC / 128);      // (32, 4)
    dim3 gFF1(NROW / 128, 4 * CC / 128);   // (32, 16)
    dim3 gHEAD(NROW / 128, VV / 128);      // (32, 250)
    dim3 gATT(TT / 128, BBATCH * HH);      // (16, 16)

    for (int l = 0; l < LLAYERS; l++) {
        ln_bf<<<NROW, 128>>>(px, ln1_w + l * CC, ln1_b + l * CC, xnh, xnl);
        gemm_bf<<<gQKV, 256, GEMM_SMEM>>>(xnh, xnl,
            wh + OFF_QKV + (size_t)l * 3 * CC * CC, wl + OFF_QKV + (size_t)l * 3 * CC * CC,
            qkv_b + l * 3 * CC, nullptr, nullptr, qkvh, qkvl, 3 * CC, CC, MODE_BF);
        attn_mma<<<gATT, 256, ATT_SMEM>>>(qkvh, qkvl, atth, attl);
        gemm_bf<<<gPROJ, 256, GEMM_SMEM>>>(atth, attl,
            wh + OFF_OUT + (size_t)l * CC * CC, wl + OFF_OUT + (size_t)l * CC * CC,
            out_b + l * CC, px, px, nullptr, nullptr, CC, CC, MODE_RES);
        ln_bf<<<NROW, 128>>>(px, ln2_w + l * CC, ln2_b + l * CC, xnh, xnl);
        gemm_bf<<<gFF1, 256, GEMM_SMEM>>>(xnh, xnl,
            wh + OFF_FF1 + (size_t)l * 4 * CC * CC, wl + OFF_FF1 + (size_t)l * 4 * CC * CC,
            ff1_b + l * 4 * CC, nullptr, nullptr, ffh, ffl, 4 * CC, CC, MODE_GELU);
        gemm_bf<<<gPROJ, 256, GEMM_SMEM>>>(ffh, ffl,
            wh + OFF_FF2 + (size_t)l * CC * 4 * CC, wl + OFF_FF2 + (size_t)l * CC * 4 * CC,
            ff2_b + l * CC, px, px, nullptr, nullptr, CC, 4 * CC, MODE_RES);
    }

    ln_bf<<<NROW, 128>>>(px, lnf_w, lnf_b, xnh, xnl);
    gemm_bf<<<gHEAD, 256, GEMM_SMEM>>>(xnh, xnl,
        wh + OFF_HEAD, wl + OFF_HEAD,
        head_b, nullptr, logits, nullptr, nullptr, VV, CC, MODE_HEAD);

    nll2_k<<<NROW, 256>>>(logits, targets, pnll);
    if (out_size > NROW * VV) {
        loss_k<<<1, 256>>>(pnll, logits + (size_t)NROW * VV);
    }
}

// round 13
// speedup vs baseline: 1.0164x; 1.0058x over previous
#include <cuda_runtime.h>
#include <cuda_bf16.h>
#include <math.h>
#include <stdint.h>

// Problem constants
#define CC 512
#define TT 2048
#define BBATCH 2
#define HH 8
#define DD 64
#define LLAYERS 6
#define VV 32000
#define NROW (BBATCH*TT)   // 4096
#define NTILES_HEAD 250

// weight plane offsets (bf16 elems)
#define OFF_QKV  0
#define OFF_OUT  4718592
#define OFF_FF1  6291456
#define OFF_FF2  12582912
#define OFF_HEAD 18874368
#define WTOTAL   35258368

// ---------------- scratch (no allocations allowed) ----------------
__device__ float g_x  [NROW * CC];
__device__ float g_nll[NROW];
__device__ float g_pm [NROW * 256];
__device__ float g_ps [NROW * 256];
__device__ __nv_bfloat16 g_wh[WTOTAL];
__device__ __nv_bfloat16 g_wl[WTOTAL];
__device__ __nv_bfloat16 g_xnh[NROW * CC],     g_xnl[NROW * CC];
__device__ __nv_bfloat16 g_qkvh[NROW * 3 * CC], g_qkvl[NROW * 3 * CC];
__device__ __nv_bfloat16 g_atth[NROW * CC],    g_attl[NROW * CC];
__device__ __nv_bfloat16 g_ffh[NROW * 4 * CC],  g_ffl[NROW * 4 * CC];

// ================= helpers =================
__device__ __forceinline__ uint32_t smem_u32(const void* p) {
    uint32_t a;
    asm("{ .reg .u64 t; cvta.to.shared.u64 t, %1; cvt.u32.u64 %0, t; }"
        : "=r"(a) : "l"(p));
    return a;
}
__device__ __forceinline__ void ldsm_x4(uint32_t* r, uint32_t addr) {
    asm volatile("ldmatrix.sync.aligned.m8n8.x4.shared.b16 {%0,%1,%2,%3}, [%4];"
                 : "=r"(r[0]), "=r"(r[1]), "=r"(r[2]), "=r"(r[3]) : "r"(addr));
}
__device__ __forceinline__ void ldsm_x4_t(uint32_t* r, uint32_t addr) {
    asm volatile("ldmatrix.sync.aligned.m8n8.x4.trans.shared.b16 {%0,%1,%2,%3}, [%4];"
                 : "=r"(r[0]), "=r"(r[1]), "=r"(r[2]), "=r"(r[3]) : "r"(addr));
}
__device__ __forceinline__ void mma_bf16(float* c, const uint32_t* a, const uint32_t* b) {
    asm volatile("mma.sync.aligned.m16n8k16.row.col.f32.bf16.bf16.f32 "
                 "{%0,%1,%2,%3}, {%4,%5,%6,%7}, {%8,%9}, {%0,%1,%2,%3};"
                 : "+f"(c[0]), "+f"(c[1]), "+f"(c[2]), "+f"(c[3])
                 : "r"(a[0]), "r"(a[1]), "r"(a[2]), "r"(a[3]),
                   "r"(b[0]), "r"(b[1]));
}
__device__ __forceinline__ void split2(float a, float b, uint32_t& hi, uint32_t& lo) {
    __nv_bfloat16 ha = __float2bfloat16(a), hb = __float2bfloat16(b);
    __nv_bfloat16 la = __float2bfloat16(a - __bfloat162float(ha));
    __nv_bfloat16 lb = __float2bfloat16(b - __bfloat162float(hb));
    hi = (uint32_t)__bfloat16_as_ushort(ha) | ((uint32_t)__bfloat16_as_ushort(hb) << 16);
    lo = (uint32_t)__bfloat16_as_ushort(la) | ((uint32_t)__bfloat16_as_ushort(lb) << 16);
}
#define CP16(dst, src) \
    asm volatile("cp.async.cg.shared.global [%0], [%1], 16;" \
                 :: "r"(dst), "l"(src) : "memory")
#define CP_COMMIT() asm volatile("cp.async.commit_group;" ::: "memory")
#define CP_WAIT0()  asm volatile("cp.async.wait_group 0;" ::: "memory")

__device__ __forceinline__ float gelu_exact(float x) {
    return 0.5f * x * (1.0f + erff(x * 0.70710678118654752f));
}

// ---------------- weight split conversion ----------------
__global__ void cvtw_k(const float* __restrict__ s,
                       __nv_bfloat16* __restrict__ dh,
                       __nv_bfloat16* __restrict__ dl, int n4) {
    int stride = gridDim.x * blockDim.x;
    int base = blockIdx.x * blockDim.x + threadIdx.x;
    for (int i = base; i < n4; i += 4 * stride) {
        float4 v[4];
        int idx[4];
        #pragma unroll
        for (int j = 0; j < 4; j++) {
            idx[j] = i + j * stride;
            if (idx[j] < n4) v[j] = ((const float4*)s)[idx[j]];
        }
        #pragma unroll
        for (int j = 0; j < 4; j++) {
            if (idx[j] < n4) {
                uint32_t h0, l0, h1, l1;
                split2(v[j].x, v[j].y, h0, l0);
                split2(v[j].z, v[j].w, h1, l1);
                *(uint2*)(dh + (size_t)idx[j] * 4) = make_uint2(h0, h1);
                *(uint2*)(dl + (size_t)idx[j] * 4) = make_uint2(l0, l1);
            }
        }
    }
}

// ---------------- embedding ----------------
__global__ void embed_k(const int* __restrict__ idx,
                        const float* __restrict__ tok,
                        const float* __restrict__ pos,
                        float* __restrict__ x) {
    int row = blockIdx.x;
    int t   = row & (TT - 1);
    int tokid = idx[row];
    const float4* te = (const float4*)(tok + (size_t)tokid * CC);
    const float4* pe = (const float4*)(pos + (size_t)t * CC);
    float4* xr = (float4*)(x + (size_t)row * CC);
    for (int i = threadIdx.x; i < CC / 4; i += blockDim.x) {
        float4 a = te[i], b = pe[i];
        a.x += b.x; a.y += b.y; a.z += b.z; a.w += b.w;
        xr[i] = a;
    }
}

// ---------------- layernorm -> bf16 hi/lo planes ----------------
__global__ __launch_bounds__(128) void ln_bf(const float* __restrict__ x,
                                             const float* __restrict__ w,
                                             const float* __restrict__ b,
                                             __nv_bfloat16* __restrict__ yh,
                                             __nv_bfloat16* __restrict__ yl) {
    int row = blockIdx.x;
    int tid = threadIdx.x;
    const float4* xr = (const float4*)(x + (size_t)row * CC);
    float4 v = xr[tid];
    float s = v.x + v.y + v.z + v.w;
    float q = v.x * v.x + v.y * v.y + v.z * v.z + v.w * v.w;
    #pragma unroll
    for (int o = 16; o > 0; o >>= 1) {
        s += __shfl_xor_sync(0xffffffffu, s, o);
        q += __shfl_xor_sync(0xffffffffu, q, o);
    }
    __shared__ float ss[4], qq[4];
    int wid = tid >> 5;
    if ((tid & 31) == 0) { ss[wid] = s; qq[wid] = q; }
    __syncthreads();
    s = ss[0] + ss[1] + ss[2] + ss[3];
    q = qq[0] + qq[1] + qq[2] + qq[3];
    float mu   = s * (1.0f / CC);
    float var  = q * (1.0f / CC) - mu * mu;
    float rstd = rsqrtf(var + 1e-5f);
    float4 wv = ((const float4*)w)[tid];
    float4 bv = ((const float4*)b)[tid];
    float o0 = (v.x - mu) * rstd * wv.x + bv.x;
    float o1 = (v.y - mu) * rstd * wv.y + bv.y;
    float o2 = (v.z - mu) * rstd * wv.z + bv.z;
    float o3 = (v.w - mu) * rstd * wv.w + bv.w;
    uint32_t h0, l0, h1, l1;
    split2(o0, o1, h0, l0);
    split2(o2, o3, h1, l1);
    *(uint2*)(yh + (size_t)row * CC + tid * 4) = make_uint2(h0, h1);
    *(uint2*)(yl + (size_t)row * CC + tid * 4) = make_uint2(l0, l1);
}

#define MODE_NONE 0
#define MODE_GELU 1
#define MODE_RES  2
#define MODE_BF   3
#define MODE_HEAD 4

// ================= gemm_bf: 128x128 CTA, 8 warps, warp tile 64x32 ===
#define BM 128
#define BN 128
#define BK 32
#define PLANE_B 10240
#define STAGE_B (4 * PLANE_B)
#define GEMM_SMEM (2 * STAGE_B)   // 81920

__global__ __launch_bounds__(256, 2) void gemm_bf(
    const __nv_bfloat16* __restrict__ Ah, const __nv_bfloat16* __restrict__ Al,
    const __nv_bfloat16* __restrict__ Bh, const __nv_bfloat16* __restrict__ Bl,
    const float* __restrict__ bias, const float* __restrict__ res,
    float* __restrict__ Cf,
    __nv_bfloat16* __restrict__ Ch, __nv_bfloat16* __restrict__ Cl,
    int N, int K, int mode) {
    extern __shared__ __align__(16) char smem[];
    uint32_t sb = smem_u32(smem);

    int tid  = threadIdx.x;
    int lane = tid & 31;
    int wid  = tid >> 5;
    int wm   = wid & 1;
    int wn   = wid >> 1;
    int bm   = blockIdx.x * BM;
    int bn   = blockIdx.y * BN;

    int r = tid >> 1;
    int cb = (tid & 1) * 2;
    const __nv_bfloat16* Agp = Ah + (size_t)(bm + r) * K + cb * 8;
    const __nv_bfloat16* Alp = Al + (size_t)(bm + r) * K + cb * 8;
    const __nv_bfloat16* Bgp = Bh + (size_t)(bn + r) * K + cb * 8;
    const __nv_bfloat16* Blp = Bl + (size_t)(bn + r) * K + cb * 8;
    uint32_t sdst = (uint32_t)(r * 80 + cb * 16);

    float acc[4][4][4];
    #pragma unroll
    for (int i = 0; i < 4; i++)
        #pragma unroll
        for (int j = 0; j < 4; j++)
            #pragma unroll
            for (int k = 0; k < 4; k++) acc[i][j][k] = 0.0f;

    int nk = K / BK;

    {
        uint32_t st = sb + sdst;
        CP16(st + 0 * PLANE_B,      Agp);     CP16(st + 0 * PLANE_B + 16, Agp + 8);
        CP16(st + 1 * PLANE_B,      Alp);     CP16(st + 1 * PLANE_B + 16, Alp + 8);
        CP16(st + 2 * PLANE_B,      Bgp);     CP16(st + 2 * PLANE_B + 16, Bgp + 8);
        CP16(st + 3 * PLANE_B,      Blp);     CP16(st + 3 * PLANE_B + 16, Blp + 8);
        CP_COMMIT();
    }

    for (int t = 0; t < nk; t++) {
        CP_WAIT0();
        __syncthreads();
        if (t + 1 < nk) {
            uint32_t st = sb + ((t + 1) & 1) * STAGE_B + sdst;
            const __nv_bfloat16* a0 = Agp + (t + 1) * BK;
            const __nv_bfloat16* a1 = Alp + (t + 1) * BK;
            const __nv_bfloat16* b0 = Bgp + (t + 1) * BK;
            const __nv_bfloat16* b1 = Blp + (t + 1) * BK;
            CP16(st + 0 * PLANE_B,      a0);  CP16(st + 0 * PLANE_B + 16, a0 + 8);
            CP16(st + 1 * PLANE_B,      a1);  CP16(st + 1 * PLANE_B + 16, a1 + 8);
            CP16(st + 2 * PLANE_B,      b0);  CP16(st + 2 * PLANE_B + 16, b0 + 8);
            CP16(st + 3 * PLANE_B,      b1);  CP16(st + 3 * PLANE_B + 16, b1 + 8);
        }
        CP_COMMIT();

        uint32_t cAh = sb + (t & 1) * STAGE_B;
        uint32_t cAl = cAh + PLANE_B;
        uint32_t cBh = cAh + 2 * PLANE_B;
        uint32_t cBl = cAh + 3 * PLANE_B;

        #pragma unroll
        for (int kf = 0; kf < 2; kf++) {
            uint32_t kb = kf * 32;
            uint32_t aoff = (uint32_t)((wm * 64 + (lane & 15)) * 80 + kb + ((lane >> 4) * 16));
            uint32_t bo4 = (uint32_t)((wn * 32 + ((lane >> 4) * 8) + (lane & 7)) * 80
                                      + kb + (((lane >> 3) & 1) * 16));

            uint32_t ah4[4][4], al4[4][4], bp4[2][4];
            #pragma unroll
            for (int mf = 0; mf < 4; mf++) ldsm_x4(ah4[mf], cAh + aoff + mf * 16 * 80);
            #pragma unroll
            for (int p = 0; p < 2; p++)   ldsm_x4(bp4[p],  cBh + bo4 + p * 16 * 80);
            #pragma unroll
            for (int p = 0; p < 2; p++) {
                #pragma unroll
                for (int mf = 0; mf < 4; mf++) {
                    mma_bf16(acc[mf][2 * p],     ah4[mf], &bp4[p][0]);
                    mma_bf16(acc[mf][2 * p + 1], ah4[mf], &bp4[p][2]);
                }
            }
            #pragma unroll
            for (int mf = 0; mf < 4; mf++) ldsm_x4(al4[mf], cAl + aoff + mf * 16 * 80);
            #pragma unroll
            for (int p = 0; p < 2; p++) {
                #pragma unroll
                for (int mf = 0; mf < 4; mf++) {
                    mma_bf16(acc[mf][2 * p],     al4[mf], &bp4[p][0]);
                    mma_bf16(acc[mf][2 * p + 1], al4[mf], &bp4[p][2]);
                }
            }
            #pragma unroll
            for (int p = 0; p < 2; p++)   ldsm_x4(bp4[p], cBl + bo4 + p * 16 * 80);
            #pragma unroll
            for (int p = 0; p < 2; p++) {
                #pragma unroll
                for (int mf = 0; mf < 4; mf++) {
                    mma_bf16(acc[mf][2 * p],     ah4[mf], &bp4[p][0]);
                    mma_bf16(acc[mf][2 * p + 1], ah4[mf], &bp4[p][2]);
                }
            }
        }
    }

    if (mode == MODE_HEAD) {
        __syncthreads();
        float* pm_s = (float*)smem;
        float* ps_s = (float*)(smem + 2048);
        #pragma unroll
        for (int mf = 0; mf < 4; mf++) {
            int rl0 = wm * 64 + mf * 16 + (lane >> 2);
            float rv0[8], rv1[8];
            #pragma unroll
            for (int nf = 0; nf < 4; nf++) {
                int col = bn + wn * 32 + nf * 8 + (lane & 3) * 2;
                float b0 = bias[col], b1 = bias[col + 1];
                float v0 = acc[mf][nf][0] + b0;
                float v1 = acc[mf][nf][1] + b1;
                float v2 = acc[mf][nf][2] + b0;
                float v3 = acc[mf][nf][3] + b1;
                int r0g = bm + rl0;
                *(float2*)(Cf + (size_t)r0g * N + col)       = make_float2(v0, v1);
                *(float2*)(Cf + (size_t)(r0g + 8) * N + col) = make_float2(v2, v3);
                rv0[nf * 2] = v0; rv0[nf * 2 + 1] = v1;
                rv1[nf * 2] = v2; rv1[nf * 2 + 1] = v3;
            }
            float m0 = rv0[0], m1 = rv1[0];
            #pragma unroll
            for (int i = 1; i < 8; i++) { m0 = fmaxf(m0, rv0[i]); m1 = fmaxf(m1, rv1[i]); }
            m0 = fmaxf(m0, __shfl_xor_sync(0xffffffffu, m0, 1));
            m0 = fmaxf(m0, __shfl_xor_sync(0xffffffffu, m0, 2));
            m1 = fmaxf(m1, __shfl_xor_sync(0xffffffffu, m1, 1));
            m1 = fmaxf(m1, __shfl_xor_sync(0xffffffffu, m1, 2));
            float s0 = 0.0f, s1 = 0.0f;
            #pragma unroll
            for (int i = 0; i < 8; i++) {
                s0 += __expf(rv0[i] - m0);
                s1 += __expf(rv1[i] - m1);
            }
            s0 += __shfl_xor_sync(0xffffffffu, s0, 1);
            s0 += __shfl_xor_sync(0xffffffffu, s0, 2);
            s1 += __shfl_xor_sync(0xffffffffu, s1, 1);
            s1 += __shfl_xor_sync(0xffffffffu, s1, 2);
            if ((lane & 3) == 0) {
                pm_s[rl0 * 4 + wn] = m0;       ps_s[rl0 * 4 + wn] = s0;
                pm_s[(rl0 + 8) * 4 + wn] = m1; ps_s[(rl0 + 8) * 4 + wn] = s1;
            }
        }
        __syncthreads();
        if (tid < 128) {
            float m = -1e30f, s = 0.0f;
            #pragma unroll
            for (int w = 0; w < 4; w++) {
                float mi = pm_s[tid * 4 + w], si = ps_s[tid * 4 + w];
                float mn = fmaxf(m, mi);
                s = s * __expf(m - mn) + si * __expf(mi - mn);
                m = mn;
            }
            g_pm[(size_t)(bm + tid) * 256 + blockIdx.y] = m;
            g_ps[(size_t)(bm + tid) * 256 + blockIdx.y] = s;
        }
        return;
    }

    #pragma unroll
    for (int mf = 0; mf < 4; mf++) {
        int r0 = bm + wm * 64 + mf * 16 + (lane >> 2);
        #pragma unroll
        for (int nf = 0; nf < 4; nf++) {
            int col = bn + wn * 32 + nf * 8 + (lane & 3) * 2;
            float b0 = bias[col], b1 = bias[col + 1];
            float v0 = acc[mf][nf][0] + b0;
            float v1 = acc[mf][nf][1] + b1;
            float v2 = acc[mf][nf][2] + b0;
            float v3 = acc[mf][nf][3] + b1;
            if (mode == MODE_GELU) {
                v0 = gelu_exact(v0); v1 = gelu_exact(v1);
                v2 = gelu_exact(v2); v3 = gelu_exact(v3);
            } else if (mode == MODE_RES) {
                float2 r0v = *(const float2*)(res + (size_t)r0 * N + col);
                float2 r1v = *(const float2*)(res + (size_t)(r0 + 8) * N + col);
                v0 += r0v.x; v1 += r0v.y; v2 += r1v.x; v3 += r1v.y;
            }
            if (mode == MODE_RES || mode == MODE_NONE) {
                *(float2*)(Cf + (size_t)r0 * N + col)       = make_float2(v0, v1);
                *(float2*)(Cf + (size_t)(r0 + 8) * N + col) = make_float2(v2, v3);
            } else {
                uint32_t hp, lp;
                split2(v0, v1, hp, lp);
                *(uint32_t*)(Ch + (size_t)r0 * N + col) = hp;
                *(uint32_t*)(Cl + (size_t)r0 * N + col) = lp;
                split2(v2, v3, hp, lp);
                *(uint32_t*)(Ch + (size_t)(r0 + 8) * N + col) = hp;
                *(uint32_t*)(Cl + (size_t)(r0 + 8) * N + col) = lp;
            }
        }
    }
}

// ====== gemm_bf64m: 64x128 CTA (M-split), 8 warps 2Mx4N, warp tile 32x32 ======
// For the N=512 GEMMs (out-proj, FF2): 256 CTAs -> 2 CTAs/SM, 16 warps.
#define APL64 5120                  // A plane: 64 rows x 80 B
#define BPL64 10240                 // B plane: 128 rows x 80 B
#define STG64 (2 * APL64 + 2 * BPL64)   // 30720
#define GEMM64_SMEM (2 * STG64)         // 61440

__global__ __launch_bounds__(256, 2) void gemm_bf64m(
    const __nv_bfloat16* __restrict__ Ah, const __nv_bfloat16* __restrict__ Al,
    const __nv_bfloat16* __restrict__ Bh, const __nv_bfloat16* __restrict__ Bl,
    const float* __restrict__ bias, const float* __restrict__ res,
    float* __restrict__ Cf, int N, int K) {
    extern __shared__ __align__(16) char smem[];
    uint32_t sb = smem_u32(smem);

    int tid  = threadIdx.x;
    int lane = tid & 31;
    int wid  = tid >> 5;
    int wm   = wid & 1;       // 2 warps in M (32 rows each)
    int wn   = wid >> 1;      // 4 warps in N (32 cols each)
    int bm   = blockIdx.x * 64;
    int bn   = blockIdx.y * 128;

    // A staging: thread -> row tid>>2, chunk tid&3 (one 16B per plane)
    int ra = tid >> 2, ca = tid & 3;
    const __nv_bfloat16* Agp = Ah + (size_t)(bm + ra) * K + ca * 8;
    const __nv_bfloat16* Alp = Al + (size_t)(bm + ra) * K + ca * 8;
    uint32_t sdA = (uint32_t)(ra * 80 + ca * 16);
    // B staging: rows ra and ra+64, chunk ca (two 16B per plane)
    const __nv_bfloat16* Bgp0 = Bh + (size_t)(bn + ra) * K + ca * 8;
    const __nv_bfloat16* Blp0 = Bl + (size_t)(bn + ra) * K + ca * 8;
    const __nv_bfloat16* Bgp1 = Bgp0 + (size_t)64 * K;
    const __nv_bfloat16* Blp1 = Blp0 + (size_t)64 * K;
    uint32_t sdB0 = (uint32_t)(ra * 80 + ca * 16);
    uint32_t sdB1 = sdB0 + 64 * 80;

    float acc[2][4][4];
    #pragma unroll
    for (int i = 0; i < 2; i++)
        #pragma unroll
        for (int j = 0; j < 4; j++)
            #pragma unroll
            for (int k = 0; k < 4; k++) acc[i][j][k] = 0.0f;

    int nk = K / BK;

    #define G64M_ISSUE(T, S) do {                                        \
        uint32_t st = sb + (uint32_t)(S) * STG64;                        \
        int k0 = (T) * BK;                                               \
        CP16(st + sdA,                     Agp + k0);                    \
        CP16(st + APL64 + sdA,             Alp + k0);                    \
        CP16(st + 2 * APL64 + sdB0,        Bgp0 + k0);                   \
        CP16(st + 2 * APL64 + sdB1,        Bgp1 + k0);                   \
        CP16(st + 2 * APL64 + BPL64 + sdB0, Blp0 + k0);                  \
        CP16(st + 2 * APL64 + BPL64 + sdB1, Blp1 + k0);                  \
    } while (0)

    G64M_ISSUE(0, 0); CP_COMMIT();

    for (int t = 0; t < nk; t++) {
        CP_WAIT0();
        __syncthreads();
        if (t + 1 < nk) { G64M_ISSUE(t + 1, (t + 1) & 1); }
        CP_COMMIT();

        uint32_t cAh = sb + (t & 1) * STG64;
        uint32_t cAl = cAh + APL64;
        uint32_t cBh = cAh + 2 * APL64;
        uint32_t cBl = cBh + BPL64;

        #pragma unroll
        for (int kf = 0; kf < 2; kf++) {
            uint32_t kb = kf * 32;
            uint32_t aoff = (uint32_t)((wm * 32 + (lane & 15)) * 80 + kb + ((lane >> 4) * 16));
            uint32_t bo4 = (uint32_t)((wn * 32 + ((lane >> 4) * 8) + (lane & 7)) * 80
                                      + kb + (((lane >> 3) & 1) * 16));

            uint32_t ah4[2][4], al4[2][4], bp4[2][4];
            #pragma unroll
            for (int mf = 0; mf < 2; mf++) ldsm_x4(ah4[mf], cAh + aoff + mf * 16 * 80);
            #pragma unroll
            for (int p = 0; p < 2; p++)   ldsm_x4(bp4[p],  cBh + bo4 + p * 16 * 80);
            #pragma unroll
            for (int p = 0; p < 2; p++) {
                #pragma unroll
                for (int mf = 0; mf < 2; mf++) {
                    mma_bf16(acc[mf][2 * p],     ah4[mf], &bp4[p][0]);
                    mma_bf16(acc[mf][2 * p + 1], ah4[mf], &bp4[p][2]);
                }
            }
            #pragma unroll
            for (int mf = 0; mf < 2; mf++) ldsm_x4(al4[mf], cAl + aoff + mf * 16 * 80);
            #pragma unroll
            for (int p = 0; p < 2; p++) {
                #pragma unroll
                for (int mf = 0; mf < 2; mf++) {
                    mma_bf16(acc[mf][2 * p],     al4[mf], &bp4[p][0]);
                    mma_bf16(acc[mf][2 * p + 1], al4[mf], &bp4[p][2]);
                }
            }
            #pragma unroll
            for (int p = 0; p < 2; p++)   ldsm_x4(bp4[p], cBl + bo4 + p * 16 * 80);
            #pragma unroll
            for (int p = 0; p < 2; p++) {
                #pragma unroll
                for (int mf = 0; mf < 2; mf++) {
                    mma_bf16(acc[mf][2 * p],     ah4[mf], &bp4[p][0]);
                    mma_bf16(acc[mf][2 * p + 1], ah4[mf], &bp4[p][2]);
                }
            }
        }
    }

    // epilogue: MODE_RES (residual add, fp32 out)
    #pragma unroll
    for (int mf = 0; mf < 2; mf++) {
        int r0 = bm + wm * 32 + mf * 16 + (lane >> 2);
        #pragma unroll
        for (int nf = 0; nf < 4; nf++) {
            int col = bn + wn * 32 + nf * 8 + (lane & 3) * 2;
            float b0 = bias[col], b1 = bias[col + 1];
            float v0 = acc[mf][nf][0] + b0;
            float v1 = acc[mf][nf][1] + b1;
            float v2 = acc[mf][nf][2] + b0;
            float v3 = acc[mf][nf][3] + b1;
            float2 r0v = *(const float2*)(res + (size_t)r0 * N + col);
            float2 r1v = *(const float2*)(res + (size_t)(r0 + 8) * N + col);
            v0 += r0v.x; v1 += r0v.y; v2 += r1v.x; v3 += r1v.y;
            *(float2*)(Cf + (size_t)r0 * N + col)       = make_float2(v0, v1);
            *(float2*)(Cf + (size_t)(r0 + 8) * N + col) = make_float2(v2, v3);
        }
    }
}

// ================= tensor-core flash attention (R10 proven config) ========
#define SQH 0
#define SQL 18432
#define SKV 36864
#define KVB 36864
#define ATT_SMEM (SKV + 2 * KVB)   // 110592

__global__ __launch_bounds__(256) void attn_mma(
    const __nv_bfloat16* __restrict__ qkvh,
    const __nv_bfloat16* __restrict__ qkvl,
    __nv_bfloat16* __restrict__ outh,
    __nv_bfloat16* __restrict__ outl) {
    extern __shared__ __align__(16) char sm[];
    uint32_t sb = smem_u32(sm);
    int tid = threadIdx.x, lane = tid & 31, w = tid >> 5;
    int bh = blockIdx.y, b = bh >> 3, h = bh & 7;
    int qb = (int)gridDim.x - 1 - (int)blockIdx.x;
    size_t bbase = (size_t)b * TT * (3 * CC);

    int ntiles = qb * 2 + 2;
    int sr2 = tid >> 2, qd = tid & 3;

    {
        size_t ro = bbase + (size_t)sr2 * (3 * CC);
        const __nv_bfloat16* kh = qkvh + ro + CC + h * DD + qd * 16;
        const __nv_bfloat16* kl = qkvl + ro + CC + h * DD + qd * 16;
        const __nv_bfloat16* vh = qkvh + ro + 2 * CC + h * DD + qd * 16;
        const __nv_bfloat16* vl = qkvl + ro + 2 * CC + h * DD + qd * 16;
        uint32_t sd = sb + SKV + (uint32_t)(sr2 * 144 + qd * 32);
        CP16(sd + 0,         kh);  CP16(sd + 16,         kh + 8);
        CP16(sd + 9216,      kl);  CP16(sd + 9216 + 16,  kl + 8);
        CP16(sd + 18432,     vh);  CP16(sd + 18432 + 16, vh + 8);
        CP16(sd + 27648,     vl);  CP16(sd + 27648 + 16, vl + 8);
        CP_COMMIT();
    }

    {
        int r = tid >> 1, hf = tid & 1;
        const __nv_bfloat16* qgh = qkvh + bbase + (size_t)(qb * 128 + r) * (3 * CC) + h * DD + hf * 32;
        const __nv_bfloat16* qgl = qkvl + bbase + (size_t)(qb * 128 + r) * (3 * CC) + h * DD + hf * 32;
        uint32_t qoff = (uint32_t)(r * 144 + hf * 64);
        #pragma unroll
        for (int j = 0; j < 4; j++) {
            *(uint4*)(sm + SQH + qoff + j * 16) = *(const uint4*)(qgh + j * 8);
            *(uint4*)(sm + SQL + qoff + j * 16) = *(const uint4*)(qgl + j * 8);
        }
    }
    __syncthreads();

    uint32_t qh[4][4], qlo[4][4];
    {
        uint32_t ro = (uint32_t)((w * 16 + (lane & 15)) * 144 + ((lane >> 4) * 16));
        #pragma unroll
        for (int kf = 0; kf < 4; kf++) {
            ldsm_x4(qh[kf],  sb + SQH + ro + kf * 32);
            ldsm_x4(qlo[kf], sb + SQL + ro + kf * 32);
        }
    }

    float o[8][4];
    #pragma unroll
    for (int i = 0; i < 8; i++)
        #pragma unroll
        for (int j = 0; j < 4; j++) o[i][j] = 0.0f;
    float m0 = -1e30f, m1 = -1e30f, l0 = 0.0f, l1 = 0.0f;

    for (int t = 0; t < ntiles; t++) {
        CP_WAIT0();
        __syncthreads();
        if (t + 1 < ntiles) {
            size_t ro = bbase + (size_t)((t + 1) * 64 + sr2) * (3 * CC);
            const __nv_bfloat16* kh = qkvh + ro + CC + h * DD + qd * 16;
            const __nv_bfloat16* kl = qkvl + ro + CC + h * DD + qd * 16;
            const __nv_bfloat16* vh = qkvh + ro + 2 * CC + h * DD + qd * 16;
            const __nv_bfloat16* vl = qkvl + ro + 2 * CC + h * DD + qd * 16;
            uint32_t sd = sb + SKV + ((t + 1) & 1) * KVB + (uint32_t)(sr2 * 144 + qd * 32);
            CP16(sd + 0,         kh);  CP16(sd + 16,         kh + 8);
            CP16(sd + 9216,      kl);  CP16(sd + 9216 + 16,  kl + 8);
            CP16(sd + 18432,     vh);  CP16(sd + 18432 + 16, vh + 8);
            CP16(sd + 27648,     vl);  CP16(sd + 27648 + 16, vl + 8);
        }
        CP_COMMIT();

        uint32_t KH = sb + SKV + (t & 1) * KVB;
        uint32_t KL = KH + 9216;
        uint32_t VH = KH + 18432;
        uint32_t VL = KH + 27648;

        float sacc[8][4];
        #pragma unroll
        for (int i = 0; i < 8; i++)
            #pragma unroll
            for (int j = 0; j < 4; j++) sacc[i][j] = 0.0f;

        #pragma unroll
        for (int kf = 0; kf < 4; kf++) {
            uint32_t bo = (uint32_t)((lane & 15) * 144 + kf * 32 + (lane >> 4) * 16);
            uint32_t kk[4][4];
            #pragma unroll
            for (int p = 0; p < 4; p++) ldsm_x4(kk[p], KH + bo + p * 16 * 144);
            #pragma unroll
            for (int p = 0; p < 4; p++) {
                uint32_t b0[2] = {kk[p][0], kk[p][2]};
                uint32_t b1[2] = {kk[p][1], kk[p][3]};
                mma_bf16(sacc[2 * p],     qh[kf],  b0);
                mma_bf16(sacc[2 * p + 1], qh[kf],  b1);
                mma_bf16(sacc[2 * p],     qlo[kf], b0);
                mma_bf16(sacc[2 * p + 1], qlo[kf], b1);
            }
            #pragma unroll
            for (int p = 0; p < 4; p++) ldsm_x4(kk[p], KL + bo + p * 16 * 144);
            #pragma unroll
            for (int p = 0; p < 4; p++) {
                uint32_t b0[2] = {kk[p][0], kk[p][2]};
                uint32_t b1[2] = {kk[p][1], kk[p][3]};
                mma_bf16(sacc[2 * p],     qh[kf], b0);
                mma_bf16(sacc[2 * p + 1], qh[kf], b1);
            }
        }
        #pragma unroll
        for (int nf = 0; nf < 8; nf++) {
            sacc[nf][0] *= 0.125f; sacc[nf][1] *= 0.125f;
            sacc[nf][2] *= 0.125f; sacc[nf][3] *= 0.125f;
        }

        if (t >= 2 * qb) {
            int row0 = qb * 128 + w * 16 + (lane >> 2);
            int kc0  = t * 64 + (lane & 3) * 2;
            #pragma unroll
            for (int nf = 0; nf < 8; nf++) {
                int kc = kc0 + nf * 8;
                if (kc     > row0)     sacc[nf][0] = -1e30f;
                if (kc + 1 > row0)     sacc[nf][1] = -1e30f;
                if (kc     > row0 + 8) sacc[nf][2] = -1e30f;
                if (kc + 1 > row0 + 8) sacc[nf][3] = -1e30f;
            }
        }

        float mx0 = -1e30f, mx1 = -1e30f;
        #pragma unroll
        for (int nf = 0; nf < 8; nf++) {
            mx0 = fmaxf(mx0, fmaxf(sacc[nf][0], sacc[nf][1]));
            mx1 = fmaxf(mx1, fmaxf(sacc[nf][2], sacc[nf][3]));
        }
        mx0 = fmaxf(mx0, __shfl_xor_sync(0xffffffffu, mx0, 1));
        mx0 = fmaxf(mx0, __shfl_xor_sync(0xffffffffu, mx0, 2));
        mx1 = fmaxf(mx1, __shfl_xor_sync(0xffffffffu, mx1, 1));
        mx1 = fmaxf(mx1, __shfl_xor_sync(0xffffffffu, mx1, 2));
        float mn0 = fmaxf(m0, mx0), mn1 = fmaxf(m1, mx1);
        float cs0 = __expf(m0 - mn0), cs1 = __expf(m1 - mn1);
        m0 = mn0; m1 = mn1;
        float ps0 = 0.0f, ps1 = 0.0f;
        #pragma unroll
        for (int nf = 0; nf < 8; nf++) {
            sacc[nf][0] = __expf(sacc[nf][0] - m0); ps0 += sacc[nf][0];
            sacc[nf][1] = __expf(sacc[nf][1] - m0); ps0 += sacc[nf][1];
            sacc[nf][2] = __expf(sacc[nf][2] - m1); ps1 += sacc[nf][2];
            sacc[nf][3] = __expf(sacc[nf][3] - m1); ps1 += sacc[nf][3];
        }
        l0 = l0 * cs0 + ps0;
        l1 = l1 * cs1 + ps1;
        #pragma unroll
        for (int nd = 0; nd < 8; nd++) {
            o[nd][0] *= cs0; o[nd][1] *= cs0;
            o[nd][2] *= cs1; o[nd][3] *= cs1;
        }

        uint32_t ph[4][4], plo[4][4];
        #pragma unroll
        for (int j = 0; j < 4; j++) {
            split2(sacc[2 * j][0],     sacc[2 * j][1],     ph[j][0], plo[j][0]);
            split2(sacc[2 * j][2],     sacc[2 * j][3],     ph[j][1], plo[j][1]);
            split2(sacc[2 * j + 1][0], sacc[2 * j + 1][1], ph[j][2], plo[j][2]);
            split2(sacc[2 * j + 1][2], sacc[2 * j + 1][3], ph[j][3], plo[j][3]);
        }

        #pragma unroll
        for (int nd = 0; nd < 8; nd++) {
            #pragma unroll
            for (int jp = 0; jp < 2; jp++) {
                uint32_t vv[4];
                uint32_t vo = (uint32_t)((jp * 32 + lane) * 144 + nd * 16);
                ldsm_x4_t(vv, VH + vo);
                {
                    uint32_t b0[2] = {vv[0], vv[1]};
                    uint32_t b1[2] = {vv[2], vv[3]};
                    mma_bf16(o[nd], ph[2 * jp],      b0);
                    mma_bf16(o[nd], ph[2 * jp + 1],  b1);
                    mma_bf16(o[nd], plo[2 * jp],     b0);
                    mma_bf16(o[nd], plo[2 * jp + 1], b1);
                }
                ldsm_x4_t(vv, VL + vo);
                {
                    uint32_t b0[2] = {vv[0], vv[1]};
                    uint32_t b1[2] = {vv[2], vv[3]};
                    mma_bf16(o[nd], ph[2 * jp],     b0);
                    mma_bf16(o[nd], ph[2 * jp + 1], b1);
                }
            }
        }
    }

    l0 += __shfl_xor_sync(0xffffffffu, l0, 1);
    l0 += __shfl_xor_sync(0xffffffffu, l0, 2);
    l1 += __shfl_xor_sync(0xffffffffu, l1, 1);
    l1 += __shfl_xor_sync(0xffffffffu, l1, 2);
    float inv0 = 1.0f / l0, inv1 = 1.0f / l1;
    int rowg = b * TT + qb * 128 + w * 16 + (lane >> 2);
    __nv_bfloat16* oph = outh + (size_t)rowg * CC + h * DD;
    __nv_bfloat16* opl = outl + (size_t)rowg * CC + h * DD;
    #pragma unroll
    for (int nd = 0; nd < 8; nd++) {
        int col = nd * 8 + (lane & 3) * 2;
        uint32_t hp, lp;
        split2(o[nd][0] * inv0, o[nd][1] * inv0, hp, lp);
        *(uint32_t*)(oph + col) = hp;
        *(uint32_t*)(opl + col) = lp;
        split2(o[nd][2] * inv1, o[nd][3] * inv1, hp, lp);
        *(uint32_t*)(oph + 8 * CC + col) = hp;
        *(uint32_t*)(opl + 8 * CC + col) = lp;
    }
}

// ---------------- NLL from logsumexp partials ----------------
__global__ __launch_bounds__(256) void nll2_k(const float* __restrict__ logits,
                                              const int* __restrict__ tgt,
                                              float* __restrict__ nll) {
    int row = blockIdx.x;
    const float* pm = g_pm + (size_t)row * 256;
    const float* ps = g_ps + (size_t)row * 256;
    float m = -1e30f, s = 0.0f;
    for (int j = threadIdx.x; j < NTILES_HEAD; j += 256) {
        float mi = pm[j], si = ps[j];
        float mn = fmaxf(m, mi);
        s = s * __expf(m - mn) + si * __expf(mi - mn);
        m = mn;
    }
    #pragma unroll
    for (int o = 16; o > 0; o >>= 1) {
        float m2 = __shfl_xor_sync(0xffffffffu, m, o);
        float s2 = __shfl_xor_sync(0xffffffffu, s, o);
        float mn = fmaxf(m, m2);
        s = s * __expf(m - mn) + s2 * __expf(m2 - mn);
        m = mn;
    }
    __shared__ float ms[8], ls[8];
    int wid = threadIdx.x >> 5;
    if ((threadIdx.x & 31) == 0) { ms[wid] = m; ls[wid] = s; }
    __syncthreads();
    if (threadIdx.x == 0) {
        float M = ms[0], S = ls[0];
        #pragma unroll
        for (int w = 1; w < 8; w++) {
            float mn = fmaxf(M, ms[w]);
            S = S * __expf(M - mn) + ls[w] * __expf(ms[w] - mn);
            M = mn;
        }
        float lse = M + logf(S);
        nll[row] = lse - logits[(size_t)row * VV + tgt[row]];
    }
}

__global__ __launch_bounds__(256) void loss_k(const float* __restrict__ nll,
                                              float* __restrict__ out_loss) {
    float s = 0.0f;
    for (int i = threadIdx.x; i < NROW; i += 256) s += nll[i];
    #pragma unroll
    for (int o = 16; o > 0; o >>= 1) s += __shfl_xor_sync(0xffffffffu, s, o);
    __shared__ float ws[8];
    int wid = threadIdx.x >> 5;
    if ((threadIdx.x & 31) == 0) ws[wid] = s;
    __syncthreads();
    if (threadIdx.x == 0) {
        float t = 0.0f;
        #pragma unroll
        for (int w = 0; w < 8; w++) t += ws[w];
        out_loss[0] = t / (float)NROW;
    }
}

// ---------------- orchestration ----------------
extern "C" void kernel_launch(void* const* d_in, const int* in_sizes, int n_in,
                              void* d_out, int out_size) {
    const int*   idx       = (const int*)  d_in[0];
    const int*   targets   = (const int*)  d_in[1];
    const float* tok_embed = (const float*)d_in[2];
    const float* pos_embed = (const float*)d_in[3];
    const float* qkv_w     = (const float*)d_in[4];
    const float* qkv_b     = (const float*)d_in[5];
    const float* out_w     = (const float*)d_in[6];
    const float* out_b     = (const float*)d_in[7];
    const float* ln1_w     = (const float*)d_in[8];
    const float* ln1_b     = (const float*)d_in[9];
    const float* ff1_w     = (const float*)d_in[10];
    const float* ff1_b     = (const float*)d_in[11];
    const float* ff2_w     = (const float*)d_in[12];
    const float* ff2_b     = (const float*)d_in[13];
    const float* ln2_w     = (const float*)d_in[14];
    const float* ln2_b     = (const float*)d_in[15];
    const float* lnf_w     = (const float*)d_in[16];
    const float* lnf_b     = (const float*)d_in[17];
    const float* head_w    = (const float*)d_in[18];
    const float* head_b    = (const float*)d_in[19];
    float* logits = (float*)d_out;

    static float *px = nullptr, *pnll = nullptr;
    static __nv_bfloat16 *wh, *wl, *xnh, *xnl, *qkvh, *qkvl, *atth, *attl, *ffh, *ffl;
    if (!px) {
        cudaGetSymbolAddress((void**)&px,   g_x);
        cudaGetSymbolAddress((void**)&pnll, g_nll);
        cudaGetSymbolAddress((void**)&wh,   g_wh);
        cudaGetSymbolAddress((void**)&wl,   g_wl);
        cudaGetSymbolAddress((void**)&xnh,  g_xnh);
        cudaGetSymbolAddress((void**)&xnl,  g_xnl);
        cudaGetSymbolAddress((void**)&qkvh, g_qkvh);
        cudaGetSymbolAddress((void**)&qkvl, g_qkvl);
        cudaGetSymbolAddress((void**)&atth, g_atth);
        cudaGetSymbolAddress((void**)&attl, g_attl);
        cudaGetSymbolAddress((void**)&ffh,  g_ffh);
        cudaGetSymbolAddress((void**)&ffl,  g_ffl);
        cudaFuncSetAttribute(gemm_bf,    cudaFuncAttributeMaxDynamicSharedMemorySize, GEMM_SMEM);
        cudaFuncSetAttribute(gemm_bf64m, cudaFuncAttributeMaxDynamicSharedMemorySize, GEMM64_SMEM);
        cudaFuncSetAttribute(attn_mma,   cudaFuncAttributeMaxDynamicSharedMemorySize, ATT_SMEM);
    }

    cvtw_k<<<2048, 256>>>(qkv_w,  wh + OFF_QKV,  wl + OFF_QKV,  6 * 3 * CC * CC / 4);
    cvtw_k<<<2048, 256>>>(out_w,  wh + OFF_OUT,  wl + OFF_OUT,  6 * CC * CC / 4);
    cvtw_k<<<2048, 256>>>(ff1_w,  wh + OFF_FF1,  wl + OFF_FF1,  6 * 4 * CC * CC / 4);
    cvtw_k<<<2048, 256>>>(ff2_w,  wh + OFF_FF2,  wl + OFF_FF2,  6 * 4 * CC * CC / 4);
    cvtw_k<<<2048, 256>>>(head_w, wh + OFF_HEAD, wl + OFF_HEAD, VV * CC / 4);

    embed_k<<<NROW, 128>>>(idx, tok_embed, pos_embed, px);

    dim3 gQKV(NROW / 128, 3 * CC / 128);   // (32, 12)
    dim3 gPROJ64(NROW / 64, CC / 128);     // (64, 4) = 256 CTAs
    dim3 gFF1(NROW / 128, 4 * CC / 128);   // (32, 16)
    dim3 gHEAD(NROW / 128, VV / 128);      // (32, 250)
    dim3 gATT(TT / 128, BBATCH * HH);      // (16, 16)

    for (int l = 0; l < LLAYERS; l++) {
        ln_bf<<<NROW, 128>>>(px, ln1_w + l * CC, ln1_b + l * CC, xnh, xnl);
        gemm_bf<<<gQKV, 256, GEMM_SMEM>>>(xnh, xnl,
            wh + OFF_QKV + (size_t)l * 3 * CC * CC, wl + OFF_QKV + (size_t)l * 3 * CC * CC,
            qkv_b + l * 3 * CC, nullptr, nullptr, qkvh, qkvl, 3 * CC, CC, MODE_BF);
        attn_mma<<<gATT, 256, ATT_SMEM>>>(qkvh, qkvl, atth, attl);
        gemm_bf64m<<<gPROJ64, 256, GEMM64_SMEM>>>(atth, attl,
            wh + OFF_OUT + (size_t)l * CC * CC, wl + OFF_OUT + (size_t)l * CC * CC,
            out_b + l * CC, px, px, CC, CC);
        ln_bf<<<NROW, 128>>>(px, ln2_w + l * CC, ln2_b + l * CC, xnh, xnl);
        gemm_bf<<<gFF1, 256, GEMM_SMEM>>>(xnh, xnl,
            wh + OFF_FF1 + (size_t)l * 4 * CC * CC, wl + OFF_FF1 + (size_t)l * 4 * CC * CC,
            ff1_b + l * 4 * CC, nullptr, nullptr, ffh, ffl, 4 * CC, CC, MODE_GELU);
        gemm_bf64m<<<gPROJ64, 256, GEMM64_SMEM>>>(ffh, ffl,
            wh + OFF_FF2 + (size_t)l * CC * 4 * CC, wl + OFF_FF2 + (size_t)l * CC * 4 * CC,
            ff2_b + l * CC, px, px, CC, 4 * CC);
    }

    ln_bf<<<NROW, 128>>>(px, lnf_w, lnf_b, xnh, xnl);
    gemm_bf<<<gHEAD, 256, GEMM_SMEM>>>(xnh, xnl,
        wh + OFF_HEAD, wl + OFF_HEAD,
        head_b, nullptr, logits, nullptr, nullptr, VV, CC, MODE_HEAD);

    nll2_k<<<NROW, 256>>>(logits, targets, pnll);
    if (out_size > NROW * VV) {
        loss_k<<<1, 256>>>(pnll, logits + (size_t)NROW * VV);
    }
}

// round 14
// speedup vs baseline: 1.0168x; 1.0005x over previous
#include <cuda_runtime.h>
#include <cuda_bf16.h>
#include <math.h>
#include <stdint.h>

// Problem constants
#define CC 512
#define TT 2048
#define BBATCH 2
#define HH 8
#define DD 64
#define LLAYERS 6
#define VV 32000
#define NROW (BBATCH*TT)   // 4096
#define NTILES_HEAD 250

// weight plane offsets (bf16 elems)
#define OFF_QKV  0
#define OFF_OUT  4718592
#define OFF_FF1  6291456
#define OFF_FF2  12582912
#define OFF_HEAD 18874368
#define WTOTAL   35258368

// ---------------- scratch (no allocations allowed) ----------------
__device__ float g_x  [NROW * CC];
__device__ float g_nll[NROW];
__device__ float g_pm [NROW * 256];
__device__ float g_ps [NROW * 256];
__device__ __nv_bfloat16 g_wh[WTOTAL];
__device__ __nv_bfloat16 g_wl[WTOTAL];
__device__ __nv_bfloat16 g_xnh[NROW * CC],     g_xnl[NROW * CC];
__device__ __nv_bfloat16 g_qkvh[NROW * 3 * CC], g_qkvl[NROW * 3 * CC];
__device__ __nv_bfloat16 g_atth[NROW * CC],    g_attl[NROW * CC];
__device__ __nv_bfloat16 g_ffh[NROW * 4 * CC],  g_ffl[NROW * 4 * CC];

// ================= helpers =================
__device__ __forceinline__ uint32_t smem_u32(const void* p) {
    uint32_t a;
    asm("{ .reg .u64 t; cvta.to.shared.u64 t, %1; cvt.u32.u64 %0, t; }"
        : "=r"(a) : "l"(p));
    return a;
}
__device__ __forceinline__ void ldsm_x4(uint32_t* r, uint32_t addr) {
    asm volatile("ldmatrix.sync.aligned.m8n8.x4.shared.b16 {%0,%1,%2,%3}, [%4];"
                 : "=r"(r[0]), "=r"(r[1]), "=r"(r[2]), "=r"(r[3]) : "r"(addr));
}
__device__ __forceinline__ void ldsm_x4_t(uint32_t* r, uint32_t addr) {
    asm volatile("ldmatrix.sync.aligned.m8n8.x4.trans.shared.b16 {%0,%1,%2,%3}, [%4];"
                 : "=r"(r[0]), "=r"(r[1]), "=r"(r[2]), "=r"(r[3]) : "r"(addr));
}
__device__ __forceinline__ void mma_bf16(float* c, const uint32_t* a, const uint32_t* b) {
    asm volatile("mma.sync.aligned.m16n8k16.row.col.f32.bf16.bf16.f32 "
                 "{%0,%1,%2,%3}, {%4,%5,%6,%7}, {%8,%9}, {%0,%1,%2,%3};"
                 : "+f"(c[0]), "+f"(c[1]), "+f"(c[2]), "+f"(c[3])
                 : "r"(a[0]), "r"(a[1]), "r"(a[2]), "r"(a[3]),
                   "r"(b[0]), "r"(b[1]));
}
__device__ __forceinline__ void split2(float a, float b, uint32_t& hi, uint32_t& lo) {
    __nv_bfloat16 ha = __float2bfloat16(a), hb = __float2bfloat16(b);
    __nv_bfloat16 la = __float2bfloat16(a - __bfloat162float(ha));
    __nv_bfloat16 lb = __float2bfloat16(b - __bfloat162float(hb));
    hi = (uint32_t)__bfloat16_as_ushort(ha) | ((uint32_t)__bfloat16_as_ushort(hb) << 16);
    lo = (uint32_t)__bfloat16_as_ushort(la) | ((uint32_t)__bfloat16_as_ushort(lb) << 16);
}
#define CP16(dst, src) \
    asm volatile("cp.async.cg.shared.global [%0], [%1], 16;" \
                 :: "r"(dst), "l"(src) : "memory")
#define CP_COMMIT() asm volatile("cp.async.commit_group;" ::: "memory")
#define CP_WAIT0()  asm volatile("cp.async.wait_group 0;" ::: "memory")

__device__ __forceinline__ float gelu_exact(float x) {
    return 0.5f * x * (1.0f + erff(x * 0.70710678118654752f));
}

// ---------------- weight split conversion ----------------
__global__ void cvtw_k(const float* __restrict__ s,
                       __nv_bfloat16* __restrict__ dh,
                       __nv_bfloat16* __restrict__ dl, int n4) {
    int stride = gridDim.x * blockDim.x;
    int base = blockIdx.x * blockDim.x + threadIdx.x;
    for (int i = base; i < n4; i += 4 * stride) {
        float4 v[4];
        int idx[4];
        #pragma unroll
        for (int j = 0; j < 4; j++) {
            idx[j] = i + j * stride;
            if (idx[j] < n4) v[j] = ((const float4*)s)[idx[j]];
        }
        #pragma unroll
        for (int j = 0; j < 4; j++) {
            if (idx[j] < n4) {
                uint32_t h0, l0, h1, l1;
                split2(v[j].x, v[j].y, h0, l0);
                split2(v[j].z, v[j].w, h1, l1);
                *(uint2*)(dh + (size_t)idx[j] * 4) = make_uint2(h0, h1);
                *(uint2*)(dl + (size_t)idx[j] * 4) = make_uint2(l0, l1);
            }
        }
    }
}

// ---------------- embedding ----------------
__global__ void embed_k(const int* __restrict__ idx,
                        const float* __restrict__ tok,
                        const float* __restrict__ pos,
                        float* __restrict__ x) {
    int row = blockIdx.x;
    int t   = row & (TT - 1);
    int tokid = idx[row];
    const float4* te = (const float4*)(tok + (size_t)tokid * CC);
    const float4* pe = (const float4*)(pos + (size_t)t * CC);
    float4* xr = (float4*)(x + (size_t)row * CC);
    for (int i = threadIdx.x; i < CC / 4; i += blockDim.x) {
        float4 a = te[i], b = pe[i];
        a.x += b.x; a.y += b.y; a.z += b.z; a.w += b.w;
        xr[i] = a;
    }
}

// ---------------- layernorm -> bf16 hi/lo planes ----------------
__global__ __launch_bounds__(128) void ln_bf(const float* __restrict__ x,
                                             const float* __restrict__ w,
                                             const float* __restrict__ b,
                                             __nv_bfloat16* __restrict__ yh,
                                             __nv_bfloat16* __restrict__ yl) {
    int row = blockIdx.x;
    int tid = threadIdx.x;
    const float4* xr = (const float4*)(x + (size_t)row * CC);
    float4 v = xr[tid];
    float s = v.x + v.y + v.z + v.w;
    float q = v.x * v.x + v.y * v.y + v.z * v.z + v.w * v.w;
    #pragma unroll
    for (int o = 16; o > 0; o >>= 1) {
        s += __shfl_xor_sync(0xffffffffu, s, o);
        q += __shfl_xor_sync(0xffffffffu, q, o);
    }
    __shared__ float ss[4], qq[4];
    int wid = tid >> 5;
    if ((tid & 31) == 0) { ss[wid] = s; qq[wid] = q; }
    __syncthreads();
    s = ss[0] + ss[1] + ss[2] + ss[3];
    q = qq[0] + qq[1] + qq[2] + qq[3];
    float mu   = s * (1.0f / CC);
    float var  = q * (1.0f / CC) - mu * mu;
    float rstd = rsqrtf(var + 1e-5f);
    float4 wv = ((const float4*)w)[tid];
    float4 bv = ((const float4*)b)[tid];
    float o0 = (v.x - mu) * rstd * wv.x + bv.x;
    float o1 = (v.y - mu) * rstd * wv.y + bv.y;
    float o2 = (v.z - mu) * rstd * wv.z + bv.z;
    float o3 = (v.w - mu) * rstd * wv.w + bv.w;
    uint32_t h0, l0, h1, l1;
    split2(o0, o1, h0, l0);
    split2(o2, o3, h1, l1);
    *(uint2*)(yh + (size_t)row * CC + tid * 4) = make_uint2(h0, h1);
    *(uint2*)(yl + (size_t)row * CC + tid * 4) = make_uint2(l0, l1);
}

#define MODE_NONE 0
#define MODE_GELU 1
#define MODE_RES  2
#define MODE_BF   3
#define MODE_HEAD 4

// ================= gemm_bf: 128x128 CTA, 8 warps, warp tile 64x32 ===
#define BM 128
#define BN 128
#define BK 32
#define PLANE_B 10240
#define STAGE_B (4 * PLANE_B)
#define GEMM_SMEM (2 * STAGE_B)   // 81920

__global__ __launch_bounds__(256, 2) void gemm_bf(
    const __nv_bfloat16* __restrict__ Ah, const __nv_bfloat16* __restrict__ Al,
    const __nv_bfloat16* __restrict__ Bh, const __nv_bfloat16* __restrict__ Bl,
    const float* __restrict__ bias, const float* __restrict__ res,
    float* __restrict__ Cf,
    __nv_bfloat16* __restrict__ Ch, __nv_bfloat16* __restrict__ Cl,
    int N, int K, int mode) {
    extern __shared__ __align__(16) char smem[];
    uint32_t sb = smem_u32(smem);

    int tid  = threadIdx.x;
    int lane = tid & 31;
    int wid  = tid >> 5;
    int wm   = wid & 1;
    int wn   = wid >> 1;
    int bm   = blockIdx.x * BM;
    int bn   = blockIdx.y * BN;

    int r = tid >> 1;
    int cb = (tid & 1) * 2;
    const __nv_bfloat16* Agp = Ah + (size_t)(bm + r) * K + cb * 8;
    const __nv_bfloat16* Alp = Al + (size_t)(bm + r) * K + cb * 8;
    const __nv_bfloat16* Bgp = Bh + (size_t)(bn + r) * K + cb * 8;
    const __nv_bfloat16* Blp = Bl + (size_t)(bn + r) * K + cb * 8;
    uint32_t sdst = (uint32_t)(r * 80 + cb * 16);

    float acc[4][4][4];
    #pragma unroll
    for (int i = 0; i < 4; i++)
        #pragma unroll
        for (int j = 0; j < 4; j++)
            #pragma unroll
            for (int k = 0; k < 4; k++) acc[i][j][k] = 0.0f;

    int nk = K / BK;

    {
        uint32_t st = sb + sdst;
        CP16(st + 0 * PLANE_B,      Agp);     CP16(st + 0 * PLANE_B + 16, Agp + 8);
        CP16(st + 1 * PLANE_B,      Alp);     CP16(st + 1 * PLANE_B + 16, Alp + 8);
        CP16(st + 2 * PLANE_B,      Bgp);     CP16(st + 2 * PLANE_B + 16, Bgp + 8);
        CP16(st + 3 * PLANE_B,      Blp);     CP16(st + 3 * PLANE_B + 16, Blp + 8);
        CP_COMMIT();
    }

    for (int t = 0; t < nk; t++) {
        CP_WAIT0();
        __syncthreads();
        if (t + 1 < nk) {
            uint32_t st = sb + ((t + 1) & 1) * STAGE_B + sdst;
            const __nv_bfloat16* a0 = Agp + (t + 1) * BK;
            const __nv_bfloat16* a1 = Alp + (t + 1) * BK;
            const __nv_bfloat16* b0 = Bgp + (t + 1) * BK;
            const __nv_bfloat16* b1 = Blp + (t + 1) * BK;
            CP16(st + 0 * PLANE_B,      a0);  CP16(st + 0 * PLANE_B + 16, a0 + 8);
            CP16(st + 1 * PLANE_B,      a1);  CP16(st + 1 * PLANE_B + 16, a1 + 8);
            CP16(st + 2 * PLANE_B,      b0);  CP16(st + 2 * PLANE_B + 16, b0 + 8);
            CP16(st + 3 * PLANE_B,      b1);  CP16(st + 3 * PLANE_B + 16, b1 + 8);
        }
        CP_COMMIT();

        uint32_t cAh = sb + (t & 1) * STAGE_B;
        uint32_t cAl = cAh + PLANE_B;
        uint32_t cBh = cAh + 2 * PLANE_B;
        uint32_t cBl = cAh + 3 * PLANE_B;

        #pragma unroll
        for (int kf = 0; kf < 2; kf++) {
            uint32_t kb = kf * 32;
            uint32_t aoff = (uint32_t)((wm * 64 + (lane & 15)) * 80 + kb + ((lane >> 4) * 16));
            uint32_t bo4 = (uint32_t)((wn * 32 + ((lane >> 4) * 8) + (lane & 7)) * 80
                                      + kb + (((lane >> 3) & 1) * 16));

            uint32_t ah4[4][4], al4[4][4], bp4[2][4];
            #pragma unroll
            for (int mf = 0; mf < 4; mf++) ldsm_x4(ah4[mf], cAh + aoff + mf * 16 * 80);
            #pragma unroll
            for (int p = 0; p < 2; p++)   ldsm_x4(bp4[p],  cBh + bo4 + p * 16 * 80);
            #pragma unroll
            for (int p = 0; p < 2; p++) {
                #pragma unroll
                for (int mf = 0; mf < 4; mf++) {
                    mma_bf16(acc[mf][2 * p],     ah4[mf], &bp4[p][0]);
                    mma_bf16(acc[mf][2 * p + 1], ah4[mf], &bp4[p][2]);
                }
            }
            #pragma unroll
            for (int mf = 0; mf < 4; mf++) ldsm_x4(al4[mf], cAl + aoff + mf * 16 * 80);
            #pragma unroll
            for (int p = 0; p < 2; p++) {
                #pragma unroll
                for (int mf = 0; mf < 4; mf++) {
                    mma_bf16(acc[mf][2 * p],     al4[mf], &bp4[p][0]);
                    mma_bf16(acc[mf][2 * p + 1], al4[mf], &bp4[p][2]);
                }
            }
            #pragma unroll
            for (int p = 0; p < 2; p++)   ldsm_x4(bp4[p], cBl + bo4 + p * 16 * 80);
            #pragma unroll
            for (int p = 0; p < 2; p++) {
                #pragma unroll
                for (int mf = 0; mf < 4; mf++) {
                    mma_bf16(acc[mf][2 * p],     ah4[mf], &bp4[p][0]);
                    mma_bf16(acc[mf][2 * p + 1], ah4[mf], &bp4[p][2]);
                }
            }
        }
    }

    if (mode == MODE_HEAD) {
        __syncthreads();
        float* pm_s = (float*)smem;
        float* ps_s = (float*)(smem + 2048);
        #pragma unroll
        for (int mf = 0; mf < 4; mf++) {
            int rl0 = wm * 64 + mf * 16 + (lane >> 2);
            float rv0[8], rv1[8];
            #pragma unroll
            for (int nf = 0; nf < 4; nf++) {
                int col = bn + wn * 32 + nf * 8 + (lane & 3) * 2;
                float b0 = bias[col], b1 = bias[col + 1];
                float v0 = acc[mf][nf][0] + b0;
                float v1 = acc[mf][nf][1] + b1;
                float v2 = acc[mf][nf][2] + b0;
                float v3 = acc[mf][nf][3] + b1;
                int r0g = bm + rl0;
                *(float2*)(Cf + (size_t)r0g * N + col)       = make_float2(v0, v1);
                *(float2*)(Cf + (size_t)(r0g + 8) * N + col) = make_float2(v2, v3);
                rv0[nf * 2] = v0; rv0[nf * 2 + 1] = v1;
                rv1[nf * 2] = v2; rv1[nf * 2 + 1] = v3;
            }
            float m0 = rv0[0], m1 = rv1[0];
            #pragma unroll
            for (int i = 1; i < 8; i++) { m0 = fmaxf(m0, rv0[i]); m1 = fmaxf(m1, rv1[i]); }
            m0 = fmaxf(m0, __shfl_xor_sync(0xffffffffu, m0, 1));
            m0 = fmaxf(m0, __shfl_xor_sync(0xffffffffu, m0, 2));
            m1 = fmaxf(m1, __shfl_xor_sync(0xffffffffu, m1, 1));
            m1 = fmaxf(m1, __shfl_xor_sync(0xffffffffu, m1, 2));
            float s0 = 0.0f, s1 = 0.0f;
            #pragma unroll
            for (int i = 0; i < 8; i++) {
                s0 += __expf(rv0[i] - m0);
                s1 += __expf(rv1[i] - m1);
            }
            s0 += __shfl_xor_sync(0xffffffffu, s0, 1);
            s0 += __shfl_xor_sync(0xffffffffu, s0, 2);
            s1 += __shfl_xor_sync(0xffffffffu, s1, 1);
            s1 += __shfl_xor_sync(0xffffffffu, s1, 2);
            if ((lane & 3) == 0) {
                pm_s[rl0 * 4 + wn] = m0;       ps_s[rl0 * 4 + wn] = s0;
                pm_s[(rl0 + 8) * 4 + wn] = m1; ps_s[(rl0 + 8) * 4 + wn] = s1;
            }
        }
        __syncthreads();
        if (tid < 128) {
            float m = -1e30f, s = 0.0f;
            #pragma unroll
            for (int w = 0; w < 4; w++) {
                float mi = pm_s[tid * 4 + w], si = ps_s[tid * 4 + w];
                float mn = fmaxf(m, mi);
                s = s * __expf(m - mn) + si * __expf(mi - mn);
                m = mn;
            }
            g_pm[(size_t)(bm + tid) * 256 + blockIdx.y] = m;
            g_ps[(size_t)(bm + tid) * 256 + blockIdx.y] = s;
        }
        return;
    }

    #pragma unroll
    for (int mf = 0; mf < 4; mf++) {
        int r0 = bm + wm * 64 + mf * 16 + (lane >> 2);
        #pragma unroll
        for (int nf = 0; nf < 4; nf++) {
            int col = bn + wn * 32 + nf * 8 + (lane & 3) * 2;
            float b0 = bias[col], b1 = bias[col + 1];
            float v0 = acc[mf][nf][0] + b0;
            float v1 = acc[mf][nf][1] + b1;
            float v2 = acc[mf][nf][2] + b0;
            float v3 = acc[mf][nf][3] + b1;
            if (mode == MODE_GELU) {
                v0 = gelu_exact(v0); v1 = gelu_exact(v1);
                v2 = gelu_exact(v2); v3 = gelu_exact(v3);
            } else if (mode == MODE_RES) {
                float2 r0v = *(const float2*)(res + (size_t)r0 * N + col);
                float2 r1v = *(const float2*)(res + (size_t)(r0 + 8) * N + col);
                v0 += r0v.x; v1 += r0v.y; v2 += r1v.x; v3 += r1v.y;
            }
            if (mode == MODE_RES || mode == MODE_NONE) {
                *(float2*)(Cf + (size_t)r0 * N + col)       = make_float2(v0, v1);
                *(float2*)(Cf + (size_t)(r0 + 8) * N + col) = make_float2(v2, v3);
            } else {
                uint32_t hp, lp;
                split2(v0, v1, hp, lp);
                *(uint32_t*)(Ch + (size_t)r0 * N + col) = hp;
                *(uint32_t*)(Cl + (size_t)r0 * N + col) = lp;
                split2(v2, v3, hp, lp);
                *(uint32_t*)(Ch + (size_t)(r0 + 8) * N + col) = hp;
                *(uint32_t*)(Cl + (size_t)(r0 + 8) * N + col) = lp;
            }
        }
    }
}

// ====== gemm_bf64m: 64x128 CTA (M-split), 8 warps 2Mx4N, warp tile 32x32 ======
#define APL64 5120
#define BPL64 10240
#define STG64 (2 * APL64 + 2 * BPL64)   // 30720
#define GEMM64_SMEM (2 * STG64)         // 61440

__global__ __launch_bounds__(256, 2) void gemm_bf64m(
    const __nv_bfloat16* __restrict__ Ah, const __nv_bfloat16* __restrict__ Al,
    const __nv_bfloat16* __restrict__ Bh, const __nv_bfloat16* __restrict__ Bl,
    const float* __restrict__ bias, const float* __restrict__ res,
    float* __restrict__ Cf, int N, int K) {
    extern __shared__ __align__(16) char smem[];
    uint32_t sb = smem_u32(smem);

    int tid  = threadIdx.x;
    int lane = tid & 31;
    int wid  = tid >> 5;
    int wm   = wid & 1;
    int wn   = wid >> 1;
    int bm   = blockIdx.x * 64;
    int bn   = blockIdx.y * 128;

    int ra = tid >> 2, ca = tid & 3;
    const __nv_bfloat16* Agp = Ah + (size_t)(bm + ra) * K + ca * 8;
    const __nv_bfloat16* Alp = Al + (size_t)(bm + ra) * K + ca * 8;
    uint32_t sdA = (uint32_t)(ra * 80 + ca * 16);
    const __nv_bfloat16* Bgp0 = Bh + (size_t)(bn + ra) * K + ca * 8;
    const __nv_bfloat16* Blp0 = Bl + (size_t)(bn + ra) * K + ca * 8;
    const __nv_bfloat16* Bgp1 = Bgp0 + (size_t)64 * K;
    const __nv_bfloat16* Blp1 = Blp0 + (size_t)64 * K;
    uint32_t sdB0 = (uint32_t)(ra * 80 + ca * 16);
    uint32_t sdB1 = sdB0 + 64 * 80;

    float acc[2][4][4];
    #pragma unroll
    for (int i = 0; i < 2; i++)
        #pragma unroll
        for (int j = 0; j < 4; j++)
            #pragma unroll
            for (int k = 0; k < 4; k++) acc[i][j][k] = 0.0f;

    int nk = K / BK;

    #define G64M_ISSUE(T, S) do {                                        \
        uint32_t st = sb + (uint32_t)(S) * STG64;                        \
        int k0 = (T) * BK;                                               \
        CP16(st + sdA,                     Agp + k0);                    \
        CP16(st + APL64 + sdA,             Alp + k0);                    \
        CP16(st + 2 * APL64 + sdB0,        Bgp0 + k0);                   \
        CP16(st + 2 * APL64 + sdB1,        Bgp1 + k0);                   \
        CP16(st + 2 * APL64 + BPL64 + sdB0, Blp0 + k0);                  \
        CP16(st + 2 * APL64 + BPL64 + sdB1, Blp1 + k0);                  \
    } while (0)

    G64M_ISSUE(0, 0); CP_COMMIT();

    for (int t = 0; t < nk; t++) {
        CP_WAIT0();
        __syncthreads();
        if (t + 1 < nk) { G64M_ISSUE(t + 1, (t + 1) & 1); }
        CP_COMMIT();

        uint32_t cAh = sb + (t & 1) * STG64;
        uint32_t cAl = cAh + APL64;
        uint32_t cBh = cAh + 2 * APL64;
        uint32_t cBl = cBh + BPL64;

        #pragma unroll
        for (int kf = 0; kf < 2; kf++) {
            uint32_t kb = kf * 32;
            uint32_t aoff = (uint32_t)((wm * 32 + (lane & 15)) * 80 + kb + ((lane >> 4) * 16));
            uint32_t bo4 = (uint32_t)((wn * 32 + ((lane >> 4) * 8) + (lane & 7)) * 80
                                      + kb + (((lane >> 3) & 1) * 16));

            uint32_t ah4[2][4], al4[2][4], bp4[2][4];
            #pragma unroll
            for (int mf = 0; mf < 2; mf++) ldsm_x4(ah4[mf], cAh + aoff + mf * 16 * 80);
            #pragma unroll
            for (int p = 0; p < 2; p++)   ldsm_x4(bp4[p],  cBh + bo4 + p * 16 * 80);
            #pragma unroll
            for (int p = 0; p < 2; p++) {
                #pragma unroll
                for (int mf = 0; mf < 2; mf++) {
                    mma_bf16(acc[mf][2 * p],     ah4[mf], &bp4[p][0]);
                    mma_bf16(acc[mf][2 * p + 1], ah4[mf], &bp4[p][2]);
                }
            }
            #pragma unroll
            for (int mf = 0; mf < 2; mf++) ldsm_x4(al4[mf], cAl + aoff + mf * 16 * 80);
            #pragma unroll
            for (int p = 0; p < 2; p++) {
                #pragma unroll
                for (int mf = 0; mf < 2; mf++) {
                    mma_bf16(acc[mf][2 * p],     al4[mf], &bp4[p][0]);
                    mma_bf16(acc[mf][2 * p + 1], al4[mf], &bp4[p][2]);
                }
            }
            #pragma unroll
            for (int p = 0; p < 2; p++)   ldsm_x4(bp4[p], cBl + bo4 + p * 16 * 80);
            #pragma unroll
            for (int p = 0; p < 2; p++) {
                #pragma unroll
                for (int mf = 0; mf < 2; mf++) {
                    mma_bf16(acc[mf][2 * p],     ah4[mf], &bp4[p][0]);
                    mma_bf16(acc[mf][2 * p + 1], ah4[mf], &bp4[p][2]);
                }
            }
        }
    }

    #pragma unroll
    for (int mf = 0; mf < 2; mf++) {
        int r0 = bm + wm * 32 + mf * 16 + (lane >> 2);
        #pragma unroll
        for (int nf = 0; nf < 4; nf++) {
            int col = bn + wn * 32 + nf * 8 + (lane & 3) * 2;
            float b0 = bias[col], b1 = bias[col + 1];
            float v0 = acc[mf][nf][0] + b0;
            float v1 = acc[mf][nf][1] + b1;
            float v2 = acc[mf][nf][2] + b0;
            float v3 = acc[mf][nf][3] + b1;
            float2 r0v = *(const float2*)(res + (size_t)r0 * N + col);
            float2 r1v = *(const float2*)(res + (size_t)(r0 + 8) * N + col);
            v0 += r0v.x; v1 += r0v.y; v2 += r1v.x; v3 += r1v.y;
            *(float2*)(Cf + (size_t)r0 * N + col)       = make_float2(v0, v1);
            *(float2*)(Cf + (size_t)(r0 + 8) * N + col) = make_float2(v2, v3);
        }
    }
}

// ================= tensor-core flash attention (front-loaded fragments) ========
#define SQH 0
#define SQL 18432
#define SKV 36864
#define KVB 36864
#define ATT_SMEM (SKV + 2 * KVB)   // 110592

__global__ __launch_bounds__(256) void attn_mma(
    const __nv_bfloat16* __restrict__ qkvh,
    const __nv_bfloat16* __restrict__ qkvl,
    __nv_bfloat16* __restrict__ outh,
    __nv_bfloat16* __restrict__ outl) {
    extern __shared__ __align__(16) char sm[];
    uint32_t sb = smem_u32(sm);
    int tid = threadIdx.x, lane = tid & 31, w = tid >> 5;
    int bh = blockIdx.y, b = bh >> 3, h = bh & 7;
    int qb = (int)gridDim.x - 1 - (int)blockIdx.x;
    size_t bbase = (size_t)b * TT * (3 * CC);

    int ntiles = qb * 2 + 2;
    int sr2 = tid >> 2, qd = tid & 3;

    {
        size_t ro = bbase + (size_t)sr2 * (3 * CC);
        const __nv_bfloat16* kh = qkvh + ro + CC + h * DD + qd * 16;
        const __nv_bfloat16* kl = qkvl + ro + CC + h * DD + qd * 16;
        const __nv_bfloat16* vh = qkvh + ro + 2 * CC + h * DD + qd * 16;
        const __nv_bfloat16* vl = qkvl + ro + 2 * CC + h * DD + qd * 16;
        uint32_t sd = sb + SKV + (uint32_t)(sr2 * 144 + qd * 32);
        CP16(sd + 0,         kh);  CP16(sd + 16,         kh + 8);
        CP16(sd + 9216,      kl);  CP16(sd + 9216 + 16,  kl + 8);
        CP16(sd + 18432,     vh);  CP16(sd + 18432 + 16, vh + 8);
        CP16(sd + 27648,     vl);  CP16(sd + 27648 + 16, vl + 8);
        CP_COMMIT();
    }

    {
        int r = tid >> 1, hf = tid & 1;
        const __nv_bfloat16* qgh = qkvh + bbase + (size_t)(qb * 128 + r) * (3 * CC) + h * DD + hf * 32;
        const __nv_bfloat16* qgl = qkvl + bbase + (size_t)(qb * 128 + r) * (3 * CC) + h * DD + hf * 32;
        uint32_t qoff = (uint32_t)(r * 144 + hf * 64);
        #pragma unroll
        for (int j = 0; j < 4; j++) {
            *(uint4*)(sm + SQH + qoff + j * 16) = *(const uint4*)(qgh + j * 8);
            *(uint4*)(sm + SQL + qoff + j * 16) = *(const uint4*)(qgl + j * 8);
        }
    }
    __syncthreads();

    uint32_t qh[4][4], qlo[4][4];
    {
        uint32_t ro = (uint32_t)((w * 16 + (lane & 15)) * 144 + ((lane >> 4) * 16));
        #pragma unroll
        for (int kf = 0; kf < 4; kf++) {
            ldsm_x4(qh[kf],  sb + SQH + ro + kf * 32);
            ldsm_x4(qlo[kf], sb + SQL + ro + kf * 32);
        }
    }

    float o[8][4];
    #pragma unroll
    for (int i = 0; i < 8; i++)
        #pragma unroll
        for (int j = 0; j < 4; j++) o[i][j] = 0.0f;
    float m0 = -1e30f, m1 = -1e30f, l0 = 0.0f, l1 = 0.0f;

    for (int t = 0; t < ntiles; t++) {
        CP_WAIT0();
        __syncthreads();
        if (t + 1 < ntiles) {
            size_t ro = bbase + (size_t)((t + 1) * 64 + sr2) * (3 * CC);
            const __nv_bfloat16* kh = qkvh + ro + CC + h * DD + qd * 16;
            const __nv_bfloat16* kl = qkvl + ro + CC + h * DD + qd * 16;
            const __nv_bfloat16* vh = qkvh + ro + 2 * CC + h * DD + qd * 16;
            const __nv_bfloat16* vl = qkvl + ro + 2 * CC + h * DD + qd * 16;
            uint32_t sd = sb + SKV + ((t + 1) & 1) * KVB + (uint32_t)(sr2 * 144 + qd * 32);
            CP16(sd + 0,         kh);  CP16(sd + 16,         kh + 8);
            CP16(sd + 9216,      kl);  CP16(sd + 9216 + 16,  kl + 8);
            CP16(sd + 18432,     vh);  CP16(sd + 18432 + 16, vh + 8);
            CP16(sd + 27648,     vl);  CP16(sd + 27648 + 16, vl + 8);
        }
        CP_COMMIT();

        uint32_t KH = sb + SKV + (t & 1) * KVB;
        uint32_t KL = KH + 9216;
        uint32_t VH = KH + 18432;
        uint32_t VL = KH + 27648;

        float sacc[8][4];
        #pragma unroll
        for (int i = 0; i < 8; i++)
            #pragma unroll
            for (int j = 0; j < 4; j++) sacc[i][j] = 0.0f;

        // ---- S = Q K^T: front-load KH+KL fragments, then 24 MMAs per kf ----
        #pragma unroll
        for (int kf = 0; kf < 4; kf++) {
            uint32_t bo = (uint32_t)((lane & 15) * 144 + kf * 32 + (lane >> 4) * 16);
            uint32_t kkh[4][4], kkl[4][4];
            #pragma unroll
            for (int p = 0; p < 4; p++) ldsm_x4(kkh[p], KH + bo + p * 16 * 144);
            #pragma unroll
            for (int p = 0; p < 4; p++) ldsm_x4(kkl[p], KL + bo + p * 16 * 144);
            #pragma unroll
            for (int p = 0; p < 4; p++) {
                uint32_t b0[2] = {kkh[p][0], kkh[p][2]};
                uint32_t b1[2] = {kkh[p][1], kkh[p][3]};
                mma_bf16(sacc[2 * p],     qh[kf],  b0);
                mma_bf16(sacc[2 * p + 1], qh[kf],  b1);
                mma_bf16(sacc[2 * p],     qlo[kf], b0);
                mma_bf16(sacc[2 * p + 1], qlo[kf], b1);
            }
            #pragma unroll
            for (int p = 0; p < 4; p++) {
                uint32_t b0[2] = {kkl[p][0], kkl[p][2]};
                uint32_t b1[2] = {kkl[p][1], kkl[p][3]};
                mma_bf16(sacc[2 * p],     qh[kf], b0);
                mma_bf16(sacc[2 * p + 1], qh[kf], b1);
            }
        }
        #pragma unroll
        for (int nf = 0; nf < 8; nf++) {
            sacc[nf][0] *= 0.125f; sacc[nf][1] *= 0.125f;
            sacc[nf][2] *= 0.125f; sacc[nf][3] *= 0.125f;
        }

        if (t >= 2 * qb) {
            int row0 = qb * 128 + w * 16 + (lane >> 2);
            int kc0  = t * 64 + (lane & 3) * 2;
            #pragma unroll
            for (int nf = 0; nf < 8; nf++) {
                int kc = kc0 + nf * 8;
                if (kc     > row0)     sacc[nf][0] = -1e30f;
                if (kc + 1 > row0)     sacc[nf][1] = -1e30f;
                if (kc     > row0 + 8) sacc[nf][2] = -1e30f;
                if (kc + 1 > row0 + 8) sacc[nf][3] = -1e30f;
            }
        }

        float mx0 = -1e30f, mx1 = -1e30f;
        #pragma unroll
        for (int nf = 0; nf < 8; nf++) {
            mx0 = fmaxf(mx0, fmaxf(sacc[nf][0], sacc[nf][1]));
            mx1 = fmaxf(mx1, fmaxf(sacc[nf][2], sacc[nf][3]));
        }
        mx0 = fmaxf(mx0, __shfl_xor_sync(0xffffffffu, mx0, 1));
        mx0 = fmaxf(mx0, __shfl_xor_sync(0xffffffffu, mx0, 2));
        mx1 = fmaxf(mx1, __shfl_xor_sync(0xffffffffu, mx1, 1));
        mx1 = fmaxf(mx1, __shfl_xor_sync(0xffffffffu, mx1, 2));
        float mn0 = fmaxf(m0, mx0), mn1 = fmaxf(m1, mx1);
        float cs0 = __expf(m0 - mn0), cs1 = __expf(m1 - mn1);
        m0 = mn0; m1 = mn1;
        float ps0 = 0.0f, ps1 = 0.0f;
        #pragma unroll
        for (int nf = 0; nf < 8; nf++) {
            sacc[nf][0] = __expf(sacc[nf][0] - m0); ps0 += sacc[nf][0];
            sacc[nf][1] = __expf(sacc[nf][1] - m0); ps0 += sacc[nf][1];
            sacc[nf][2] = __expf(sacc[nf][2] - m1); ps1 += sacc[nf][2];
            sacc[nf][3] = __expf(sacc[nf][3] - m1); ps1 += sacc[nf][3];
        }
        l0 = l0 * cs0 + ps0;
        l1 = l1 * cs1 + ps1;
        #pragma unroll
        for (int nd = 0; nd < 8; nd++) {
            o[nd][0] *= cs0; o[nd][1] *= cs0;
            o[nd][2] *= cs1; o[nd][3] *= cs1;
        }

        uint32_t ph[4][4], plo[4][4];
        #pragma unroll
        for (int j = 0; j < 4; j++) {
            split2(sacc[2 * j][0],     sacc[2 * j][1],     ph[j][0], plo[j][0]);
            split2(sacc[2 * j][2],     sacc[2 * j][3],     ph[j][1], plo[j][1]);
            split2(sacc[2 * j + 1][0], sacc[2 * j + 1][1], ph[j][2], plo[j][2]);
            split2(sacc[2 * j + 1][2], sacc[2 * j + 1][3], ph[j][3], plo[j][3]);
        }

        // ---- O += P V: front-load all 4 V fragments per nd, then 12 MMAs ----
        #pragma unroll
        for (int nd = 0; nd < 8; nd++) {
            uint32_t vh0[4], vh1[4], vl0[4], vl1[4];
            uint32_t vo0 = (uint32_t)(lane * 144 + nd * 16);
            uint32_t vo1 = (uint32_t)((32 + lane) * 144 + nd * 16);
            ldsm_x4_t(vh0, VH + vo0);
            ldsm_x4_t(vh1, VH + vo1);
            ldsm_x4_t(vl0, VL + vo0);
            ldsm_x4_t(vl1, VL + vo1);
            {
                uint32_t b0[2] = {vh0[0], vh0[1]};
                uint32_t b1[2] = {vh0[2], vh0[3]};
                mma_bf16(o[nd], ph[0],  b0);
                mma_bf16(o[nd], ph[1],  b1);
                mma_bf16(o[nd], plo[0], b0);
                mma_bf16(o[nd], plo[1], b1);
            }
            {
                uint32_t b0[2] = {vh1[0], vh1[1]};
                uint32_t b1[2] = {vh1[2], vh1[3]};
                mma_bf16(o[nd], ph[2],  b0);
                mma_bf16(o[nd], ph[3],  b1);
                mma_bf16(o[nd], plo[2], b0);
                mma_bf16(o[nd], plo[3], b1);
            }
            {
                uint32_t b0[2] = {vl0[0], vl0[1]};
                uint32_t b1[2] = {vl0[2], vl0[3]};
                mma_bf16(o[nd], ph[0], b0);
                mma_bf16(o[nd], ph[1], b1);
            }
            {
                uint32_t b0[2] = {vl1[0], vl1[1]};
                uint32_t b1[2] = {vl1[2], vl1[3]};
                mma_bf16(o[nd], ph[2], b0);
                mma_bf16(o[nd], ph[3], b1);
            }
        }
    }

    l0 += __shfl_xor_sync(0xffffffffu, l0, 1);
    l0 += __shfl_xor_sync(0xffffffffu, l0, 2);
    l1 += __shfl_xor_sync(0xffffffffu, l1, 1);
    l1 += __shfl_xor_sync(0xffffffffu, l1, 2);
    float inv0 = 1.0f / l0, inv1 = 1.0f / l1;
    int rowg = b * TT + qb * 128 + w * 16 + (lane >> 2);
    __nv_bfloat16* oph = outh + (size_t)rowg * CC + h * DD;
    __nv_bfloat16* opl = outl + (size_t)rowg * CC + h * DD;
    #pragma unroll
    for (int nd = 0; nd < 8; nd++) {
        int col = nd * 8 + (lane & 3) * 2;
        uint32_t hp, lp;
        split2(o[nd][0] * inv0, o[nd][1] * inv0, hp, lp);
        *(uint32_t*)(oph + col) = hp;
        *(uint32_t*)(opl + col) = lp;
        split2(o[nd][2] * inv1, o[nd][3] * inv1, hp, lp);
        *(uint32_t*)(oph + 8 * CC + col) = hp;
        *(uint32_t*)(opl + 8 * CC + col) = lp;
    }
}

// ---------------- NLL from logsumexp partials ----------------
__global__ __launch_bounds__(256) void nll2_k(const float* __restrict__ logits,
                                              const int* __restrict__ tgt,
                                              float* __restrict__ nll) {
    int row = blockIdx.x;
    const float* pm = g_pm + (size_t)row * 256;
    const float* ps = g_ps + (size_t)row * 256;
    float m = -1e30f, s = 0.0f;
    for (int j = threadIdx.x; j < NTILES_HEAD; j += 256) {
        float mi = pm[j], si = ps[j];
        float mn = fmaxf(m, mi);
        s = s * __expf(m - mn) + si * __expf(mi - mn);
        m = mn;
    }
    #pragma unroll
    for (int o = 16; o > 0; o >>= 1) {
        float m2 = __shfl_xor_sync(0xffffffffu, m, o);
        float s2 = __shfl_xor_sync(0xffffffffu, s, o);
        float mn = fmaxf(m, m2);
        s = s * __expf(m - mn) + s2 * __expf(m2 - mn);
        m = mn;
    }
    __shared__ float ms[8], ls[8];
    int wid = threadIdx.x >> 5;
    if ((threadIdx.x & 31) == 0) { ms[wid] = m; ls[wid] = s; }
    __syncthreads();
    if (threadIdx.x == 0) {
        float M = ms[0], S = ls[0];
        #pragma unroll
        for (int w = 1; w < 8; w++) {
            float mn = fmaxf(M, ms[w]);
            S = S * __expf(M - mn) + ls[w] * __expf(ms[w] - mn);
            M = mn;
        }
        float lse = M + logf(S);
        nll[row] = lse - logits[(size_t)row * VV + tgt[row]];
    }
}

__global__ __launch_bounds__(256) void loss_k(const float* __restrict__ nll,
                                              float* __restrict__ out_loss) {
    float s = 0.0f;
    for (int i = threadIdx.x; i < NROW; i += 256) s += nll[i];
    #pragma unroll
    for (int o = 16; o > 0; o >>= 1) s += __shfl_xor_sync(0xffffffffu, s, o);
    __shared__ float ws[8];
    int wid = threadIdx.x >> 5;
    if ((threadIdx.x & 31) == 0) ws[wid] = s;
    __syncthreads();
    if (threadIdx.x == 0) {
        float t = 0.0f;
        #pragma unroll
        for (int w = 0; w < 8; w++) t += ws[w];
        out_loss[0] = t / (float)NROW;
    }
}

// ---------------- orchestration ----------------
extern "C" void kernel_launch(void* const* d_in, const int* in_sizes, int n_in,
                              void* d_out, int out_size) {
    const int*   idx       = (const int*)  d_in[0];
    const int*   targets   = (const int*)  d_in[1];
    const float* tok_embed = (const float*)d_in[2];
    const float* pos_embed = (const float*)d_in[3];
    const float* qkv_w     = (const float*)d_in[4];
    const float* qkv_b     = (const float*)d_in[5];
    const float* out_w     = (const float*)d_in[6];
    const float* out_b     = (const float*)d_in[7];
    const float* ln1_w     = (const float*)d_in[8];
    const float* ln1_b     = (const float*)d_in[9];
    const float* ff1_w     = (const float*)d_in[10];
    const float* ff1_b     = (const float*)d_in[11];
    const float* ff2_w     = (const float*)d_in[12];
    const float* ff2_b     = (const float*)d_in[13];
    const float* ln2_w     = (const float*)d_in[14];
    const float* ln2_b     = (const float*)d_in[15];
    const float* lnf_w     = (const float*)d_in[16];
    const float* lnf_b     = (const float*)d_in[17];
    const float* head_w    = (const float*)d_in[18];
    const float* head_b    = (const float*)d_in[19];
    float* logits = (float*)d_out;

    static float *px = nullptr, *pnll = nullptr;
    static __nv_bfloat16 *wh, *wl, *xnh, *xnl, *qkvh, *qkvl, *atth, *attl, *ffh, *ffl;
    if (!px) {
        cudaGetSymbolAddress((void**)&px,   g_x);
        cudaGetSymbolAddress((void**)&pnll, g_nll);
        cudaGetSymbolAddress((void**)&wh,   g_wh);
        cudaGetSymbolAddress((void**)&wl,   g_wl);
        cudaGetSymbolAddress((void**)&xnh,  g_xnh);
        cudaGetSymbolAddress((void**)&xnl,  g_xnl);
        cudaGetSymbolAddress((void**)&qkvh, g_qkvh);
        cudaGetSymbolAddress((void**)&qkvl, g_qkvl);
        cudaGetSymbolAddress((void**)&atth, g_atth);
        cudaGetSymbolAddress((void**)&attl, g_attl);
        cudaGetSymbolAddress((void**)&ffh,  g_ffh);
        cudaGetSymbolAddress((void**)&ffl,  g_ffl);
        cudaFuncSetAttribute(gemm_bf,    cudaFuncAttributeMaxDynamicSharedMemorySize, GEMM_SMEM);
        cudaFuncSetAttribute(gemm_bf64m, cudaFuncAttributeMaxDynamicSharedMemorySize, GEMM64_SMEM);
        cudaFuncSetAttribute(attn_mma,   cudaFuncAttributeMaxDynamicSharedMemorySize, ATT_SMEM);
    }

    cvtw_k<<<2048, 256>>>(qkv_w,  wh + OFF_QKV,  wl + OFF_QKV,  6 * 3 * CC * CC / 4);
    cvtw_k<<<2048, 256>>>(out_w,  wh + OFF_OUT,  wl + OFF_OUT,  6 * CC * CC / 4);
    cvtw_k<<<2048, 256>>>(ff1_w,  wh + OFF_FF1,  wl + OFF_FF1,  6 * 4 * CC * CC / 4);
    cvtw_k<<<2048, 256>>>(ff2_w,  wh + OFF_FF2,  wl + OFF_FF2,  6 * 4 * CC * CC / 4);
    cvtw_k<<<2048, 256>>>(head_w, wh + OFF_HEAD, wl + OFF_HEAD, VV * CC / 4);

    embed_k<<<NROW, 128>>>(idx, tok_embed, pos_embed, px);

    dim3 gQKV(NROW / 128, 3 * CC / 128);   // (32, 12)
    dim3 gPROJ64(NROW / 64, CC / 128);     // (64, 4) = 256 CTAs
    dim3 gFF1(NROW / 128, 4 * CC / 128);   // (32, 16)
    dim3 gHEAD(NROW / 128, VV / 128);      // (32, 250)
    dim3 gATT(TT / 128, BBATCH * HH);      // (16, 16)

    for (int l = 0; l < LLAYERS; l++) {
        ln_bf<<<NROW, 128>>>(px, ln1_w + l * CC, ln1_b + l * CC, xnh, xnl);
        gemm_bf<<<gQKV, 256, GEMM_SMEM>>>(xnh, xnl,
            wh + OFF_QKV + (size_t)l * 3 * CC * CC, wl + OFF_QKV + (size_t)l * 3 * CC * CC,
            qkv_b + l * 3 * CC, nullptr, nullptr, qkvh, qkvl, 3 * CC, CC, MODE_BF);
        attn_mma<<<gATT, 256, ATT_SMEM>>>(qkvh, qkvl, atth, attl);
        gemm_bf64m<<<gPROJ64, 256, GEMM64_SMEM>>>(atth, attl,
            wh + OFF_OUT + (size_t)l * CC * CC, wl + OFF_OUT + (size_t)l * CC * CC,
            out_b + l * CC, px, px, CC, CC);
        ln_bf<<<NROW, 128>>>(px, ln2_w + l * CC, ln2_b + l * CC, xnh, xnl);
        gemm_bf<<<gFF1, 256, GEMM_SMEM>>>(xnh, xnl,
            wh + OFF_FF1 + (size_t)l * 4 * CC * CC, wl + OFF_FF1 + (size_t)l * 4 * CC * CC,
            ff1_b + l * 4 * CC, nullptr, nullptr, ffh, ffl, 4 * CC, CC, MODE_GELU);
        gemm_bf64m<<<gPROJ64, 256, GEMM64_SMEM>>>(ffh, ffl,
            wh + OFF_FF2 + (size_t)l * CC * 4 * CC, wl + OFF_FF2 + (size_t)l * CC * 4 * CC,
            ff2_b + l * CC, px, px, CC, 4 * CC);
    }

    ln_bf<<<NROW, 128>>>(px, lnf_w, lnf_b, xnh, xnl);
    gemm_bf<<<gHEAD, 256, GEMM_SMEM>>>(xnh, xnl,
        wh + OFF_HEAD, wl + OFF_HEAD,
        head_b, nullptr, logits, nullptr, nullptr, VV, CC, MODE_HEAD);

    nll2_k<<<NROW, 256>>>(logits, targets, pnll);
    if (out_size > NROW * VV) {
        loss_k<<<1, 256>>>(pnll, logits + (size_t)NROW * VV);
    }
}

// round 15
// speedup vs baseline: 1.0185x; 1.0016x over previous
#include <cuda_runtime.h>
#include <cuda_bf16.h>
#include <math.h>
#include <stdint.h>

// Problem constants
#define CC 512
#define TT 2048
#define BBATCH 2
#define HH 8
#define DD 64
#define LLAYERS 6
#define VV 32000
#define NROW (BBATCH*TT)   // 4096
#define NTILES_HEAD 250

// weight plane offsets (bf16 elems)
#define OFF_QKV  0
#define OFF_OUT  4718592
#define OFF_FF1  6291456
#define OFF_FF2  12582912
#define OFF_HEAD 18874368
#define WTOTAL   35258368

// ---------------- scratch (no allocations allowed) ----------------
__device__ float g_x  [NROW * CC];
__device__ float g_nll[NROW];
__device__ float g_pm [NROW * 256];
__device__ float g_ps [NROW * 256];
__device__ __nv_bfloat16 g_wh[WTOTAL];
__device__ __nv_bfloat16 g_wl[WTOTAL];
__device__ __nv_bfloat16 g_xnh[NROW * CC],     g_xnl[NROW * CC];
__device__ __nv_bfloat16 g_qkvh[NROW * 3 * CC], g_qkvl[NROW * 3 * CC];
__device__ __nv_bfloat16 g_atth[NROW * CC],    g_attl[NROW * CC];
__device__ __nv_bfloat16 g_ffh[NROW * 4 * CC],  g_ffl[NROW * 4 * CC];

// ================= helpers =================
__device__ __forceinline__ uint32_t smem_u32(const void* p) {
    uint32_t a;
    asm("{ .reg .u64 t; cvta.to.shared.u64 t, %1; cvt.u32.u64 %0, t; }"
        : "=r"(a) : "l"(p));
    return a;
}
__device__ __forceinline__ void ldsm_x4(uint32_t* r, uint32_t addr) {
    asm volatile("ldmatrix.sync.aligned.m8n8.x4.shared.b16 {%0,%1,%2,%3}, [%4];"
                 : "=r"(r[0]), "=r"(r[1]), "=r"(r[2]), "=r"(r[3]) : "r"(addr));
}
__device__ __forceinline__ void ldsm_x4_t(uint32_t* r, uint32_t addr) {
    asm volatile("ldmatrix.sync.aligned.m8n8.x4.trans.shared.b16 {%0,%1,%2,%3}, [%4];"
                 : "=r"(r[0]), "=r"(r[1]), "=r"(r[2]), "=r"(r[3]) : "r"(addr));
}
__device__ __forceinline__ void mma_bf16(float* c, const uint32_t* a, const uint32_t* b) {
    asm volatile("mma.sync.aligned.m16n8k16.row.col.f32.bf16.bf16.f32 "
                 "{%0,%1,%2,%3}, {%4,%5,%6,%7}, {%8,%9}, {%0,%1,%2,%3};"
                 : "+f"(c[0]), "+f"(c[1]), "+f"(c[2]), "+f"(c[3])
                 : "r"(a[0]), "r"(a[1]), "r"(a[2]), "r"(a[3]),
                   "r"(b[0]), "r"(b[1]));
}
__device__ __forceinline__ void split2(float a, float b, uint32_t& hi, uint32_t& lo) {
    __nv_bfloat16 ha = __float2bfloat16(a), hb = __float2bfloat16(b);
    __nv_bfloat16 la = __float2bfloat16(a - __bfloat162float(ha));
    __nv_bfloat16 lb = __float2bfloat16(b - __bfloat162float(hb));
    hi = (uint32_t)__bfloat16_as_ushort(ha) | ((uint32_t)__bfloat16_as_ushort(hb) << 16);
    lo = (uint32_t)__bfloat16_as_ushort(la) | ((uint32_t)__bfloat16_as_ushort(lb) << 16);
}
#define CP16(dst, src) \
    asm volatile("cp.async.cg.shared.global [%0], [%1], 16;" \
                 :: "r"(dst), "l"(src) : "memory")
#define CP_COMMIT() asm volatile("cp.async.commit_group;" ::: "memory")
#define CP_WAIT0()  asm volatile("cp.async.wait_group 0;" ::: "memory")

__device__ __forceinline__ float gelu_exact(float x) {
    return 0.5f * x * (1.0f + erff(x * 0.70710678118654752f));
}

// ---------------- weight split conversion ----------------
__global__ void cvtw_k(const float* __restrict__ s,
                       __nv_bfloat16* __restrict__ dh,
                       __nv_bfloat16* __restrict__ dl, int n4) {
    int stride = gridDim.x * blockDim.x;
    int base = blockIdx.x * blockDim.x + threadIdx.x;
    for (int i = base; i < n4; i += 4 * stride) {
        float4 v[4];
        int idx[4];
        #pragma unroll
        for (int j = 0; j < 4; j++) {
            idx[j] = i + j * stride;
            if (idx[j] < n4) v[j] = ((const float4*)s)[idx[j]];
        }
        #pragma unroll
        for (int j = 0; j < 4; j++) {
            if (idx[j] < n4) {
                uint32_t h0, l0, h1, l1;
                split2(v[j].x, v[j].y, h0, l0);
                split2(v[j].z, v[j].w, h1, l1);
                *(uint2*)(dh + (size_t)idx[j] * 4) = make_uint2(h0, h1);
                *(uint2*)(dl + (size_t)idx[j] * 4) = make_uint2(l0, l1);
            }
        }
    }
}

// ---------------- embedding ----------------
__global__ void embed_k(const int* __restrict__ idx,
                        const float* __restrict__ tok,
                        const float* __restrict__ pos,
                        float* __restrict__ x) {
    int row = blockIdx.x;
    int t   = row & (TT - 1);
    int tokid = idx[row];
    const float4* te = (const float4*)(tok + (size_t)tokid * CC);
    const float4* pe = (const float4*)(pos + (size_t)t * CC);
    float4* xr = (float4*)(x + (size_t)row * CC);
    for (int i = threadIdx.x; i < CC / 4; i += blockDim.x) {
        float4 a = te[i], b = pe[i];
        a.x += b.x; a.y += b.y; a.z += b.z; a.w += b.w;
        xr[i] = a;
    }
}

// ---------------- layernorm -> bf16 hi/lo planes ----------------
__global__ __launch_bounds__(128) void ln_bf(const float* __restrict__ x,
                                             const float* __restrict__ w,
                                             const float* __restrict__ b,
                                             __nv_bfloat16* __restrict__ yh,
                                             __nv_bfloat16* __restrict__ yl) {
    int row = blockIdx.x;
    int tid = threadIdx.x;
    const float4* xr = (const float4*)(x + (size_t)row * CC);
    float4 v = xr[tid];
    float s = v.x + v.y + v.z + v.w;
    float q = v.x * v.x + v.y * v.y + v.z * v.z + v.w * v.w;
    #pragma unroll
    for (int o = 16; o > 0; o >>= 1) {
        s += __shfl_xor_sync(0xffffffffu, s, o);
        q += __shfl_xor_sync(0xffffffffu, q, o);
    }
    __shared__ float ss[4], qq[4];
    int wid = tid >> 5;
    if ((tid & 31) == 0) { ss[wid] = s; qq[wid] = q; }
    __syncthreads();
    s = ss[0] + ss[1] + ss[2] + ss[3];
    q = qq[0] + qq[1] + qq[2] + qq[3];
    float mu   = s * (1.0f / CC);
    float var  = q * (1.0f / CC) - mu * mu;
    float rstd = rsqrtf(var + 1e-5f);
    float4 wv = ((const float4*)w)[tid];
    float4 bv = ((const float4*)b)[tid];
    float o0 = (v.x - mu) * rstd * wv.x + bv.x;
    float o1 = (v.y - mu) * rstd * wv.y + bv.y;
    float o2 = (v.z - mu) * rstd * wv.z + bv.z;
    float o3 = (v.w - mu) * rstd * wv.w + bv.w;
    uint32_t h0, l0, h1, l1;
    split2(o0, o1, h0, l0);
    split2(o2, o3, h1, l1);
    *(uint2*)(yh + (size_t)row * CC + tid * 4) = make_uint2(h0, h1);
    *(uint2*)(yl + (size_t)row * CC + tid * 4) = make_uint2(l0, l1);
}

#define MODE_NONE 0
#define MODE_GELU 1
#define MODE_RES  2
#define MODE_BF   3
#define MODE_HEAD 4

// ================= gemm_bf: 128x128 CTA, 8 warps, warp tile 64x32 ===
#define BM 128
#define BN 128
#define BK 32
#define PLANE_B 10240
#define STAGE_B (4 * PLANE_B)
#define GEMM_SMEM (2 * STAGE_B)   // 81920

__global__ __launch_bounds__(256, 2) void gemm_bf(
    const __nv_bfloat16* __restrict__ Ah, const __nv_bfloat16* __restrict__ Al,
    const __nv_bfloat16* __restrict__ Bh, const __nv_bfloat16* __restrict__ Bl,
    const float* __restrict__ bias, const float* __restrict__ res,
    float* __restrict__ Cf,
    __nv_bfloat16* __restrict__ Ch, __nv_bfloat16* __restrict__ Cl,
    int N, int K, int mode) {
    extern __shared__ __align__(16) char smem[];
    uint32_t sb = smem_u32(smem);

    int tid  = threadIdx.x;
    int lane = tid & 31;
    int wid  = tid >> 5;
    int wm   = wid & 1;
    int wn   = wid >> 1;
    int bm   = blockIdx.x * BM;
    int bn   = blockIdx.y * BN;

    int r = tid >> 1;
    int cb = (tid & 1) * 2;
    const __nv_bfloat16* Agp = Ah + (size_t)(bm + r) * K + cb * 8;
    const __nv_bfloat16* Alp = Al + (size_t)(bm + r) * K + cb * 8;
    const __nv_bfloat16* Bgp = Bh + (size_t)(bn + r) * K + cb * 8;
    const __nv_bfloat16* Blp = Bl + (size_t)(bn + r) * K + cb * 8;
    uint32_t sdst = (uint32_t)(r * 80 + cb * 16);

    float acc[4][4][4];
    #pragma unroll
    for (int i = 0; i < 4; i++)
        #pragma unroll
        for (int j = 0; j < 4; j++)
            #pragma unroll
            for (int k = 0; k < 4; k++) acc[i][j][k] = 0.0f;

    int nk = K / BK;

    {
        uint32_t st = sb + sdst;
        CP16(st + 0 * PLANE_B,      Agp);     CP16(st + 0 * PLANE_B + 16, Agp + 8);
        CP16(st + 1 * PLANE_B,      Alp);     CP16(st + 1 * PLANE_B + 16, Alp + 8);
        CP16(st + 2 * PLANE_B,      Bgp);     CP16(st + 2 * PLANE_B + 16, Bgp + 8);
        CP16(st + 3 * PLANE_B,      Blp);     CP16(st + 3 * PLANE_B + 16, Blp + 8);
        CP_COMMIT();
    }

    for (int t = 0; t < nk; t++) {
        CP_WAIT0();
        __syncthreads();
        if (t + 1 < nk) {
            uint32_t st = sb + ((t + 1) & 1) * STAGE_B + sdst;
            const __nv_bfloat16* a0 = Agp + (t + 1) * BK;
            const __nv_bfloat16* a1 = Alp + (t + 1) * BK;
            const __nv_bfloat16* b0 = Bgp + (t + 1) * BK;
            const __nv_bfloat16* b1 = Blp + (t + 1) * BK;
            CP16(st + 0 * PLANE_B,      a0);  CP16(st + 0 * PLANE_B + 16, a0 + 8);
            CP16(st + 1 * PLANE_B,      a1);  CP16(st + 1 * PLANE_B + 16, a1 + 8);
            CP16(st + 2 * PLANE_B,      b0);  CP16(st + 2 * PLANE_B + 16, b0 + 8);
            CP16(st + 3 * PLANE_B,      b1);  CP16(st + 3 * PLANE_B + 16, b1 + 8);
        }
        CP_COMMIT();

        uint32_t cAh = sb + (t & 1) * STAGE_B;
        uint32_t cAl = cAh + PLANE_B;
        uint32_t cBh = cAh + 2 * PLANE_B;
        uint32_t cBl = cAh + 3 * PLANE_B;

        #pragma unroll
        for (int kf = 0; kf < 2; kf++) {
            uint32_t kb = kf * 32;
            uint32_t aoff = (uint32_t)((wm * 64 + (lane & 15)) * 80 + kb + ((lane >> 4) * 16));
            uint32_t bo4 = (uint32_t)((wn * 32 + ((lane >> 4) * 8) + (lane & 7)) * 80
                                      + kb + (((lane >> 3) & 1) * 16));

            uint32_t ah4[4][4], al4[4][4], bp4[2][4];
            #pragma unroll
            for (int mf = 0; mf < 4; mf++) ldsm_x4(ah4[mf], cAh + aoff + mf * 16 * 80);
            #pragma unroll
            for (int p = 0; p < 2; p++)   ldsm_x4(bp4[p],  cBh + bo4 + p * 16 * 80);
            #pragma unroll
            for (int p = 0; p < 2; p++) {
                #pragma unroll
                for (int mf = 0; mf < 4; mf++) {
                    mma_bf16(acc[mf][2 * p],     ah4[mf], &bp4[p][0]);
                    mma_bf16(acc[mf][2 * p + 1], ah4[mf], &bp4[p][2]);
                }
            }
            #pragma unroll
            for (int mf = 0; mf < 4; mf++) ldsm_x4(al4[mf], cAl + aoff + mf * 16 * 80);
            #pragma unroll
            for (int p = 0; p < 2; p++) {
                #pragma unroll
                for (int mf = 0; mf < 4; mf++) {
                    mma_bf16(acc[mf][2 * p],     al4[mf], &bp4[p][0]);
                    mma_bf16(acc[mf][2 * p + 1], al4[mf], &bp4[p][2]);
                }
            }
            #pragma unroll
            for (int p = 0; p < 2; p++)   ldsm_x4(bp4[p], cBl + bo4 + p * 16 * 80);
            #pragma unroll
            for (int p = 0; p < 2; p++) {
                #pragma unroll
                for (int mf = 0; mf < 4; mf++) {
                    mma_bf16(acc[mf][2 * p],     ah4[mf], &bp4[p][0]);
                    mma_bf16(acc[mf][2 * p + 1], ah4[mf], &bp4[p][2]);
                }
            }
        }
    }

    if (mode == MODE_HEAD) {
        __syncthreads();
        float* pm_s = (float*)smem;
        float* ps_s = (float*)(smem + 2048);
        #pragma unroll
        for (int mf = 0; mf < 4; mf++) {
            int rl0 = wm * 64 + mf * 16 + (lane >> 2);
            float rv0[8], rv1[8];
            #pragma unroll
            for (int nf = 0; nf < 4; nf++) {
                int col = bn + wn * 32 + nf * 8 + (lane & 3) * 2;
                float b0 = bias[col], b1 = bias[col + 1];
                float v0 = acc[mf][nf][0] + b0;
                float v1 = acc[mf][nf][1] + b1;
                float v2 = acc[mf][nf][2] + b0;
                float v3 = acc[mf][nf][3] + b1;
                int r0g = bm + rl0;
                *(float2*)(Cf + (size_t)r0g * N + col)       = make_float2(v0, v1);
                *(float2*)(Cf + (size_t)(r0g + 8) * N + col) = make_float2(v2, v3);
                rv0[nf * 2] = v0; rv0[nf * 2 + 1] = v1;
                rv1[nf * 2] = v2; rv1[nf * 2 + 1] = v3;
            }
            float m0 = rv0[0], m1 = rv1[0];
            #pragma unroll
            for (int i = 1; i < 8; i++) { m0 = fmaxf(m0, rv0[i]); m1 = fmaxf(m1, rv1[i]); }
            m0 = fmaxf(m0, __shfl_xor_sync(0xffffffffu, m0, 1));
            m0 = fmaxf(m0, __shfl_xor_sync(0xffffffffu, m0, 2));
            m1 = fmaxf(m1, __shfl_xor_sync(0xffffffffu, m1, 1));
            m1 = fmaxf(m1, __shfl_xor_sync(0xffffffffu, m1, 2));
            float s0 = 0.0f, s1 = 0.0f;
            #pragma unroll
            for (int i = 0; i < 8; i++) {
                s0 += __expf(rv0[i] - m0);
                s1 += __expf(rv1[i] - m1);
            }
            s0 += __shfl_xor_sync(0xffffffffu, s0, 1);
            s0 += __shfl_xor_sync(0xffffffffu, s0, 2);
            s1 += __shfl_xor_sync(0xffffffffu, s1, 1);
            s1 += __shfl_xor_sync(0xffffffffu, s1, 2);
            if ((lane & 3) == 0) {
                pm_s[rl0 * 4 + wn] = m0;       ps_s[rl0 * 4 + wn] = s0;
                pm_s[(rl0 + 8) * 4 + wn] = m1; ps_s[(rl0 + 8) * 4 + wn] = s1;
            }
        }
        __syncthreads();
        if (tid < 128) {
            float m = -1e30f, s = 0.0f;
            #pragma unroll
            for (int w = 0; w < 4; w++) {
                float mi = pm_s[tid * 4 + w], si = ps_s[tid * 4 + w];
                float mn = fmaxf(m, mi);
                s = s * __expf(m - mn) + si * __expf(mi - mn);
                m = mn;
            }
            g_pm[(size_t)(bm + tid) * 256 + blockIdx.y] = m;
            g_ps[(size_t)(bm + tid) * 256 + blockIdx.y] = s;
        }
        return;
    }

    #pragma unroll
    for (int mf = 0; mf < 4; mf++) {
        int r0 = bm + wm * 64 + mf * 16 + (lane >> 2);
        #pragma unroll
        for (int nf = 0; nf < 4; nf++) {
            int col = bn + wn * 32 + nf * 8 + (lane & 3) * 2;
            float b0 = bias[col], b1 = bias[col + 1];
            float v0 = acc[mf][nf][0] + b0;
            float v1 = acc[mf][nf][1] + b1;
            float v2 = acc[mf][nf][2] + b0;
            float v3 = acc[mf][nf][3] + b1;
            if (mode == MODE_GELU) {
                v0 = gelu_exact(v0); v1 = gelu_exact(v1);
                v2 = gelu_exact(v2); v3 = gelu_exact(v3);
            } else if (mode == MODE_RES) {
                float2 r0v = *(const float2*)(res + (size_t)r0 * N + col);
                float2 r1v = *(const float2*)(res + (size_t)(r0 + 8) * N + col);
                v0 += r0v.x; v1 += r0v.y; v2 += r1v.x; v3 += r1v.y;
            }
            if (mode == MODE_RES || mode == MODE_NONE) {
                *(float2*)(Cf + (size_t)r0 * N + col)       = make_float2(v0, v1);
                *(float2*)(Cf + (size_t)(r0 + 8) * N + col) = make_float2(v2, v3);
            } else {
                uint32_t hp, lp;
                split2(v0, v1, hp, lp);
                *(uint32_t*)(Ch + (size_t)r0 * N + col) = hp;
                *(uint32_t*)(Cl + (size_t)r0 * N + col) = lp;
                split2(v2, v3, hp, lp);
                *(uint32_t*)(Ch + (size_t)(r0 + 8) * N + col) = hp;
                *(uint32_t*)(Cl + (size_t)(r0 + 8) * N + col) = lp;
            }
        }
    }
}

// ====== gemm_bf64m: 64x128 CTA (M-split), 8 warps 2Mx4N, warp tile 32x32 ======
#define APL64 5120
#define BPL64 10240
#define STG64 (2 * APL64 + 2 * BPL64)   // 30720
#define GEMM64_SMEM (2 * STG64)         // 61440

__global__ __launch_bounds__(256, 2) void gemm_bf64m(
    const __nv_bfloat16* __restrict__ Ah, const __nv_bfloat16* __restrict__ Al,
    const __nv_bfloat16* __restrict__ Bh, const __nv_bfloat16* __restrict__ Bl,
    const float* __restrict__ bias, const float* __restrict__ res,
    float* __restrict__ Cf,
    __nv_bfloat16* __restrict__ Ch, __nv_bfloat16* __restrict__ Cl,
    int N, int K, int mode) {
    extern __shared__ __align__(16) char smem[];
    uint32_t sb = smem_u32(smem);

    int tid  = threadIdx.x;
    int lane = tid & 31;
    int wid  = tid >> 5;
    int wm   = wid & 1;
    int wn   = wid >> 1;
    int bm   = blockIdx.x * 64;
    int bn   = blockIdx.y * 128;

    int ra = tid >> 2, ca = tid & 3;
    const __nv_bfloat16* Agp = Ah + (size_t)(bm + ra) * K + ca * 8;
    const __nv_bfloat16* Alp = Al + (size_t)(bm + ra) * K + ca * 8;
    uint32_t sdA = (uint32_t)(ra * 80 + ca * 16);
    const __nv_bfloat16* Bgp0 = Bh + (size_t)(bn + ra) * K + ca * 8;
    const __nv_bfloat16* Blp0 = Bl + (size_t)(bn + ra) * K + ca * 8;
    const __nv_bfloat16* Bgp1 = Bgp0 + (size_t)64 * K;
    const __nv_bfloat16* Blp1 = Blp0 + (size_t)64 * K;
    uint32_t sdB0 = (uint32_t)(ra * 80 + ca * 16);
    uint32_t sdB1 = sdB0 + 64 * 80;

    float acc[2][4][4];
    #pragma unroll
    for (int i = 0; i < 2; i++)
        #pragma unroll
        for (int j = 0; j < 4; j++)
            #pragma unroll
            for (int k = 0; k < 4; k++) acc[i][j][k] = 0.0f;

    int nk = K / BK;

    #define G64M_ISSUE(T, S) do {                                        \
        uint32_t st = sb + (uint32_t)(S) * STG64;                        \
        int k0 = (T) * BK;                                               \
        CP16(st + sdA,                     Agp + k0);                    \
        CP16(st + APL64 + sdA,             Alp + k0);                    \
        CP16(st + 2 * APL64 + sdB0,        Bgp0 + k0);                   \
        CP16(st + 2 * APL64 + sdB1,        Bgp1 + k0);                   \
        CP16(st + 2 * APL64 + BPL64 + sdB0, Blp0 + k0);                  \
        CP16(st + 2 * APL64 + BPL64 + sdB1, Blp1 + k0);                  \
    } while (0)

    G64M_ISSUE(0, 0); CP_COMMIT();

    for (int t = 0; t < nk; t++) {
        CP_WAIT0();
        __syncthreads();
        if (t + 1 < nk) { G64M_ISSUE(t + 1, (t + 1) & 1); }
        CP_COMMIT();

        uint32_t cAh = sb + (t & 1) * STG64;
        uint32_t cAl = cAh + APL64;
        uint32_t cBh = cAh + 2 * APL64;
        uint32_t cBl = cBh + BPL64;

        #pragma unroll
        for (int kf = 0; kf < 2; kf++) {
            uint32_t kb = kf * 32;
            uint32_t aoff = (uint32_t)((wm * 32 + (lane & 15)) * 80 + kb + ((lane >> 4) * 16));
            uint32_t bo4 = (uint32_t)((wn * 32 + ((lane >> 4) * 8) + (lane & 7)) * 80
                                      + kb + (((lane >> 3) & 1) * 16));

            uint32_t ah4[2][4], al4[2][4], bp4[2][4];
            #pragma unroll
            for (int mf = 0; mf < 2; mf++) ldsm_x4(ah4[mf], cAh + aoff + mf * 16 * 80);
            #pragma unroll
            for (int p = 0; p < 2; p++)   ldsm_x4(bp4[p],  cBh + bo4 + p * 16 * 80);
            #pragma unroll
            for (int p = 0; p < 2; p++) {
                #pragma unroll
                for (int mf = 0; mf < 2; mf++) {
                    mma_bf16(acc[mf][2 * p],     ah4[mf], &bp4[p][0]);
                    mma_bf16(acc[mf][2 * p + 1], ah4[mf], &bp4[p][2]);
                }
            }
            #pragma unroll
            for (int mf = 0; mf < 2; mf++) ldsm_x4(al4[mf], cAl + aoff + mf * 16 * 80);
            #pragma unroll
            for (int p = 0; p < 2; p++) {
                #pragma unroll
                for (int mf = 0; mf < 2; mf++) {
                    mma_bf16(acc[mf][2 * p],     al4[mf], &bp4[p][0]);
                    mma_bf16(acc[mf][2 * p + 1], al4[mf], &bp4[p][2]);
                }
            }
            #pragma unroll
            for (int p = 0; p < 2; p++)   ldsm_x4(bp4[p], cBl + bo4 + p * 16 * 80);
            #pragma unroll
            for (int p = 0; p < 2; p++) {
                #pragma unroll
                for (int mf = 0; mf < 2; mf++) {
                    mma_bf16(acc[mf][2 * p],     ah4[mf], &bp4[p][0]);
                    mma_bf16(acc[mf][2 * p + 1], ah4[mf], &bp4[p][2]);
                }
            }
        }
    }

    #pragma unroll
    for (int mf = 0; mf < 2; mf++) {
        int r0 = bm + wm * 32 + mf * 16 + (lane >> 2);
        #pragma unroll
        for (int nf = 0; nf < 4; nf++) {
            int col = bn + wn * 32 + nf * 8 + (lane & 3) * 2;
            float b0 = bias[col], b1 = bias[col + 1];
            float v0 = acc[mf][nf][0] + b0;
            float v1 = acc[mf][nf][1] + b1;
            float v2 = acc[mf][nf][2] + b0;
            float v3 = acc[mf][nf][3] + b1;
            if (mode == MODE_RES) {
                float2 r0v = *(const float2*)(res + (size_t)r0 * N + col);
                float2 r1v = *(const float2*)(res + (size_t)(r0 + 8) * N + col);
                v0 += r0v.x; v1 += r0v.y; v2 += r1v.x; v3 += r1v.y;
                *(float2*)(Cf + (size_t)r0 * N + col)       = make_float2(v0, v1);
                *(float2*)(Cf + (size_t)(r0 + 8) * N + col) = make_float2(v2, v3);
            } else {   // MODE_BF: bf16 hi/lo planes
                uint32_t hp, lp;
                split2(v0, v1, hp, lp);
                *(uint32_t*)(Ch + (size_t)r0 * N + col) = hp;
                *(uint32_t*)(Cl + (size_t)r0 * N + col) = lp;
                split2(v2, v3, hp, lp);
                *(uint32_t*)(Ch + (size_t)(r0 + 8) * N + col) = hp;
                *(uint32_t*)(Cl + (size_t)(r0 + 8) * N + col) = lp;
            }
        }
    }
}

// ================= tensor-core flash attention ========
#define SQH 0
#define SQL 18432
#define SKV 36864
#define KVB 36864
#define ATT_SMEM (SKV + 2 * KVB)   // 110592

__global__ __launch_bounds__(256) void attn_mma(
    const __nv_bfloat16* __restrict__ qkvh,
    const __nv_bfloat16* __restrict__ qkvl,
    __nv_bfloat16* __restrict__ outh,
    __nv_bfloat16* __restrict__ outl) {
    extern __shared__ __align__(16) char sm[];
    uint32_t sb = smem_u32(sm);
    int tid = threadIdx.x, lane = tid & 31, w = tid >> 5;
    int bh = blockIdx.y, b = bh >> 3, h = bh & 7;
    int qb = (int)gridDim.x - 1 - (int)blockIdx.x;
    size_t bbase = (size_t)b * TT * (3 * CC);

    int ntiles = qb * 2 + 2;
    int sr2 = tid >> 2, qd = tid & 3;

    {
        size_t ro = bbase + (size_t)sr2 * (3 * CC);
        const __nv_bfloat16* kh = qkvh + ro + CC + h * DD + qd * 16;
        const __nv_bfloat16* kl = qkvl + ro + CC + h * DD + qd * 16;
        const __nv_bfloat16* vh = qkvh + ro + 2 * CC + h * DD + qd * 16;
        const __nv_bfloat16* vl = qkvl + ro + 2 * CC + h * DD + qd * 16;
        uint32_t sd = sb + SKV + (uint32_t)(sr2 * 144 + qd * 32);
        CP16(sd + 0,         kh);  CP16(sd + 16,         kh + 8);
        CP16(sd + 9216,      kl);  CP16(sd + 9216 + 16,  kl + 8);
        CP16(sd + 18432,     vh);  CP16(sd + 18432 + 16, vh + 8);
        CP16(sd + 27648,     vl);  CP16(sd + 27648 + 16, vl + 8);
        CP_COMMIT();
    }

    {
        int r = tid >> 1, hf = tid & 1;
        const __nv_bfloat16* qgh = qkvh + bbase + (size_t)(qb * 128 + r) * (3 * CC) + h * DD + hf * 32;
        const __nv_bfloat16* qgl = qkvl + bbase + (size_t)(qb * 128 + r) * (3 * CC) + h * DD + hf * 32;
        uint32_t qoff = (uint32_t)(r * 144 + hf * 64);
        #pragma unroll
        for (int j = 0; j < 4; j++) {
            *(uint4*)(sm + SQH + qoff + j * 16) = *(const uint4*)(qgh + j * 8);
            *(uint4*)(sm + SQL + qoff + j * 16) = *(const uint4*)(qgl + j * 8);
        }
    }
    __syncthreads();

    uint32_t qh[4][4], qlo[4][4];
    {
        uint32_t ro = (uint32_t)((w * 16 + (lane & 15)) * 144 + ((lane >> 4) * 16));
        #pragma unroll
        for (int kf = 0; kf < 4; kf++) {
            ldsm_x4(qh[kf],  sb + SQH + ro + kf * 32);
            ldsm_x4(qlo[kf], sb + SQL + ro + kf * 32);
        }
    }

    float o[8][4];
    #pragma unroll
    for (int i = 0; i < 8; i++)
        #pragma unroll
        for (int j = 0; j < 4; j++) o[i][j] = 0.0f;
    float m0 = -1e30f, m1 = -1e30f, l0 = 0.0f, l1 = 0.0f;

    for (int t = 0; t < ntiles; t++) {
        CP_WAIT0();
        __syncthreads();
        if (t + 1 < ntiles) {
            size_t ro = bbase + (size_t)((t + 1) * 64 + sr2) * (3 * CC);
            const __nv_bfloat16* kh = qkvh + ro + CC + h * DD + qd * 16;
            const __nv_bfloat16* kl = qkvl + ro + CC + h * DD + qd * 16;
            const __nv_bfloat16* vh = qkvh + ro + 2 * CC + h * DD + qd * 16;
            const __nv_bfloat16* vl = qkvl + ro + 2 * CC + h * DD + qd * 16;
            uint32_t sd = sb + SKV + ((t + 1) & 1) * KVB + (uint32_t)(sr2 * 144 + qd * 32);
            CP16(sd + 0,         kh);  CP16(sd + 16,         kh + 8);
            CP16(sd + 9216,      kl);  CP16(sd + 9216 + 16,  kl + 8);
            CP16(sd + 18432,     vh);  CP16(sd + 18432 + 16, vh + 8);
            CP16(sd + 27648,     vl);  CP16(sd + 27648 + 16, vl + 8);
        }
        CP_COMMIT();

        uint32_t KH = sb + SKV + (t & 1) * KVB;
        uint32_t KL = KH + 9216;
        uint32_t VH = KH + 18432;
        uint32_t VL = KH + 27648;

        float sacc[8][4];
        #pragma unroll
        for (int i = 0; i < 8; i++)
            #pragma unroll
            for (int j = 0; j < 4; j++) sacc[i][j] = 0.0f;

        #pragma unroll
        for (int kf = 0; kf < 4; kf++) {
            uint32_t bo = (uint32_t)((lane & 15) * 144 + kf * 32 + (lane >> 4) * 16);
            uint32_t kkh[4][4], kkl[4][4];
            #pragma unroll
            for (int p = 0; p < 4; p++) ldsm_x4(kkh[p], KH + bo + p * 16 * 144);
            #pragma unroll
            for (int p = 0; p < 4; p++) ldsm_x4(kkl[p], KL + bo + p * 16 * 144);
            #pragma unroll
            for (int p = 0; p < 4; p++) {
                uint32_t b0[2] = {kkh[p][0], kkh[p][2]};
                uint32_t b1[2] = {kkh[p][1], kkh[p][3]};
                mma_bf16(sacc[2 * p],     qh[kf],  b0);
                mma_bf16(sacc[2 * p + 1], qh[kf],  b1);
                mma_bf16(sacc[2 * p],     qlo[kf], b0);
                mma_bf16(sacc[2 * p + 1], qlo[kf], b1);
            }
            #pragma unroll
            for (int p = 0; p < 4; p++) {
                uint32_t b0[2] = {kkl[p][0], kkl[p][2]};
                uint32_t b1[2] = {kkl[p][1], kkl[p][3]};
                mma_bf16(sacc[2 * p],     qh[kf], b0);
                mma_bf16(sacc[2 * p + 1], qh[kf], b1);
            }
        }
        #pragma unroll
        for (int nf = 0; nf < 8; nf++) {
            sacc[nf][0] *= 0.125f; sacc[nf][1] *= 0.125f;
            sacc[nf][2] *= 0.125f; sacc[nf][3] *= 0.125f;
        }

        if (t >= 2 * qb) {
            int row0 = qb * 128 + w * 16 + (lane >> 2);
            int kc0  = t * 64 + (lane & 3) * 2;
            #pragma unroll
            for (int nf = 0; nf < 8; nf++) {
                int kc = kc0 + nf * 8;
                if (kc     > row0)     sacc[nf][0] = -1e30f;
                if (kc + 1 > row0)     sacc[nf][1] = -1e30f;
                if (kc     > row0 + 8) sacc[nf][2] = -1e30f;
                if (kc + 1 > row0 + 8) sacc[nf][3] = -1e30f;
            }
        }

        float mx0 = -1e30f, mx1 = -1e30f;
        #pragma unroll
        for (int nf = 0; nf < 8; nf++) {
            mx0 = fmaxf(mx0, fmaxf(sacc[nf][0], sacc[nf][1]));
            mx1 = fmaxf(mx1, fmaxf(sacc[nf][2], sacc[nf][3]));
        }
        mx0 = fmaxf(mx0, __shfl_xor_sync(0xffffffffu, mx0, 1));
        mx0 = fmaxf(mx0, __shfl_xor_sync(0xffffffffu, mx0, 2));
        mx1 = fmaxf(mx1, __shfl_xor_sync(0xffffffffu, mx1, 1));
        mx1 = fmaxf(mx1, __shfl_xor_sync(0xffffffffu, mx1, 2));
        float mn0 = fmaxf(m0, mx0), mn1 = fmaxf(m1, mx1);
        float cs0 = __expf(m0 - mn0), cs1 = __expf(m1 - mn1);
        m0 = mn0; m1 = mn1;
        float ps0 = 0.0f, ps1 = 0.0f;
        #pragma unroll
        for (int nf = 0; nf < 8; nf++) {
            sacc[nf][0] = __expf(sacc[nf][0] - m0); ps0 += sacc[nf][0];
            sacc[nf][1] = __expf(sacc[nf][1] - m0); ps0 += sacc[nf][1];
            sacc[nf][2] = __expf(sacc[nf][2] - m1); ps1 += sacc[nf][2];
            sacc[nf][3] = __expf(sacc[nf][3] - m1); ps1 += sacc[nf][3];
        }
        l0 = l0 * cs0 + ps0;
        l1 = l1 * cs1 + ps1;
        #pragma unroll
        for (int nd = 0; nd < 8; nd++) {
            o[nd][0] *= cs0; o[nd][1] *= cs0;
            o[nd][2] *= cs1; o[nd][3] *= cs1;
        }

        uint32_t ph[4][4], plo[4][4];
        #pragma unroll
        for (int j = 0; j < 4; j++) {
            split2(sacc[2 * j][0],     sacc[2 * j][1],     ph[j][0], plo[j][0]);
            split2(sacc[2 * j][2],     sacc[2 * j][3],     ph[j][1], plo[j][1]);
            split2(sacc[2 * j + 1][0], sacc[2 * j + 1][1], ph[j][2], plo[j][2]);
            split2(sacc[2 * j + 1][2], sacc[2 * j + 1][3], ph[j][3], plo[j][3]);
        }

        #pragma unroll
        for (int nd = 0; nd < 8; nd++) {
            uint32_t vh0[4], vh1[4], vl0[4], vl1[4];
            uint32_t vo0 = (uint32_t)(lane * 144 + nd * 16);
            uint32_t vo1 = (uint32_t)((32 + lane) * 144 + nd * 16);
            ldsm_x4_t(vh0, VH + vo0);
            ldsm_x4_t(vh1, VH + vo1);
            ldsm_x4_t(vl0, VL + vo0);
            ldsm_x4_t(vl1, VL + vo1);
            {
                uint32_t b0[2] = {vh0[0], vh0[1]};
                uint32_t b1[2] = {vh0[2], vh0[3]};
                mma_bf16(o[nd], ph[0],  b0);
                mma_bf16(o[nd], ph[1],  b1);
                mma_bf16(o[nd], plo[0], b0);
                mma_bf16(o[nd], plo[1], b1);
            }
            {
                uint32_t b0[2] = {vh1[0], vh1[1]};
                uint32_t b1[2] = {vh1[2], vh1[3]};
                mma_bf16(o[nd], ph[2],  b0);
                mma_bf16(o[nd], ph[3],  b1);
                mma_bf16(o[nd], plo[2], b0);
                mma_bf16(o[nd], plo[3], b1);
            }
            {
                uint32_t b0[2] = {vl0[0], vl0[1]};
                uint32_t b1[2] = {vl0[2], vl0[3]};
                mma_bf16(o[nd], ph[0], b0);
                mma_bf16(o[nd], ph[1], b1);
            }
            {
                uint32_t b0[2] = {vl1[0], vl1[1]};
                uint32_t b1[2] = {vl1[2], vl1[3]};
                mma_bf16(o[nd], ph[2], b0);
                mma_bf16(o[nd], ph[3], b1);
            }
        }
    }

    l0 += __shfl_xor_sync(0xffffffffu, l0, 1);
    l0 += __shfl_xor_sync(0xffffffffu, l0, 2);
    l1 += __shfl_xor_sync(0xffffffffu, l1, 1);
    l1 += __shfl_xor_sync(0xffffffffu, l1, 2);
    float inv0 = 1.0f / l0, inv1 = 1.0f / l1;
    int rowg = b * TT + qb * 128 + w * 16 + (lane >> 2);
    __nv_bfloat16* oph = outh + (size_t)rowg * CC + h * DD;
    __nv_bfloat16* opl = outl + (size_t)rowg * CC + h * DD;
    #pragma unroll
    for (int nd = 0; nd < 8; nd++) {
        int col = nd * 8 + (lane & 3) * 2;
        uint32_t hp, lp;
        split2(o[nd][0] * inv0, o[nd][1] * inv0, hp, lp);
        *(uint32_t*)(oph + col) = hp;
        *(uint32_t*)(opl + col) = lp;
        split2(o[nd][2] * inv1, o[nd][3] * inv1, hp, lp);
        *(uint32_t*)(oph + 8 * CC + col) = hp;
        *(uint32_t*)(opl + 8 * CC + col) = lp;
    }
}

// ---------------- NLL from logsumexp partials ----------------
__global__ __launch_bounds__(256) void nll2_k(const float* __restrict__ logits,
                                              const int* __restrict__ tgt,
                                              float* __restrict__ nll) {
    int row = blockIdx.x;
    const float* pm = g_pm + (size_t)row * 256;
    const float* ps = g_ps + (size_t)row * 256;
    float m = -1e30f, s = 0.0f;
    for (int j = threadIdx.x; j < NTILES_HEAD; j += 256) {
        float mi = pm[j], si = ps[j];
        float mn = fmaxf(m, mi);
        s = s * __expf(m - mn) + si * __expf(mi - mn);
        m = mn;
    }
    #pragma unroll
    for (int o = 16; o > 0; o >>= 1) {
        float m2 = __shfl_xor_sync(0xffffffffu, m, o);
        float s2 = __shfl_xor_sync(0xffffffffu, s, o);
        float mn = fmaxf(m, m2);
        s = s * __expf(m - mn) + s2 * __expf(m2 - mn);
        m = mn;
    }
    __shared__ float ms[8], ls[8];
    int wid = threadIdx.x >> 5;
    if ((threadIdx.x & 31) == 0) { ms[wid] = m; ls[wid] = s; }
    __syncthreads();
    if (threadIdx.x == 0) {
        float M = ms[0], S = ls[0];
        #pragma unroll
        for (int w = 1; w < 8; w++) {
            float mn = fmaxf(M, ms[w]);
            S = S * __expf(M - mn) + ls[w] * __expf(ms[w] - mn);
            M = mn;
        }
        float lse = M + logf(S);
        nll[row] = lse - logits[(size_t)row * VV + tgt[row]];
    }
}

__global__ __launch_bounds__(256) void loss_k(const float* __restrict__ nll,
                                              float* __restrict__ out_loss) {
    float s = 0.0f;
    for (int i = threadIdx.x; i < NROW; i += 256) s += nll[i];
    #pragma unroll
    for (int o = 16; o > 0; o >>= 1) s += __shfl_xor_sync(0xffffffffu, s, o);
    __shared__ float ws[8];
    int wid = threadIdx.x >> 5;
    if ((threadIdx.x & 31) == 0) ws[wid] = s;
    __syncthreads();
    if (threadIdx.x == 0) {
        float t = 0.0f;
        #pragma unroll
        for (int w = 0; w < 8; w++) t += ws[w];
        out_loss[0] = t / (float)NROW;
    }
}

// ---------------- orchestration ----------------
extern "C" void kernel_launch(void* const* d_in, const int* in_sizes, int n_in,
                              void* d_out, int out_size) {
    const int*   idx       = (const int*)  d_in[0];
    const int*   targets   = (const int*)  d_in[1];
    const float* tok_embed = (const float*)d_in[2];
    const float* pos_embed = (const float*)d_in[3];
    const float* qkv_w     = (const float*)d_in[4];
    const float* qkv_b     = (const float*)d_in[5];
    const float* out_w     = (const float*)d_in[6];
    const float* out_b     = (const float*)d_in[7];
    const float* ln1_w     = (const float*)d_in[8];
    const float* ln1_b     = (const float*)d_in[9];
    const float* ff1_w     = (const float*)d_in[10];
    const float* ff1_b     = (const float*)d_in[11];
    const float* ff2_w     = (const float*)d_in[12];
    const float* ff2_b     = (const float*)d_in[13];
    const float* ln2_w     = (const float*)d_in[14];
    const float* ln2_b     = (const float*)d_in[15];
    const float* lnf_w     = (const float*)d_in[16];
    const float* lnf_b     = (const float*)d_in[17];
    const float* head_w    = (const float*)d_in[18];
    const float* head_b    = (const float*)d_in[19];
    float* logits = (float*)d_out;

    static float *px = nullptr, *pnll = nullptr;
    static __nv_bfloat16 *wh, *wl, *xnh, *xnl, *qkvh, *qkvl, *atth, *attl, *ffh, *ffl;
    if (!px) {
        cudaGetSymbolAddress((void**)&px,   g_x);
        cudaGetSymbolAddress((void**)&pnll, g_nll);
        cudaGetSymbolAddress((void**)&wh,   g_wh);
        cudaGetSymbolAddress((void**)&wl,   g_wl);
        cudaGetSymbolAddress((void**)&xnh,  g_xnh);
        cudaGetSymbolAddress((void**)&xnl,  g_xnl);
        cudaGetSymbolAddress((void**)&qkvh, g_qkvh);
        cudaGetSymbolAddress((void**)&qkvl, g_qkvl);
        cudaGetSymbolAddress((void**)&atth, g_atth);
        cudaGetSymbolAddress((void**)&attl, g_attl);
        cudaGetSymbolAddress((void**)&ffh,  g_ffh);
        cudaGetSymbolAddress((void**)&ffl,  g_ffl);
        cudaFuncSetAttribute(gemm_bf,    cudaFuncAttributeMaxDynamicSharedMemorySize, GEMM_SMEM);
        cudaFuncSetAttribute(gemm_bf64m, cudaFuncAttributeMaxDynamicSharedMemorySize, GEMM64_SMEM);
        cudaFuncSetAttribute(attn_mma,   cudaFuncAttributeMaxDynamicSharedMemorySize, ATT_SMEM);
    }

    cvtw_k<<<2048, 256>>>(qkv_w,  wh + OFF_QKV,  wl + OFF_QKV,  6 * 3 * CC * CC / 4);
    cvtw_k<<<2048, 256>>>(out_w,  wh + OFF_OUT,  wl + OFF_OUT,  6 * CC * CC / 4);
    cvtw_k<<<2048, 256>>>(ff1_w,  wh + OFF_FF1,  wl + OFF_FF1,  6 * 4 * CC * CC / 4);
    cvtw_k<<<2048, 256>>>(ff2_w,  wh + OFF_FF2,  wl + OFF_FF2,  6 * 4 * CC * CC / 4);
    cvtw_k<<<2048, 256>>>(head_w, wh + OFF_HEAD, wl + OFF_HEAD, VV * CC / 4);

    embed_k<<<NROW, 128>>>(idx, tok_embed, pos_embed, px);

    dim3 gQKV64(NROW / 64, 3 * CC / 128);  // (64, 12) = 768 CTAs
    dim3 gPROJ64(NROW / 64, CC / 128);     // (64, 4)  = 256 CTAs
    dim3 gFF1(NROW / 128, 4 * CC / 128);   // (32, 16)
    dim3 gHEAD(NROW / 128, VV / 128);      // (32, 250)
    dim3 gATT(TT / 128, BBATCH * HH);      // (16, 16)

    for (int l = 0; l < LLAYERS; l++) {
        ln_bf<<<NROW, 128>>>(px, ln1_w + l * CC, ln1_b + l * CC, xnh, xnl);
        gemm_bf64m<<<gQKV64, 256, GEMM64_SMEM>>>(xnh, xnl,
            wh + OFF_QKV + (size_t)l * 3 * CC * CC, wl + OFF_QKV + (size_t)l * 3 * CC * CC,
            qkv_b + l * 3 * CC, nullptr, nullptr, qkvh, qkvl, 3 * CC, CC, MODE_BF);
        attn_mma<<<gATT, 256, ATT_SMEM>>>(qkvh, qkvl, atth, attl);
        gemm_bf64m<<<gPROJ64, 256, GEMM64_SMEM>>>(atth, attl,
            wh + OFF_OUT + (size_t)l * CC * CC, wl + OFF_OUT + (size_t)l * CC * CC,
            out_b + l * CC, px, px, nullptr, nullptr, CC, CC, MODE_RES);
        ln_bf<<<NROW, 128>>>(px, ln2_w + l * CC, ln2_b + l * CC, xnh, xnl);
        gemm_bf<<<gFF1, 256, GEMM_SMEM>>>(xnh, xnl,
            wh + OFF_FF1 + (size_t)l * 4 * CC * CC, wl + OFF_FF1 + (size_t)l * 4 * CC * CC,
            ff1_b + l * 4 * CC, nullptr, nullptr, ffh, ffl, 4 * CC, CC, MODE_GELU);
        gemm_bf64m<<<gPROJ64, 256, GEMM64_SMEM>>>(ffh, ffl,
            wh + OFF_FF2 + (size_t)l * CC * 4 * CC, wl + OFF_FF2 + (size_t)l * CC * 4 * CC,
            ff2_b + l * CC, px, px, nullptr, nullptr, CC, 4 * CC, MODE_RES);
    }

    ln_bf<<<NROW, 128>>>(px, lnf_w, lnf_b, xnh, xnl);
    gemm_bf<<<gHEAD, 256, GEMM_SMEM>>>(xnh, xnl,
        wh + OFF_HEAD, wl + OFF_HEAD,
        head_b, nullptr, logits, nullptr, nullptr, VV, CC, MODE_HEAD);

    nll2_k<<<NROW, 256>>>(logits, targets, pnll);
    if (out_size > NROW * VV) {
        loss_k<<<1, 256>>>(pnll, logits + (size_t)NROW * VV);
    }
}